// round 7
// baseline (speedup 1.0000x reference)
#include <cuda_runtime.h>
#include <cuda_bf16.h>
#include <cstdint>

// ---------------- problem constants ----------------
#define BATCH 2
#define SEQ   2048
#define DMODEL 768
#define NHEAD 12
#define HDIM  64
#define STRIDE_ 8
#define QB    128
#define KMAX  (SEQ/STRIDE_)   // 256
#define KPAD  257

#define M_TOTAL (BATCH*SEQ)   // 4096
#define K_DIM   DMODEL        // 768
#define N_QKV   (3*DMODEL)    // 2304

// ---------------- device scratch ----------------
__device__ float g_qkv[M_TOTAL * N_QKV];
__device__ __nv_bfloat16 g_ah[M_TOTAL * K_DIM];
__device__ __nv_bfloat16 g_al[M_TOTAL * K_DIM];
__device__ __nv_bfloat16 g_bh[N_QKV * K_DIM];
__device__ __nv_bfloat16 g_bl[N_QKV * K_DIM];
__device__ __nv_bfloat16 g_owh[DMODEL * K_DIM];
__device__ __nv_bfloat16 g_owl[DMODEL * K_DIM];
__device__ __nv_bfloat16 g_xh[M_TOTAL * K_DIM];
__device__ __nv_bfloat16 g_xl[M_TOTAL * K_DIM];

// ---------------- PTX helpers (portable: sm_80+) ----------------
__device__ __forceinline__ uint32_t smem_u32(const void* p) {
    uint32_t a;
    asm("{ .reg .u64 t; cvta.to.shared.u64 t, %1; cvt.u32.u64 %0, t; }" : "=r"(a) : "l"(p));
    return a;
}

#define CP_ASYNC16(dst, src) \
    asm volatile("cp.async.cg.shared.global [%0], [%1], 16;" :: "r"(dst), "l"(src))
#define CP_COMMIT() asm volatile("cp.async.commit_group;" ::: "memory")
#define CP_WAIT1() asm volatile("cp.async.wait_group 1;" ::: "memory")
#define CP_WAIT0() asm volatile("cp.async.wait_group 0;" ::: "memory")

#define LDSM_X4(r0, r1, r2, r3, addr) \
    asm volatile("ldmatrix.sync.aligned.m8n8.x4.shared.b16 {%0,%1,%2,%3}, [%4];" \
        : "=r"(r0), "=r"(r1), "=r"(r2), "=r"(r3) : "r"(addr))

// NOTE: non-volatile — pure register computation; lets ptxas schedule freely.
#define MMA_BF16(c, a, b) \
    asm("mma.sync.aligned.m16n8k16.row.col.f32.bf16.bf16.f32 " \
        "{%0,%1,%2,%3}, {%4,%5,%6,%7}, {%8,%9}, {%0,%1,%2,%3};" \
        : "+f"((c)[0]), "+f"((c)[1]), "+f"((c)[2]), "+f"((c)[3]) \
        : "r"((a)[0]), "r"((a)[1]), "r"((a)[2]), "r"((a)[3]), \
          "r"((b)[0]), "r"((b)[1]))

// ---------------- fp32 -> bf16 hi/lo split ----------------
__global__ __launch_bounds__(256)
void conv_hilo_kernel(const float* __restrict__ in, __nv_bfloat16* __restrict__ hi,
                      __nv_bfloat16* __restrict__ lo, int n4)
{
    int i = blockIdx.x * 256 + threadIdx.x;
    if (i >= n4) return;
    float4 v = ((const float4*)in)[i];
    __nv_bfloat16 h0 = __float2bfloat16(v.x);
    __nv_bfloat16 h1 = __float2bfloat16(v.y);
    __nv_bfloat16 h2 = __float2bfloat16(v.z);
    __nv_bfloat16 h3 = __float2bfloat16(v.w);
    __nv_bfloat16 l0 = __float2bfloat16(v.x - __bfloat162float(h0));
    __nv_bfloat16 l1 = __float2bfloat16(v.y - __bfloat162float(h1));
    __nv_bfloat16 l2 = __float2bfloat16(v.z - __bfloat162float(h2));
    __nv_bfloat16 l3 = __float2bfloat16(v.w - __bfloat162float(h3));
    __nv_bfloat162* hp = (__nv_bfloat162*)hi;
    __nv_bfloat162* lp = (__nv_bfloat162*)lo;
    hp[2*i]   = __nv_bfloat162(h0, h1);
    hp[2*i+1] = __nv_bfloat162(h2, h3);
    lp[2*i]   = __nv_bfloat162(l0, l1);
    lp[2*i+1] = __nv_bfloat162(l2, l3);
}

// ---------------- mma.sync GEMM: 128x128, 2-stage, 2 CTAs/SM ----------------
#define GBK 32
#define NCHUNK (K_DIM / GBK)          // 24
#define TPAD 40
#define TILE_BYTES (128 * TPAD * 2)   // 10240
#define STAGE_BYTES (4 * TILE_BYTES)  // 40960
#define GEMM_SMEM (2 * STAGE_BYTES)   // 81920 -> 2 CTAs/SM

__global__ __launch_bounds__(256, 2)
void gemm_mma_kernel(const __nv_bfloat16* __restrict__ Ah, const __nv_bfloat16* __restrict__ Al,
                     const __nv_bfloat16* __restrict__ Bh, const __nv_bfloat16* __restrict__ Bl,
                     const float* __restrict__ bias, float* __restrict__ C, int N)
{
    extern __shared__ char dsm[];
    const uint32_t sbase = smem_u32(dsm);
    const int tid = threadIdx.x;
    const int lane = tid & 31;
    const int wid = tid >> 5;
    const int wm = (wid & 1) * 64;
    const int wn = (wid >> 1) * 32;
    const int bm = blockIdx.y * 128;
    const int bn = blockIdx.x * 128;

    const __nv_bfloat16* gp[4] = { Ah, Al, Bh, Bl };

    float acc[4][4][4];
    #pragma unroll
    for (int i = 0; i < 4; i++)
        #pragma unroll
        for (int j = 0; j < 4; j++)
            #pragma unroll
            for (int r = 0; r < 4; r++) acc[i][j][r] = 0.f;

    auto issue = [&](int stage, int kc) {
        const uint32_t st = sbase + (uint32_t)stage * STAGE_BYTES;
        #pragma unroll
        for (int t = 0; t < 8; ++t) {
            int task = tid + t * 256;
            int tile = task >> 9;
            int idx  = task & 511;
            int r = idx >> 2, q = idx & 3;
            int row = (tile < 2 ? bm : bn) + r;
            uint32_t dst = st + (uint32_t)tile * TILE_BYTES + (uint32_t)(r * TPAD + q * 8) * 2;
            CP_ASYNC16(dst, gp[tile] + (size_t)row * K_DIM + kc + q * 8);
        }
        CP_COMMIT();
    };

    issue(0, 0);
    issue(1, GBK);

    const int g = lane >> 3;
    const int arow = wm + (g & 1) * 8 + (lane & 7);
    const int acoff = (g >> 1) * 8;
    const int brow0 = wn + (g >> 1) * 8 + (lane & 7);
    const int bcoff = (g & 1) * 8;

    for (int c = 0; c < NCHUNK; ++c) {
        if (c + 1 < NCHUNK) { CP_WAIT1(); } else { CP_WAIT0(); }
        __syncthreads();

        const uint32_t st = sbase + (uint32_t)(c & 1) * STAGE_BYTES;
        const uint32_t aH = st;
        const uint32_t aL = st + TILE_BYTES;
        const uint32_t bH = st + 2 * TILE_BYTES;
        const uint32_t bL = st + 3 * TILE_BYTES;

        #pragma unroll
        for (int ks = 0; ks < 2; ++ks) {
            const int acol = ks * 16 + acoff;
            const int bcol = ks * 16 + bcoff;
            uint32_t ah[4][4], al[4][4];
            #pragma unroll
            for (int mf = 0; mf < 4; ++mf) {
                uint32_t off = (uint32_t)((arow + mf * 16) * TPAD + acol) * 2;
                LDSM_X4(ah[mf][0], ah[mf][1], ah[mf][2], ah[mf][3], aH + off);
                LDSM_X4(al[mf][0], al[mf][1], al[mf][2], al[mf][3], aL + off);
            }
            #pragma unroll
            for (int nf2 = 0; nf2 < 2; ++nf2) {
                uint32_t off = (uint32_t)((brow0 + nf2 * 16) * TPAD + bcol) * 2;
                uint32_t bh[2][2], bl[2][2];
                LDSM_X4(bh[0][0], bh[0][1], bh[1][0], bh[1][1], bH + off);
                LDSM_X4(bl[0][0], bl[0][1], bl[1][0], bl[1][1], bL + off);
                // product-major ordering: 8 independent accumulators per wave
                // -> accumulator RAW reuse distance = 8 MMAs (covers HMMA latency)
                #pragma unroll
                for (int mf = 0; mf < 4; ++mf)
                    #pragma unroll
                    for (int q = 0; q < 2; ++q)
                        MMA_BF16(acc[mf][2 * nf2 + q], ah[mf], bh[q]);
                #pragma unroll
                for (int mf = 0; mf < 4; ++mf)
                    #pragma unroll
                    for (int q = 0; q < 2; ++q)
                        MMA_BF16(acc[mf][2 * nf2 + q], ah[mf], bl[q]);
                #pragma unroll
                for (int mf = 0; mf < 4; ++mf)
                    #pragma unroll
                    for (int q = 0; q < 2; ++q)
                        MMA_BF16(acc[mf][2 * nf2 + q], al[mf], bh[q]);
            }
        }
        __syncthreads();
        if (c + 2 < NCHUNK) issue(c & 1, (c + 2) * GBK);
    }

    #pragma unroll
    for (int mf = 0; mf < 4; ++mf) {
        const int m = bm + wm + mf * 16 + (lane >> 2);
        #pragma unroll
        for (int nf = 0; nf < 4; ++nf) {
            const int n = bn + wn + nf * 8 + (lane & 3) * 2;
            const float2 bv = *(const float2*)&bias[n];
            float2 v0 = { acc[mf][nf][0] + bv.x, acc[mf][nf][1] + bv.y };
            float2 v1 = { acc[mf][nf][2] + bv.x, acc[mf][nf][3] + bv.y };
            *(float2*)&C[(size_t)m * N + n]       = v0;
            *(float2*)&C[(size_t)(m + 8) * N + n] = v1;
        }
    }
}

// ---------------- strided attention: 2 queries/warp, vectorized -------------
__global__ __launch_bounds__(512, 1)
void attn_kernel(const float* __restrict__ qkv,
                 __nv_bfloat16* __restrict__ oh, __nv_bfloat16* __restrict__ ol)
{
    extern __shared__ float smf[];
    float* kT = smf;                    // [HDIM][KPAD]
    float* vS = smf + HDIM * KPAD;      // [n_pad][HDIM]
    __shared__ float sq[32][HDIM];
    __shared__ float sp[32][32];

    const int bh = blockIdx.y;
    const int b = bh / NHEAD;
    const int h = bh % NHEAD;
    const int q0 = blockIdx.x * QB;
    int n_str = (q0 + QB - 1) / STRIDE_ + 1;
    if (n_str > KMAX) n_str = KMAX;
    const int n_pad = (n_str + 31) & ~31;

    const int tid = threadIdx.x;

    for (int idx = tid; idx < n_str * 16; idx += 512) {
        const int t = idx >> 4;
        const int d4 = (idx & 15) * 4;
        const int j = t * STRIDE_;
        const float* kb = qkv + ((size_t)(b * SEQ + j)) * (3 * DMODEL) + h * HDIM;
        float4 kv = *(const float4*)(kb + DMODEL + d4);
        float4 vv = *(const float4*)(kb + 2 * DMODEL + d4);
        kT[(d4 + 0) * KPAD + t] = kv.x;
        kT[(d4 + 1) * KPAD + t] = kv.y;
        kT[(d4 + 2) * KPAD + t] = kv.z;
        kT[(d4 + 3) * KPAD + t] = kv.w;
        *(float4*)&vS[t * HDIM + d4] = vv;
    }
    for (int idx = tid; idx < (n_pad - n_str) * 16; idx += 512) {
        const int t = n_str + (idx >> 4);
        const int d4 = (idx & 15) * 4;
        *(float4*)&vS[t * HDIM + d4] = make_float4(0.f, 0.f, 0.f, 0.f);
        kT[(d4 + 0) * KPAD + t] = 0.f;
        kT[(d4 + 1) * KPAD + t] = 0.f;
        kT[(d4 + 2) * KPAD + t] = 0.f;
        kT[(d4 + 3) * KPAD + t] = 0.f;
    }
    __syncthreads();

    const int w = tid >> 5;
    const int lane = tid & 31;
    const float scale = 0.125f;

    for (int pass = 0; pass < 4; ++pass) {
        const int ia = q0 + pass * 32 + w;
        const int ib = ia + 16;
        const size_t qba = (size_t)(b * SEQ + ia) * (3 * DMODEL) + h * HDIM;
        const size_t qbb = (size_t)(b * SEQ + ib) * (3 * DMODEL) + h * HDIM;
        const float qa0 = qkv[qba + lane], qa1 = qkv[qba + lane + 32];
        const float qb0 = qkv[qbb + lane], qb1 = qkv[qbb + lane + 32];
        sq[w][lane] = qa0;       sq[w][lane + 32] = qa1;
        sq[w + 16][lane] = qb0;  sq[w + 16][lane + 32] = qb1;
        __syncwarp();

        const int n_a = ia / STRIDE_ + 1;
        const int n_b = ib / STRIDE_ + 1;
        float ma = -1e30f, mb = -1e30f, la = 0.f, lb = 0.f;
        float oa0 = 0.f, oa1 = 0.f, ob0 = 0.f, ob1 = 0.f;

        for (int t0 = 0; t0 < n_b; t0 += 32) {
            const int t = t0 + lane;
            float da = 0.f, db = 0.f;
            #pragma unroll
            for (int d = 0; d < HDIM; d += 4) {
                const float4 a4 = *(const float4*)&sq[w][d];
                const float4 b4 = *(const float4*)&sq[w + 16][d];
                const float k0 = kT[(d + 0) * KPAD + t];
                const float k1 = kT[(d + 1) * KPAD + t];
                const float k2 = kT[(d + 2) * KPAD + t];
                const float k3 = kT[(d + 3) * KPAD + t];
                da += a4.x * k0 + a4.y * k1 + a4.z * k2 + a4.w * k3;
                db += b4.x * k0 + b4.y * k1 + b4.z * k2 + b4.w * k3;
            }
            const float sa = (t < n_a) ? da * scale : -1e30f;
            const float sb = (t < n_b) ? db * scale : -1e30f;

            float mxa = sa, mxb = sb;
            #pragma unroll
            for (int off = 16; off; off >>= 1) {
                mxa = fmaxf(mxa, __shfl_xor_sync(0xFFFFFFFFu, mxa, off));
                mxb = fmaxf(mxb, __shfl_xor_sync(0xFFFFFFFFu, mxb, off));
            }
            const float mna = fmaxf(ma, mxa);
            const float mnb = fmaxf(mb, mxb);
            const float ala = __expf(ma - mna);
            const float alb = __expf(mb - mnb);
            float pa = __expf(sa - mna);
            float pb = __expf(sb - mnb);
            float sua = pa, sub = pb;
            #pragma unroll
            for (int off = 16; off; off >>= 1) {
                sua += __shfl_xor_sync(0xFFFFFFFFu, sua, off);
                sub += __shfl_xor_sync(0xFFFFFFFFu, sub, off);
            }
            la = la * ala + sua;
            lb = lb * alb + sub;
            ma = mna;
            mb = mnb;

            sp[w][lane] = pa;
            sp[w + 16][lane] = pb;
            __syncwarp();

            float a0 = 0.f, a1 = 0.f, b0 = 0.f, b1 = 0.f;
            const float* vb = &vS[(size_t)t0 * HDIM + 2 * lane];
            #pragma unroll
            for (int j4 = 0; j4 < 32; j4 += 4) {
                const float4 p4a = *(const float4*)&sp[w][j4];
                const float4 p4b = *(const float4*)&sp[w + 16][j4];
                const float2 v0 = *(const float2*)&vb[(j4 + 0) * HDIM];
                const float2 v1 = *(const float2*)&vb[(j4 + 1) * HDIM];
                const float2 v2 = *(const float2*)&vb[(j4 + 2) * HDIM];
                const float2 v3 = *(const float2*)&vb[(j4 + 3) * HDIM];
                a0 += p4a.x * v0.x + p4a.y * v1.x + p4a.z * v2.x + p4a.w * v3.x;
                a1 += p4a.x * v0.y + p4a.y * v1.y + p4a.z * v2.y + p4a.w * v3.y;
                b0 += p4b.x * v0.x + p4b.y * v1.x + p4b.z * v2.x + p4b.w * v3.x;
                b1 += p4b.x * v0.y + p4b.y * v1.y + p4b.z * v2.y + p4b.w * v3.y;
            }
            oa0 = oa0 * ala + a0;
            oa1 = oa1 * ala + a1;
            ob0 = ob0 * alb + b0;
            ob1 = ob1 * alb + b1;
            __syncwarp();
        }

        #pragma unroll
        for (int sel = 0; sel < 2; ++sel) {
            const int i = sel ? ib : ia;
            const float q0r = sel ? qb0 : qa0;
            const float q1r = sel ? qb1 : qa1;
            float& m_ = sel ? mb : ma;
            float& l_ = sel ? lb : la;
            float& x0 = sel ? ob0 : oa0;
            float& x1 = sel ? ob1 : oa1;
            #pragma unroll
            for (int e = 0; e < 2; e++) {
                const int j = i - e;
                if (j >= 0 && (j & 7) != 0) {
                    const size_t kb = (size_t)(b * SEQ + j) * (3 * DMODEL) + h * HDIM;
                    float part = q0r * qkv[kb + DMODEL + lane] + q1r * qkv[kb + DMODEL + lane + 32];
                    #pragma unroll
                    for (int off = 16; off; off >>= 1)
                        part += __shfl_xor_sync(0xFFFFFFFFu, part, off);
                    const float s = part * scale;
                    const float mn = fmaxf(m_, s);
                    const float al = __expf(m_ - mn);
                    const float p = __expf(s - mn);
                    const float2 vv = *(const float2*)&qkv[kb + 2 * DMODEL + 2 * lane];
                    l_ = l_ * al + p;
                    x0 = x0 * al + p * vv.x;
                    x1 = x1 * al + p * vv.y;
                    m_ = mn;
                }
            }
        }

        {
            const float iva = 1.f / la, ivb = 1.f / lb;
            const float fa0 = oa0 * iva, fa1 = oa1 * iva;
            const float fb0 = ob0 * ivb, fb1 = ob1 * ivb;
            const size_t oba = (size_t)(b * SEQ + ia) * DMODEL + h * HDIM + 2 * lane;
            const size_t obb = (size_t)(b * SEQ + ib) * DMODEL + h * HDIM + 2 * lane;
            __nv_bfloat16 h0 = __float2bfloat16(fa0), h1 = __float2bfloat16(fa1);
            *(__nv_bfloat162*)&oh[oba] = __nv_bfloat162(h0, h1);
            *(__nv_bfloat162*)&ol[oba] = __nv_bfloat162(
                __float2bfloat16(fa0 - __bfloat162float(h0)),
                __float2bfloat16(fa1 - __bfloat162float(h1)));
            h0 = __float2bfloat16(fb0); h1 = __float2bfloat16(fb1);
            *(__nv_bfloat162*)&oh[obb] = __nv_bfloat162(h0, h1);
            *(__nv_bfloat162*)&ol[obb] = __nv_bfloat162(
                __float2bfloat16(fb0 - __bfloat162float(h0)),
                __float2bfloat16(fb1 - __bfloat162float(h1)));
        }
        __syncwarp();
    }
}

// ---------------- launcher ----------------
extern "C" void kernel_launch(void* const* d_in, const int* in_sizes, int n_in,
                              void* d_out, int out_size)
{
    const float* x      = (const float*)d_in[0];
    const float* qkv_w  = (const float*)d_in[1];
    const float* qkv_b  = (const float*)d_in[2];
    const float* out_w  = (const float*)d_in[3];
    const float* out_b  = (const float*)d_in[4];
    float* out = (float*)d_out;

    float* qkv; cudaGetSymbolAddress((void**)&qkv, g_qkv);
    __nv_bfloat16 *ah, *al, *bh, *bl, *owh, *owl, *xh, *xl;
    cudaGetSymbolAddress((void**)&ah,  g_ah);
    cudaGetSymbolAddress((void**)&al,  g_al);
    cudaGetSymbolAddress((void**)&bh,  g_bh);
    cudaGetSymbolAddress((void**)&bl,  g_bl);
    cudaGetSymbolAddress((void**)&owh, g_owh);
    cudaGetSymbolAddress((void**)&owl, g_owl);
    cudaGetSymbolAddress((void**)&xh,  g_xh);
    cudaGetSymbolAddress((void**)&xl,  g_xl);

    cudaFuncSetAttribute(gemm_mma_kernel, cudaFuncAttributeMaxDynamicSharedMemorySize, GEMM_SMEM);
    const int attn_smem = (HDIM * KPAD + KMAX * HDIM) * sizeof(float);
    cudaFuncSetAttribute(attn_kernel, cudaFuncAttributeMaxDynamicSharedMemorySize, attn_smem);

    // hi/lo splits of x and weights
    {
        int n4 = M_TOTAL * K_DIM / 4;
        conv_hilo_kernel<<<(n4 + 255) / 256, 256>>>(x, xh, xl, n4);
        n4 = N_QKV * K_DIM / 4;
        conv_hilo_kernel<<<(n4 + 255) / 256, 256>>>(qkv_w, bh, bl, n4);
        n4 = DMODEL * K_DIM / 4;
        conv_hilo_kernel<<<(n4 + 255) / 256, 256>>>(out_w, owh, owl, n4);
    }

    // 1) QKV projection: 576 CTAs, 2 CTAs/SM
    gemm_mma_kernel<<<dim3(N_QKV / 128, M_TOTAL / 128), 256, GEMM_SMEM>>>(
        xh, xl, bh, bl, qkv_b, qkv, N_QKV);

    // 2) strided attention (writes bf16 hi/lo directly)
    attn_kernel<<<dim3(SEQ / QB, BATCH * NHEAD), 512, attn_smem>>>(qkv, ah, al);

    // 3) output projection: 192 CTAs
    gemm_mma_kernel<<<dim3(DMODEL / 128, M_TOTAL / 128), 256, GEMM_SMEM>>>(
        ah, al, owh, owl, out_b, out, DMODEL);
}

// round 8
// speedup vs baseline: 1.2912x; 1.2912x over previous
#include <cuda_runtime.h>
#include <cuda_bf16.h>
#include <cstdint>

// ---------------- problem constants ----------------
#define BATCH 2
#define SEQ   2048
#define DMODEL 768
#define NHEAD 12
#define HDIM  64
#define STRIDE_ 8
#define QB    128

#define M_TOTAL (BATCH*SEQ)   // 4096
#define K_DIM   DMODEL        // 768
#define N_QKV   (3*DMODEL)    // 2304

// ---------------- device scratch ----------------
__device__ float g_qkv[M_TOTAL * N_QKV];
__device__ __nv_bfloat16 g_ah[M_TOTAL * K_DIM];
__device__ __nv_bfloat16 g_al[M_TOTAL * K_DIM];
__device__ __nv_bfloat16 g_bh[N_QKV * K_DIM];
__device__ __nv_bfloat16 g_bl[N_QKV * K_DIM];
__device__ __nv_bfloat16 g_owh[DMODEL * K_DIM];
__device__ __nv_bfloat16 g_owl[DMODEL * K_DIM];
__device__ __nv_bfloat16 g_xh[M_TOTAL * K_DIM];
__device__ __nv_bfloat16 g_xl[M_TOTAL * K_DIM];

// ---------------- PTX helpers (portable: sm_80+) ----------------
__device__ __forceinline__ uint32_t smem_u32(const void* p) {
    uint32_t a;
    asm("{ .reg .u64 t; cvta.to.shared.u64 t, %1; cvt.u32.u64 %0, t; }" : "=r"(a) : "l"(p));
    return a;
}

#define CP_ASYNC16(dst, src) \
    asm volatile("cp.async.cg.shared.global [%0], [%1], 16;" :: "r"(dst), "l"(src))
#define CP_COMMIT() asm volatile("cp.async.commit_group;" ::: "memory")
#define CP_WAIT1() asm volatile("cp.async.wait_group 1;" ::: "memory")
#define CP_WAIT0() asm volatile("cp.async.wait_group 0;" ::: "memory")

#define LDSM_X4(r0, r1, r2, r3, addr) \
    asm volatile("ldmatrix.sync.aligned.m8n8.x4.shared.b16 {%0,%1,%2,%3}, [%4];" \
        : "=r"(r0), "=r"(r1), "=r"(r2), "=r"(r3) : "r"(addr))

#define LDSM_X4_T(r0, r1, r2, r3, addr) \
    asm volatile("ldmatrix.sync.aligned.m8n8.x4.trans.shared.b16 {%0,%1,%2,%3}, [%4];" \
        : "=r"(r0), "=r"(r1), "=r"(r2), "=r"(r3) : "r"(addr))

#define MMA_BF16(c, a0, a1, a2, a3, b0, b1) \
    asm("mma.sync.aligned.m16n8k16.row.col.f32.bf16.bf16.f32 " \
        "{%0,%1,%2,%3}, {%4,%5,%6,%7}, {%8,%9}, {%0,%1,%2,%3};" \
        : "+f"((c)[0]), "+f"((c)[1]), "+f"((c)[2]), "+f"((c)[3]) \
        : "r"(a0), "r"(a1), "r"(a2), "r"(a3), "r"(b0), "r"(b1))

#define MMA_BF16A(c, a, b) MMA_BF16(c, (a)[0], (a)[1], (a)[2], (a)[3], (b)[0], (b)[1])

// pack two fp32 into bf16x2 (hi=b, lo=a) + residual pack
__device__ __forceinline__ uint32_t pack_bf16x2(float a, float b) {
    uint32_t r;
    asm("cvt.rn.bf16x2.f32 %0, %1, %2;" : "=r"(r) : "f"(b), "f"(a));
    return r;
}
__device__ __forceinline__ void hilo2(float a, float b, uint32_t& hp, uint32_t& lp) {
    hp = pack_bf16x2(a, b);
    float fa = __uint_as_float(hp << 16);
    float fb = __uint_as_float(hp & 0xffff0000u);
    lp = pack_bf16x2(a - fa, b - fb);
}

// ---------------- fp32 -> bf16 hi/lo split ----------------
__global__ __launch_bounds__(256)
void conv_hilo_kernel(const float* __restrict__ in, __nv_bfloat16* __restrict__ hi,
                      __nv_bfloat16* __restrict__ lo, int n4)
{
    int i = blockIdx.x * 256 + threadIdx.x;
    if (i >= n4) return;
    float4 v = ((const float4*)in)[i];
    uint32_t h0, l0, h1, l1;
    hilo2(v.x, v.y, h0, l0);
    hilo2(v.z, v.w, h1, l1);
    ((uint2*)hi)[i] = make_uint2(h0, h1);
    ((uint2*)lo)[i] = make_uint2(l0, l1);
}

// ---------------- mma.sync GEMM: 128x128, 2-stage, 2 CTAs/SM ----------------
#define GBK 32
#define NCHUNK (K_DIM / GBK)          // 24
#define TPAD 40
#define TILE_BYTES (128 * TPAD * 2)   // 10240
#define STAGE_BYTES (4 * TILE_BYTES)  // 40960
#define GEMM_SMEM (2 * STAGE_BYTES)   // 81920 -> 2 CTAs/SM

__global__ __launch_bounds__(256, 2)
void gemm_mma_kernel(const __nv_bfloat16* __restrict__ Ah, const __nv_bfloat16* __restrict__ Al,
                     const __nv_bfloat16* __restrict__ Bh, const __nv_bfloat16* __restrict__ Bl,
                     const float* __restrict__ bias, float* __restrict__ C, int N)
{
    extern __shared__ char dsm[];
    const uint32_t sbase = smem_u32(dsm);
    const int tid = threadIdx.x;
    const int lane = tid & 31;
    const int wid = tid >> 5;
    const int wm = (wid & 1) * 64;
    const int wn = (wid >> 1) * 32;
    const int bm = blockIdx.y * 128;
    const int bn = blockIdx.x * 128;

    const __nv_bfloat16* gp[4] = { Ah, Al, Bh, Bl };

    float acc[4][4][4];
    #pragma unroll
    for (int i = 0; i < 4; i++)
        #pragma unroll
        for (int j = 0; j < 4; j++)
            #pragma unroll
            for (int r = 0; r < 4; r++) acc[i][j][r] = 0.f;

    auto issue = [&](int stage, int kc) {
        const uint32_t st = sbase + (uint32_t)stage * STAGE_BYTES;
        #pragma unroll
        for (int t = 0; t < 8; ++t) {
            int task = tid + t * 256;
            int tile = task >> 9;
            int idx  = task & 511;
            int r = idx >> 2, q = idx & 3;
            int row = (tile < 2 ? bm : bn) + r;
            uint32_t dst = st + (uint32_t)tile * TILE_BYTES + (uint32_t)(r * TPAD + q * 8) * 2;
            CP_ASYNC16(dst, gp[tile] + (size_t)row * K_DIM + kc + q * 8);
        }
        CP_COMMIT();
    };

    issue(0, 0);
    issue(1, GBK);

    const int g = lane >> 3;
    const int arow = wm + (g & 1) * 8 + (lane & 7);
    const int acoff = (g >> 1) * 8;
    const int brow0 = wn + (g >> 1) * 8 + (lane & 7);
    const int bcoff = (g & 1) * 8;

    for (int c = 0; c < NCHUNK; ++c) {
        if (c + 1 < NCHUNK) { CP_WAIT1(); } else { CP_WAIT0(); }
        __syncthreads();

        const uint32_t st = sbase + (uint32_t)(c & 1) * STAGE_BYTES;
        const uint32_t aH = st;
        const uint32_t aL = st + TILE_BYTES;
        const uint32_t bH = st + 2 * TILE_BYTES;
        const uint32_t bL = st + 3 * TILE_BYTES;

        #pragma unroll
        for (int ks = 0; ks < 2; ++ks) {
            const int acol = ks * 16 + acoff;
            const int bcol = ks * 16 + bcoff;
            uint32_t ah[4][4], al[4][4];
            #pragma unroll
            for (int mf = 0; mf < 4; ++mf) {
                uint32_t off = (uint32_t)((arow + mf * 16) * TPAD + acol) * 2;
                LDSM_X4(ah[mf][0], ah[mf][1], ah[mf][2], ah[mf][3], aH + off);
                LDSM_X4(al[mf][0], al[mf][1], al[mf][2], al[mf][3], aL + off);
            }
            #pragma unroll
            for (int nf2 = 0; nf2 < 2; ++nf2) {
                uint32_t off = (uint32_t)((brow0 + nf2 * 16) * TPAD + bcol) * 2;
                uint32_t bh[2][2], bl[2][2];
                LDSM_X4(bh[0][0], bh[0][1], bh[1][0], bh[1][1], bH + off);
                LDSM_X4(bl[0][0], bl[0][1], bl[1][0], bl[1][1], bL + off);
                #pragma unroll
                for (int mf = 0; mf < 4; ++mf)
                    #pragma unroll
                    for (int q = 0; q < 2; ++q)
                        MMA_BF16A(acc[mf][2 * nf2 + q], ah[mf], bh[q]);
                #pragma unroll
                for (int mf = 0; mf < 4; ++mf)
                    #pragma unroll
                    for (int q = 0; q < 2; ++q)
                        MMA_BF16A(acc[mf][2 * nf2 + q], ah[mf], bl[q]);
                #pragma unroll
                for (int mf = 0; mf < 4; ++mf)
                    #pragma unroll
                    for (int q = 0; q < 2; ++q)
                        MMA_BF16A(acc[mf][2 * nf2 + q], al[mf], bh[q]);
            }
        }
        __syncthreads();
        if (c + 2 < NCHUNK) issue(c & 1, (c + 2) * GBK);
    }

    #pragma unroll
    for (int mf = 0; mf < 4; ++mf) {
        const int m = bm + wm + mf * 16 + (lane >> 2);
        #pragma unroll
        for (int nf = 0; nf < 4; ++nf) {
            const int n = bn + wn + nf * 8 + (lane & 3) * 2;
            const float2 bv = *(const float2*)&bias[n];
            float2 v0 = { acc[mf][nf][0] + bv.x, acc[mf][nf][1] + bv.y };
            float2 v1 = { acc[mf][nf][2] + bv.x, acc[mf][nf][3] + bv.y };
            *(float2*)&C[(size_t)m * N + n]       = v0;
            *(float2*)&C[(size_t)(m + 8) * N + n] = v1;
        }
    }
}

// ================= MMA flash attention (strided mask) =================
// smem layout (bytes), row stride 72 bf16 = 144 B
#define TROWB 144
#define AT_KH 0
#define AT_KL 36864
#define AT_VH 73728
#define AT_VL 110592
#define AT_QH 147456
#define AT_QL 165888
#define ATTN_SMEM 184320

__global__ __launch_bounds__(256, 1)
void attn_mma_kernel(const float* __restrict__ qkv,
                     __nv_bfloat16* __restrict__ oh, __nv_bfloat16* __restrict__ ol)
{
    extern __shared__ char smraw[];
    const uint32_t sb = smem_u32(smraw);
    const int tid = threadIdx.x;
    const int lane = tid & 31;
    const int w = tid >> 5;

    const int bh = blockIdx.y;
    const int b = bh / NHEAD;
    const int h = bh % NHEAD;
    const int qb = blockIdx.x;
    const int q0 = qb * QB;
    const int n_str = 16 * (qb + 1);               // strided keys for this block (t-units)
    const int n_pad = (n_str + 63) & ~63;

    // ---- stage K, V (strided rows) as bf16 hi/lo ----
    for (int task = tid; task < n_str * 16; task += 256) {
        const int t   = task >> 4;
        const int sel = (task >> 3) & 1;            // 0 = K, 1 = V
        const int d8  = (task & 7) << 3;
        const size_t src = (size_t)(b * SEQ + t * STRIDE_) * (3 * DMODEL)
                         + (size_t)(1 + sel) * DMODEL + h * HDIM + d8;
        const float4 v0 = *(const float4*)&qkv[src];
        const float4 v1 = *(const float4*)&qkv[src + 4];
        uint32_t hp0, lp0, hp1, lp1, hp2, lp2, hp3, lp3;
        hilo2(v0.x, v0.y, hp0, lp0);
        hilo2(v0.z, v0.w, hp1, lp1);
        hilo2(v1.x, v1.y, hp2, lp2);
        hilo2(v1.z, v1.w, hp3, lp3);
        const int dst = t * TROWB + d8 * 2;
        *(uint4*)(smraw + (sel ? AT_VH : AT_KH) + dst) = make_uint4(hp0, hp1, hp2, hp3);
        *(uint4*)(smraw + (sel ? AT_VL : AT_KL) + dst) = make_uint4(lp0, lp1, lp2, lp3);
    }
    // zero-fill tail rows [n_str, n_pad)
    for (int task = tid; task < (n_pad - n_str) * 8; task += 256) {
        const int t  = n_str + (task >> 3);
        const int d8 = (task & 7) << 3;
        const int dst = t * TROWB + d8 * 2;
        const uint4 z = make_uint4(0, 0, 0, 0);
        *(uint4*)(smraw + AT_KH + dst) = z;
        *(uint4*)(smraw + AT_KL + dst) = z;
        *(uint4*)(smraw + AT_VH + dst) = z;
        *(uint4*)(smraw + AT_VL + dst) = z;
    }
    // stage Q (pre-scaled by 1/8) as bf16 hi/lo
    for (int task = tid; task < 128 * 8; task += 256) {
        const int r  = task >> 3;
        const int d8 = (task & 7) << 3;
        const size_t src = (size_t)(b * SEQ + q0 + r) * (3 * DMODEL) + h * HDIM + d8;
        float4 v0 = *(const float4*)&qkv[src];
        float4 v1 = *(const float4*)&qkv[src + 4];
        v0.x *= 0.125f; v0.y *= 0.125f; v0.z *= 0.125f; v0.w *= 0.125f;
        v1.x *= 0.125f; v1.y *= 0.125f; v1.z *= 0.125f; v1.w *= 0.125f;
        uint32_t hp0, lp0, hp1, lp1, hp2, lp2, hp3, lp3;
        hilo2(v0.x, v0.y, hp0, lp0);
        hilo2(v0.z, v0.w, hp1, lp1);
        hilo2(v1.x, v1.y, hp2, lp2);
        hilo2(v1.z, v1.w, hp3, lp3);
        const int dst = r * TROWB + d8 * 2;
        *(uint4*)(smraw + AT_QH + dst) = make_uint4(hp0, hp1, hp2, hp3);
        *(uint4*)(smraw + AT_QL + dst) = make_uint4(lp0, lp1, lp2, lp3);
    }
    __syncthreads();

    // ---- per-warp fragment setup ----
    const int g = lane >> 3;
    const int tig = lane & 3;
    // A (Q) addressing: same scheme as GEMM kernel
    const int arow = 16 * w + (g & 1) * 8 + (lane & 7);
    const int acoff = (g >> 1) * 8;
    uint32_t qh[4][4], ql[4][4];
    #pragma unroll
    for (int kd = 0; kd < 4; ++kd) {
        const uint32_t off = (uint32_t)(arow * TROWB + (kd * 16 + acoff) * 2);
        LDSM_X4(qh[kd][0], qh[kd][1], qh[kd][2], qh[kd][3], sb + AT_QH + off);
        LDSM_X4(ql[kd][0], ql[kd][1], ql[kd][2], ql[kd][3], sb + AT_QL + off);
    }

    float ofr[8][4];
    #pragma unroll
    for (int i = 0; i < 8; i++) { ofr[i][0]=0.f; ofr[i][1]=0.f; ofr[i][2]=0.f; ofr[i][3]=0.f; }
    float m0 = -1e30f, m1 = -1e30f, l0 = 0.f, l1 = 0.f;

    const int row0q = q0 + 16 * w + (lane >> 2);
    const int nt0 = (row0q >> 3) + 1;               // valid t count for row0
    const int nt1 = ((row0q + 8) >> 3) + 1;         // for row1
    const int nchunks = (16 * qb + 2 * w + 2 + 63) >> 6;

    // B (K) addressing (same as GEMM B side)
    const int skrow = (g >> 1) * 8 + (lane & 7);
    const int sdcol = (g & 1) * 8;
    // B (V, trans) addressing
    const int vkrow = (g & 1) * 8 + (lane & 7);
    const int vdcol = (g >> 1) * 8;

    for (int ch = 0; ch < nchunks; ++ch) {
        const int c0 = ch * 64;
        float sfr[8][4];
        #pragma unroll
        for (int i = 0; i < 8; i++) { sfr[i][0]=0.f; sfr[i][1]=0.f; sfr[i][2]=0.f; sfr[i][3]=0.f; }

        // S = Qh*Kh + Ql*Kh + Qh*Kl
        #pragma unroll
        for (int kd = 0; kd < 4; ++kd) {
            #pragma unroll
            for (int kg = 0; kg < 4; ++kg) {
                const uint32_t addr = sb + AT_KH +
                    (uint32_t)((c0 + kg * 16 + skrow) * TROWB + (kd * 16 + sdcol) * 2);
                uint32_t kh[4], kl[4];
                LDSM_X4(kh[0], kh[1], kh[2], kh[3], addr);
                LDSM_X4(kl[0], kl[1], kl[2], kl[3], addr + (AT_KL - AT_KH));
                MMA_BF16(sfr[2*kg],   qh[kd][0], qh[kd][1], qh[kd][2], qh[kd][3], kh[0], kh[1]);
                MMA_BF16(sfr[2*kg+1], qh[kd][0], qh[kd][1], qh[kd][2], qh[kd][3], kh[2], kh[3]);
                MMA_BF16(sfr[2*kg],   ql[kd][0], ql[kd][1], ql[kd][2], ql[kd][3], kh[0], kh[1]);
                MMA_BF16(sfr[2*kg+1], ql[kd][0], ql[kd][1], ql[kd][2], ql[kd][3], kh[2], kh[3]);
                MMA_BF16(sfr[2*kg],   qh[kd][0], qh[kd][1], qh[kd][2], qh[kd][3], kl[0], kl[1]);
                MMA_BF16(sfr[2*kg+1], qh[kd][0], qh[kd][1], qh[kd][2], qh[kd][3], kl[2], kl[3]);
            }
        }

        // mask + online softmax stats
        float mx0 = -1e30f, mx1 = -1e30f;
        #pragma unroll
        for (int nf = 0; nf < 8; ++nf) {
            const int tb = c0 + nf * 8 + 2 * tig;
            if (tb >= nt0)     sfr[nf][0] = -1e30f;
            if (tb + 1 >= nt0) sfr[nf][1] = -1e30f;
            if (tb >= nt1)     sfr[nf][2] = -1e30f;
            if (tb + 1 >= nt1) sfr[nf][3] = -1e30f;
            mx0 = fmaxf(mx0, fmaxf(sfr[nf][0], sfr[nf][1]));
            mx1 = fmaxf(mx1, fmaxf(sfr[nf][2], sfr[nf][3]));
        }
        mx0 = fmaxf(mx0, __shfl_xor_sync(0xFFFFFFFFu, mx0, 1));
        mx0 = fmaxf(mx0, __shfl_xor_sync(0xFFFFFFFFu, mx0, 2));
        mx1 = fmaxf(mx1, __shfl_xor_sync(0xFFFFFFFFu, mx1, 1));
        mx1 = fmaxf(mx1, __shfl_xor_sync(0xFFFFFFFFu, mx1, 2));
        const float mn0 = fmaxf(m0, mx0);
        const float mn1 = fmaxf(m1, mx1);
        const float al0 = __expf(m0 - mn0);
        const float al1 = __expf(m1 - mn1);
        float s0 = 0.f, s1 = 0.f;
        #pragma unroll
        for (int nf = 0; nf < 8; ++nf) {
            sfr[nf][0] = __expf(sfr[nf][0] - mn0);
            sfr[nf][1] = __expf(sfr[nf][1] - mn0);
            sfr[nf][2] = __expf(sfr[nf][2] - mn1);
            sfr[nf][3] = __expf(sfr[nf][3] - mn1);
            s0 += sfr[nf][0] + sfr[nf][1];
            s1 += sfr[nf][2] + sfr[nf][3];
        }
        s0 += __shfl_xor_sync(0xFFFFFFFFu, s0, 1);
        s0 += __shfl_xor_sync(0xFFFFFFFFu, s0, 2);
        s1 += __shfl_xor_sync(0xFFFFFFFFu, s1, 1);
        s1 += __shfl_xor_sync(0xFFFFFFFFu, s1, 2);
        l0 = l0 * al0 + s0;
        l1 = l1 * al1 + s1;
        m0 = mn0; m1 = mn1;
        #pragma unroll
        for (int nf = 0; nf < 8; ++nf) {
            ofr[nf][0] *= al0; ofr[nf][1] *= al0;
            ofr[nf][2] *= al1; ofr[nf][3] *= al1;
        }

        // pack P into A fragments (hi + residual)
        uint32_t ph[4][4], pl[4][4];
        #pragma unroll
        for (int kk = 0; kk < 4; ++kk) {
            hilo2(sfr[2*kk][0],   sfr[2*kk][1],   ph[kk][0], pl[kk][0]);
            hilo2(sfr[2*kk][2],   sfr[2*kk][3],   ph[kk][1], pl[kk][1]);
            hilo2(sfr[2*kk+1][0], sfr[2*kk+1][1], ph[kk][2], pl[kk][2]);
            hilo2(sfr[2*kk+1][2], sfr[2*kk+1][3], ph[kk][3], pl[kk][3]);
        }

        // O += Ph*Vh + Pl*Vh + Ph*Vl
        #pragma unroll
        for (int kk = 0; kk < 4; ++kk) {
            #pragma unroll
            for (int dd = 0; dd < 4; ++dd) {
                const uint32_t addr = sb + AT_VH +
                    (uint32_t)((c0 + kk * 16 + vkrow) * TROWB + (dd * 16 + vdcol) * 2);
                uint32_t vh[4], vl[4];
                LDSM_X4_T(vh[0], vh[1], vh[2], vh[3], addr);
                LDSM_X4_T(vl[0], vl[1], vl[2], vl[3], addr + (AT_VL - AT_VH));
                MMA_BF16(ofr[2*dd],   ph[kk][0], ph[kk][1], ph[kk][2], ph[kk][3], vh[0], vh[1]);
                MMA_BF16(ofr[2*dd+1], ph[kk][0], ph[kk][1], ph[kk][2], ph[kk][3], vh[2], vh[3]);
                MMA_BF16(ofr[2*dd],   pl[kk][0], pl[kk][1], pl[kk][2], pl[kk][3], vh[0], vh[1]);
                MMA_BF16(ofr[2*dd+1], pl[kk][0], pl[kk][1], pl[kk][2], pl[kk][3], vh[2], vh[3]);
                MMA_BF16(ofr[2*dd],   ph[kk][0], ph[kk][1], ph[kk][2], ph[kk][3], vl[0], vl[1]);
                MMA_BF16(ofr[2*dd+1], ph[kk][0], ph[kk][1], ph[kk][2], ph[kk][3], vl[2], vl[3]);
            }
        }
    }

    // ---- epilogue: dump O + stats, scalar local keys, write bf16 hi/lo ----
    __syncthreads();                                 // all warps done reading K/V
    float* sO = (float*)smraw;                       // [128][64] fp32, reuses K region
    float* sM = (float*)(smraw + AT_VH);             // [128]
    float* sL = sM + 128;                            // [128]
    {
        const int r0 = 16 * w + (lane >> 2);
        #pragma unroll
        for (int nf = 0; nf < 8; ++nf) {
            const int col = nf * 8 + 2 * tig;
            sO[r0 * 64 + col]       = ofr[nf][0];
            sO[r0 * 64 + col + 1]   = ofr[nf][1];
            sO[(r0+8) * 64 + col]   = ofr[nf][2];
            sO[(r0+8) * 64 + col+1] = ofr[nf][3];
        }
        if (tig == 0) {
            sM[r0] = m0; sL[r0] = l0;
            sM[r0 + 8] = m1; sL[r0 + 8] = l1;
        }
    }
    __syncwarp();

    for (int r = 0; r < 16; ++r) {
        const int srow = 16 * w + r;
        const int i = q0 + srow;
        float m_ = sM[srow], l_ = sL[srow];
        float x0 = sO[srow * 64 + lane];
        float x1 = sO[srow * 64 + lane + 32];
        const size_t qbase = (size_t)(b * SEQ + i) * (3 * DMODEL) + h * HDIM;
        const float q0v = qkv[qbase + lane];
        const float q1v = qkv[qbase + lane + 32];
        #pragma unroll
        for (int e = 0; e < 2; ++e) {
            const int j = i - e;
            if (j >= 0 && (j & 7) != 0) {
                const size_t kb = (size_t)(b * SEQ + j) * (3 * DMODEL) + h * HDIM + DMODEL;
                float part = q0v * qkv[kb + lane] + q1v * qkv[kb + lane + 32];
                #pragma unroll
                for (int off = 16; off; off >>= 1)
                    part += __shfl_xor_sync(0xFFFFFFFFu, part, off);
                const float s = part * 0.125f;
                const float mn = fmaxf(m_, s);
                const float al = __expf(m_ - mn);
                const float p = __expf(s - mn);
                x0 = x0 * al + p * qkv[kb + DMODEL + lane];
                x1 = x1 * al + p * qkv[kb + DMODEL + lane + 32];
                l_ = l_ * al + p;
                m_ = mn;
            }
        }
        const float inv = 1.f / l_;
        const float fa0 = x0 * inv, fa1 = x1 * inv;
        const size_t ob = (size_t)(b * SEQ + i) * DMODEL + h * HDIM;
        const __nv_bfloat16 h0 = __float2bfloat16(fa0);
        const __nv_bfloat16 h1 = __float2bfloat16(fa1);
        oh[ob + lane]      = h0;
        oh[ob + lane + 32] = h1;
        ol[ob + lane]      = __float2bfloat16(fa0 - __bfloat162float(h0));
        ol[ob + lane + 32] = __float2bfloat16(fa1 - __bfloat162float(h1));
    }
}

// ---------------- launcher ----------------
extern "C" void kernel_launch(void* const* d_in, const int* in_sizes, int n_in,
                              void* d_out, int out_size)
{
    const float* x      = (const float*)d_in[0];
    const float* qkv_w  = (const float*)d_in[1];
    const float* qkv_b  = (const float*)d_in[2];
    const float* out_w  = (const float*)d_in[3];
    const float* out_b  = (const float*)d_in[4];
    float* out = (float*)d_out;

    float* qkv; cudaGetSymbolAddress((void**)&qkv, g_qkv);
    __nv_bfloat16 *ah, *al, *bh, *bl, *owh, *owl, *xh, *xl;
    cudaGetSymbolAddress((void**)&ah,  g_ah);
    cudaGetSymbolAddress((void**)&al,  g_al);
    cudaGetSymbolAddress((void**)&bh,  g_bh);
    cudaGetSymbolAddress((void**)&bl,  g_bl);
    cudaGetSymbolAddress((void**)&owh, g_owh);
    cudaGetSymbolAddress((void**)&owl, g_owl);
    cudaGetSymbolAddress((void**)&xh,  g_xh);
    cudaGetSymbolAddress((void**)&xl,  g_xl);

    cudaFuncSetAttribute(gemm_mma_kernel, cudaFuncAttributeMaxDynamicSharedMemorySize, GEMM_SMEM);
    cudaFuncSetAttribute(attn_mma_kernel, cudaFuncAttributeMaxDynamicSharedMemorySize, ATTN_SMEM);

    // hi/lo splits of x and weights
    {
        int n4 = M_TOTAL * K_DIM / 4;
        conv_hilo_kernel<<<(n4 + 255) / 256, 256>>>(x, xh, xl, n4);
        n4 = N_QKV * K_DIM / 4;
        conv_hilo_kernel<<<(n4 + 255) / 256, 256>>>(qkv_w, bh, bl, n4);
        n4 = DMODEL * K_DIM / 4;
        conv_hilo_kernel<<<(n4 + 255) / 256, 256>>>(out_w, owh, owl, n4);
    }

    // 1) QKV projection
    gemm_mma_kernel<<<dim3(N_QKV / 128, M_TOTAL / 128), 256, GEMM_SMEM>>>(
        xh, xl, bh, bl, qkv_b, qkv, N_QKV);

    // 2) strided attention on tensor cores (writes bf16 hi/lo directly)
    attn_mma_kernel<<<dim3(SEQ / QB, BATCH * NHEAD), 256, ATTN_SMEM>>>(qkv, ah, al);

    // 3) output projection
    gemm_mma_kernel<<<dim3(DMODEL / 128, M_TOTAL / 128), 256, GEMM_SMEM>>>(
        ah, al, owh, owl, out_b, out, DMODEL);
}

// round 9
// speedup vs baseline: 1.5963x; 1.2363x over previous
#include <cuda_runtime.h>
#include <cuda_bf16.h>
#include <cuda_fp16.h>
#include <cstdint>

// ---------------- problem constants ----------------
#define BATCH 2
#define SEQ   2048
#define DMODEL 768
#define NHEAD 12
#define HDIM  64
#define STRIDE_ 8
#define QB    128

#define M_TOTAL (BATCH*SEQ)   // 4096
#define K_DIM   DMODEL        // 768
#define N_QKV   (3*DMODEL)    // 2304

// ---------------- device scratch ----------------
__device__ float g_qkv[M_TOTAL * N_QKV];
__device__ __half g_ah[M_TOTAL * K_DIM];    // attention out hi
__device__ __half g_al[M_TOTAL * K_DIM];    // attention out lo
__device__ __half g_bh[N_QKV * K_DIM];      // qkv_w fp16
__device__ __half g_owh[DMODEL * K_DIM];    // out_w fp16
__device__ __half g_xh[M_TOTAL * K_DIM];    // x hi
__device__ __half g_xl[M_TOTAL * K_DIM];    // x lo

// ---------------- PTX helpers (portable: sm_80+) ----------------
__device__ __forceinline__ uint32_t smem_u32(const void* p) {
    uint32_t a;
    asm("{ .reg .u64 t; cvta.to.shared.u64 t, %1; cvt.u32.u64 %0, t; }" : "=r"(a) : "l"(p));
    return a;
}

#define CP_ASYNC16(dst, src) \
    asm volatile("cp.async.cg.shared.global [%0], [%1], 16;" :: "r"(dst), "l"(src))
#define CP_COMMIT() asm volatile("cp.async.commit_group;" ::: "memory")
#define CP_WAIT1() asm volatile("cp.async.wait_group 1;" ::: "memory")
#define CP_WAIT0() asm volatile("cp.async.wait_group 0;" ::: "memory")

#define LDSM_X4(r0, r1, r2, r3, addr) \
    asm volatile("ldmatrix.sync.aligned.m8n8.x4.shared.b16 {%0,%1,%2,%3}, [%4];" \
        : "=r"(r0), "=r"(r1), "=r"(r2), "=r"(r3) : "r"(addr))

#define LDSM_X4_T(r0, r1, r2, r3, addr) \
    asm volatile("ldmatrix.sync.aligned.m8n8.x4.trans.shared.b16 {%0,%1,%2,%3}, [%4];" \
        : "=r"(r0), "=r"(r1), "=r"(r2), "=r"(r3) : "r"(addr))

#define MMA_BF16(c, a0, a1, a2, a3, b0, b1) \
    asm("mma.sync.aligned.m16n8k16.row.col.f32.bf16.bf16.f32 " \
        "{%0,%1,%2,%3}, {%4,%5,%6,%7}, {%8,%9}, {%0,%1,%2,%3};" \
        : "+f"((c)[0]), "+f"((c)[1]), "+f"((c)[2]), "+f"((c)[3]) \
        : "r"(a0), "r"(a1), "r"(a2), "r"(a3), "r"(b0), "r"(b1))

#define MMA_F16(c, a0, a1, a2, a3, b0, b1) \
    asm("mma.sync.aligned.m16n8k16.row.col.f32.f16.f16.f32 " \
        "{%0,%1,%2,%3}, {%4,%5,%6,%7}, {%8,%9}, {%0,%1,%2,%3};" \
        : "+f"((c)[0]), "+f"((c)[1]), "+f"((c)[2]), "+f"((c)[3]) \
        : "r"(a0), "r"(a1), "r"(a2), "r"(a3), "r"(b0), "r"(b1))

// bf16 hi/lo pack (attention internals)
__device__ __forceinline__ uint32_t pack_bf16x2(float a, float b) {
    uint32_t r;
    asm("cvt.rn.bf16x2.f32 %0, %1, %2;" : "=r"(r) : "f"(b), "f"(a));
    return r;
}
__device__ __forceinline__ void hilo2(float a, float b, uint32_t& hp, uint32_t& lp) {
    hp = pack_bf16x2(a, b);
    float fa = __uint_as_float(hp << 16);
    float fb = __uint_as_float(hp & 0xffff0000u);
    lp = pack_bf16x2(a - fa, b - fb);
}

// fp16 hi/lo pack (GEMM operands)
__device__ __forceinline__ void hilo2_f16(float a, float b, uint32_t& hp, uint32_t& lp) {
    __half2 h = __floats2half2_rn(a, b);
    hp = *(uint32_t*)&h;
    __half2 l = __floats2half2_rn(a - __half2float(__low2half(h)),
                                  b - __half2float(__high2half(h)));
    lp = *(uint32_t*)&l;
}

// ---------------- fp32 -> fp16 hi/lo split ----------------
__global__ __launch_bounds__(256)
void conv_hilo_kernel(const float* __restrict__ in, __half* __restrict__ hi,
                      __half* __restrict__ lo, int n4)
{
    int i = blockIdx.x * 256 + threadIdx.x;
    if (i >= n4) return;
    float4 v = ((const float4*)in)[i];
    uint32_t h0, l0, h1, l1;
    hilo2_f16(v.x, v.y, h0, l0);
    hilo2_f16(v.z, v.w, h1, l1);
    ((uint2*)hi)[i] = make_uint2(h0, h1);
    ((uint2*)lo)[i] = make_uint2(l0, l1);
}

// fp32 -> fp16 (single, for weights)
__global__ __launch_bounds__(256)
void conv_h_kernel(const float* __restrict__ in, __half* __restrict__ hi, int n4)
{
    int i = blockIdx.x * 256 + threadIdx.x;
    if (i >= n4) return;
    float4 v = ((const float4*)in)[i];
    __half2 a = __floats2half2_rn(v.x, v.y);
    __half2 b = __floats2half2_rn(v.z, v.w);
    ((uint2*)hi)[i] = make_uint2(*(uint32_t*)&a, *(uint32_t*)&b);
}

// ------- fp16 2-product GEMM: C = (Ah+Al)[M,768] * (Bh[N,768])^T + bias -------
#define GBK 32
#define NCHUNK (K_DIM / GBK)          // 24
#define TPAD 40
#define TILE_BYTES (128 * TPAD * 2)   // 10240
#define STAGE_BYTES (3 * TILE_BYTES)  // 30720 (Ah, Al, Bh)
#define GEMM_SMEM (2 * STAGE_BYTES)   // 61440 -> 2 CTAs/SM

__global__ __launch_bounds__(256, 2)
void gemm_mma_kernel(const __half* __restrict__ Ah, const __half* __restrict__ Al,
                     const __half* __restrict__ Bh,
                     const float* __restrict__ bias, float* __restrict__ C, int N)
{
    extern __shared__ char dsm[];
    const uint32_t sbase = smem_u32(dsm);
    const int tid = threadIdx.x;
    const int lane = tid & 31;
    const int wid = tid >> 5;
    const int wm = (wid & 1) * 64;
    const int wn = (wid >> 1) * 32;
    const int bm = blockIdx.y * 128;
    const int bn = blockIdx.x * 128;

    const __half* gp[3] = { Ah, Al, Bh };

    float acc[4][4][4];
    #pragma unroll
    for (int i = 0; i < 4; i++)
        #pragma unroll
        for (int j = 0; j < 4; j++)
            #pragma unroll
            for (int r = 0; r < 4; r++) acc[i][j][r] = 0.f;

    auto issue = [&](int stage, int kc) {
        const uint32_t st = sbase + (uint32_t)stage * STAGE_BYTES;
        #pragma unroll
        for (int t = 0; t < 6; ++t) {
            int task = tid + t * 256;          // 0..1535
            int tile = task >> 9;              // 0..2
            int idx  = task & 511;
            int r = idx >> 2, q = idx & 3;
            int row = (tile < 2 ? bm : bn) + r;
            uint32_t dst = st + (uint32_t)tile * TILE_BYTES + (uint32_t)(r * TPAD + q * 8) * 2;
            CP_ASYNC16(dst, gp[tile] + (size_t)row * K_DIM + kc + q * 8);
        }
        CP_COMMIT();
    };

    issue(0, 0);
    issue(1, GBK);

    const int g = lane >> 3;
    const int arow = wm + (g & 1) * 8 + (lane & 7);
    const int acoff = (g >> 1) * 8;
    const int brow0 = wn + (g >> 1) * 8 + (lane & 7);
    const int bcoff = (g & 1) * 8;

    for (int c = 0; c < NCHUNK; ++c) {
        if (c + 1 < NCHUNK) { CP_WAIT1(); } else { CP_WAIT0(); }
        __syncthreads();

        const uint32_t st = sbase + (uint32_t)(c & 1) * STAGE_BYTES;
        const uint32_t aH = st;
        const uint32_t aL = st + TILE_BYTES;
        const uint32_t bH = st + 2 * TILE_BYTES;

        #pragma unroll
        for (int ks = 0; ks < 2; ++ks) {
            const int acol = ks * 16 + acoff;
            const int bcol = ks * 16 + bcoff;
            uint32_t ah[4][4], al[4][4];
            #pragma unroll
            for (int mf = 0; mf < 4; ++mf) {
                uint32_t off = (uint32_t)((arow + mf * 16) * TPAD + acol) * 2;
                LDSM_X4(ah[mf][0], ah[mf][1], ah[mf][2], ah[mf][3], aH + off);
                LDSM_X4(al[mf][0], al[mf][1], al[mf][2], al[mf][3], aL + off);
            }
            #pragma unroll
            for (int nf2 = 0; nf2 < 2; ++nf2) {
                uint32_t off = (uint32_t)((brow0 + nf2 * 16) * TPAD + bcol) * 2;
                uint32_t bh[2][2];
                LDSM_X4(bh[0][0], bh[0][1], bh[1][0], bh[1][1], bH + off);
                #pragma unroll
                for (int mf = 0; mf < 4; ++mf)
                    #pragma unroll
                    for (int q = 0; q < 2; ++q)
                        MMA_F16(acc[mf][2 * nf2 + q], ah[mf][0], ah[mf][1], ah[mf][2], ah[mf][3],
                                bh[q][0], bh[q][1]);
                #pragma unroll
                for (int mf = 0; mf < 4; ++mf)
                    #pragma unroll
                    for (int q = 0; q < 2; ++q)
                        MMA_F16(acc[mf][2 * nf2 + q], al[mf][0], al[mf][1], al[mf][2], al[mf][3],
                                bh[q][0], bh[q][1]);
            }
        }
        __syncthreads();
        if (c + 2 < NCHUNK) issue(c & 1, (c + 2) * GBK);
    }

    #pragma unroll
    for (int mf = 0; mf < 4; ++mf) {
        const int m = bm + wm + mf * 16 + (lane >> 2);
        #pragma unroll
        for (int nf = 0; nf < 4; ++nf) {
            const int n = bn + wn + nf * 8 + (lane & 3) * 2;
            const float2 bv = *(const float2*)&bias[n];
            float2 v0 = { acc[mf][nf][0] + bv.x, acc[mf][nf][1] + bv.y };
            float2 v1 = { acc[mf][nf][2] + bv.x, acc[mf][nf][3] + bv.y };
            *(float2*)&C[(size_t)m * N + n]       = v0;
            *(float2*)&C[(size_t)(m + 8) * N + n] = v1;
        }
    }
}

// ================= MMA flash attention (strided mask) =================
// smem layout (bytes), row stride 72 bf16 = 144 B
#define TROWB 144
#define AT_KH 0
#define AT_KL 36864
#define AT_VH 73728
#define AT_VL 110592
#define AT_QH 147456
#define AT_QL 165888
#define ATTN_SMEM 184320

__global__ __launch_bounds__(256, 1)
void attn_mma_kernel(const float* __restrict__ qkv,
                     __half* __restrict__ oh, __half* __restrict__ ol)
{
    extern __shared__ char smraw[];
    const uint32_t sb = smem_u32(smraw);
    const int tid = threadIdx.x;
    const int lane = tid & 31;
    const int w = tid >> 5;

    const int bh = blockIdx.y;
    const int b = bh / NHEAD;
    const int h = bh % NHEAD;
    const int qb = blockIdx.x;
    const int q0 = qb * QB;
    const int n_str = 16 * (qb + 1);
    const int n_pad = (n_str + 63) & ~63;

    // ---- stage K, V (strided rows) as bf16 hi/lo ----
    for (int task = tid; task < n_str * 16; task += 256) {
        const int t   = task >> 4;
        const int sel = (task >> 3) & 1;
        const int d8  = (task & 7) << 3;
        const size_t src = (size_t)(b * SEQ + t * STRIDE_) * (3 * DMODEL)
                         + (size_t)(1 + sel) * DMODEL + h * HDIM + d8;
        const float4 v0 = *(const float4*)&qkv[src];
        const float4 v1 = *(const float4*)&qkv[src + 4];
        uint32_t hp0, lp0, hp1, lp1, hp2, lp2, hp3, lp3;
        hilo2(v0.x, v0.y, hp0, lp0);
        hilo2(v0.z, v0.w, hp1, lp1);
        hilo2(v1.x, v1.y, hp2, lp2);
        hilo2(v1.z, v1.w, hp3, lp3);
        const int dst = t * TROWB + d8 * 2;
        *(uint4*)(smraw + (sel ? AT_VH : AT_KH) + dst) = make_uint4(hp0, hp1, hp2, hp3);
        *(uint4*)(smraw + (sel ? AT_VL : AT_KL) + dst) = make_uint4(lp0, lp1, lp2, lp3);
    }
    for (int task = tid; task < (n_pad - n_str) * 8; task += 256) {
        const int t  = n_str + (task >> 3);
        const int d8 = (task & 7) << 3;
        const int dst = t * TROWB + d8 * 2;
        const uint4 z = make_uint4(0, 0, 0, 0);
        *(uint4*)(smraw + AT_KH + dst) = z;
        *(uint4*)(smraw + AT_KL + dst) = z;
        *(uint4*)(smraw + AT_VH + dst) = z;
        *(uint4*)(smraw + AT_VL + dst) = z;
    }
    for (int task = tid; task < 128 * 8; task += 256) {
        const int r  = task >> 3;
        const int d8 = (task & 7) << 3;
        const size_t src = (size_t)(b * SEQ + q0 + r) * (3 * DMODEL) + h * HDIM + d8;
        float4 v0 = *(const float4*)&qkv[src];
        float4 v1 = *(const float4*)&qkv[src + 4];
        v0.x *= 0.125f; v0.y *= 0.125f; v0.z *= 0.125f; v0.w *= 0.125f;
        v1.x *= 0.125f; v1.y *= 0.125f; v1.z *= 0.125f; v1.w *= 0.125f;
        uint32_t hp0, lp0, hp1, lp1, hp2, lp2, hp3, lp3;
        hilo2(v0.x, v0.y, hp0, lp0);
        hilo2(v0.z, v0.w, hp1, lp1);
        hilo2(v1.x, v1.y, hp2, lp2);
        hilo2(v1.z, v1.w, hp3, lp3);
        const int dst = r * TROWB + d8 * 2;
        *(uint4*)(smraw + AT_QH + dst) = make_uint4(hp0, hp1, hp2, hp3);
        *(uint4*)(smraw + AT_QL + dst) = make_uint4(lp0, lp1, lp2, lp3);
    }
    __syncthreads();

    const int g = lane >> 3;
    const int tig = lane & 3;
    const int arow = 16 * w + (g & 1) * 8 + (lane & 7);
    const int acoff = (g >> 1) * 8;
    uint32_t qh[4][4], ql[4][4];
    #pragma unroll
    for (int kd = 0; kd < 4; ++kd) {
        const uint32_t off = (uint32_t)(arow * TROWB + (kd * 16 + acoff) * 2);
        LDSM_X4(qh[kd][0], qh[kd][1], qh[kd][2], qh[kd][3], sb + AT_QH + off);
        LDSM_X4(ql[kd][0], ql[kd][1], ql[kd][2], ql[kd][3], sb + AT_QL + off);
    }

    float ofr[8][4];
    #pragma unroll
    for (int i = 0; i < 8; i++) { ofr[i][0]=0.f; ofr[i][1]=0.f; ofr[i][2]=0.f; ofr[i][3]=0.f; }
    float m0 = -1e30f, m1 = -1e30f, l0 = 0.f, l1 = 0.f;

    const int row0q = q0 + 16 * w + (lane >> 2);
    const int nt0 = (row0q >> 3) + 1;
    const int nt1 = ((row0q + 8) >> 3) + 1;
    const int nchunks = (16 * qb + 2 * w + 2 + 63) >> 6;

    const int skrow = (g >> 1) * 8 + (lane & 7);
    const int sdcol = (g & 1) * 8;
    const int vkrow = (g & 1) * 8 + (lane & 7);
    const int vdcol = (g >> 1) * 8;

    for (int ch = 0; ch < nchunks; ++ch) {
        const int c0 = ch * 64;
        float sfr[8][4];
        #pragma unroll
        for (int i = 0; i < 8; i++) { sfr[i][0]=0.f; sfr[i][1]=0.f; sfr[i][2]=0.f; sfr[i][3]=0.f; }

        #pragma unroll
        for (int kd = 0; kd < 4; ++kd) {
            #pragma unroll
            for (int kg = 0; kg < 4; ++kg) {
                const uint32_t addr = sb + AT_KH +
                    (uint32_t)((c0 + kg * 16 + skrow) * TROWB + (kd * 16 + sdcol) * 2);
                uint32_t kh[4], kl[4];
                LDSM_X4(kh[0], kh[1], kh[2], kh[3], addr);
                LDSM_X4(kl[0], kl[1], kl[2], kl[3], addr + (AT_KL - AT_KH));
                MMA_BF16(sfr[2*kg],   qh[kd][0], qh[kd][1], qh[kd][2], qh[kd][3], kh[0], kh[1]);
                MMA_BF16(sfr[2*kg+1], qh[kd][0], qh[kd][1], qh[kd][2], qh[kd][3], kh[2], kh[3]);
                MMA_BF16(sfr[2*kg],   ql[kd][0], ql[kd][1], ql[kd][2], ql[kd][3], kh[0], kh[1]);
                MMA_BF16(sfr[2*kg+1], ql[kd][0], ql[kd][1], ql[kd][2], ql[kd][3], kh[2], kh[3]);
                MMA_BF16(sfr[2*kg],   qh[kd][0], qh[kd][1], qh[kd][2], qh[kd][3], kl[0], kl[1]);
                MMA_BF16(sfr[2*kg+1], qh[kd][0], qh[kd][1], qh[kd][2], qh[kd][3], kl[2], kl[3]);
            }
        }

        float mx0 = -1e30f, mx1 = -1e30f;
        #pragma unroll
        for (int nf = 0; nf < 8; ++nf) {
            const int tb = c0 + nf * 8 + 2 * tig;
            if (tb >= nt0)     sfr[nf][0] = -1e30f;
            if (tb + 1 >= nt0) sfr[nf][1] = -1e30f;
            if (tb >= nt1)     sfr[nf][2] = -1e30f;
            if (tb + 1 >= nt1) sfr[nf][3] = -1e30f;
            mx0 = fmaxf(mx0, fmaxf(sfr[nf][0], sfr[nf][1]));
            mx1 = fmaxf(mx1, fmaxf(sfr[nf][2], sfr[nf][3]));
        }
        mx0 = fmaxf(mx0, __shfl_xor_sync(0xFFFFFFFFu, mx0, 1));
        mx0 = fmaxf(mx0, __shfl_xor_sync(0xFFFFFFFFu, mx0, 2));
        mx1 = fmaxf(mx1, __shfl_xor_sync(0xFFFFFFFFu, mx1, 1));
        mx1 = fmaxf(mx1, __shfl_xor_sync(0xFFFFFFFFu, mx1, 2));
        const float mn0 = fmaxf(m0, mx0);
        const float mn1 = fmaxf(m1, mx1);
        const float al0 = __expf(m0 - mn0);
        const float al1 = __expf(m1 - mn1);
        float s0 = 0.f, s1 = 0.f;
        #pragma unroll
        for (int nf = 0; nf < 8; ++nf) {
            sfr[nf][0] = __expf(sfr[nf][0] - mn0);
            sfr[nf][1] = __expf(sfr[nf][1] - mn0);
            sfr[nf][2] = __expf(sfr[nf][2] - mn1);
            sfr[nf][3] = __expf(sfr[nf][3] - mn1);
            s0 += sfr[nf][0] + sfr[nf][1];
            s1 += sfr[nf][2] + sfr[nf][3];
        }
        s0 += __shfl_xor_sync(0xFFFFFFFFu, s0, 1);
        s0 += __shfl_xor_sync(0xFFFFFFFFu, s0, 2);
        s1 += __shfl_xor_sync(0xFFFFFFFFu, s1, 1);
        s1 += __shfl_xor_sync(0xFFFFFFFFu, s1, 2);
        l0 = l0 * al0 + s0;
        l1 = l1 * al1 + s1;
        m0 = mn0; m1 = mn1;
        #pragma unroll
        for (int nf = 0; nf < 8; ++nf) {
            ofr[nf][0] *= al0; ofr[nf][1] *= al0;
            ofr[nf][2] *= al1; ofr[nf][3] *= al1;
        }

        uint32_t ph[4][4], pl[4][4];
        #pragma unroll
        for (int kk = 0; kk < 4; ++kk) {
            hilo2(sfr[2*kk][0],   sfr[2*kk][1],   ph[kk][0], pl[kk][0]);
            hilo2(sfr[2*kk][2],   sfr[2*kk][3],   ph[kk][1], pl[kk][1]);
            hilo2(sfr[2*kk+1][0], sfr[2*kk+1][1], ph[kk][2], pl[kk][2]);
            hilo2(sfr[2*kk+1][2], sfr[2*kk+1][3], ph[kk][3], pl[kk][3]);
        }

        #pragma unroll
        for (int kk = 0; kk < 4; ++kk) {
            #pragma unroll
            for (int dd = 0; dd < 4; ++dd) {
                const uint32_t addr = sb + AT_VH +
                    (uint32_t)((c0 + kk * 16 + vkrow) * TROWB + (dd * 16 + vdcol) * 2);
                uint32_t vh[4], vl[4];
                LDSM_X4_T(vh[0], vh[1], vh[2], vh[3], addr);
                LDSM_X4_T(vl[0], vl[1], vl[2], vl[3], addr + (AT_VL - AT_VH));
                MMA_BF16(ofr[2*dd],   ph[kk][0], ph[kk][1], ph[kk][2], ph[kk][3], vh[0], vh[1]);
                MMA_BF16(ofr[2*dd+1], ph[kk][0], ph[kk][1], ph[kk][2], ph[kk][3], vh[2], vh[3]);
                MMA_BF16(ofr[2*dd],   pl[kk][0], pl[kk][1], pl[kk][2], pl[kk][3], vh[0], vh[1]);
                MMA_BF16(ofr[2*dd+1], pl[kk][0], pl[kk][1], pl[kk][2], pl[kk][3], vh[2], vh[3]);
                MMA_BF16(ofr[2*dd],   ph[kk][0], ph[kk][1], ph[kk][2], ph[kk][3], vl[0], vl[1]);
                MMA_BF16(ofr[2*dd+1], ph[kk][0], ph[kk][1], ph[kk][2], ph[kk][3], vl[2], vl[3]);
            }
        }
    }

    // ---- epilogue ----
    __syncthreads();
    float* sO = (float*)smraw;
    float* sM = (float*)(smraw + AT_VH);
    float* sL = sM + 128;
    {
        const int r0 = 16 * w + (lane >> 2);
        #pragma unroll
        for (int nf = 0; nf < 8; ++nf) {
            const int col = nf * 8 + 2 * tig;
            sO[r0 * 64 + col]       = ofr[nf][0];
            sO[r0 * 64 + col + 1]   = ofr[nf][1];
            sO[(r0+8) * 64 + col]   = ofr[nf][2];
            sO[(r0+8) * 64 + col+1] = ofr[nf][3];
        }
        if (tig == 0) {
            sM[r0] = m0; sL[r0] = l0;
            sM[r0 + 8] = m1; sL[r0 + 8] = l1;
        }
    }
    __syncwarp();

    for (int r = 0; r < 16; ++r) {
        const int srow = 16 * w + r;
        const int i = q0 + srow;
        float m_ = sM[srow], l_ = sL[srow];
        float x0 = sO[srow * 64 + lane];
        float x1 = sO[srow * 64 + lane + 32];
        const size_t qbase = (size_t)(b * SEQ + i) * (3 * DMODEL) + h * HDIM;
        const float q0v = qkv[qbase + lane];
        const float q1v = qkv[qbase + lane + 32];
        #pragma unroll
        for (int e = 0; e < 2; ++e) {
            const int j = i - e;
            if (j >= 0 && (j & 7) != 0) {
                const size_t kb = (size_t)(b * SEQ + j) * (3 * DMODEL) + h * HDIM + DMODEL;
                float part = q0v * qkv[kb + lane] + q1v * qkv[kb + lane + 32];
                #pragma unroll
                for (int off = 16; off; off >>= 1)
                    part += __shfl_xor_sync(0xFFFFFFFFu, part, off);
                const float s = part * 0.125f;
                const float mn = fmaxf(m_, s);
                const float al = __expf(m_ - mn);
                const float p = __expf(s - mn);
                x0 = x0 * al + p * qkv[kb + DMODEL + lane];
                x1 = x1 * al + p * qkv[kb + DMODEL + lane + 32];
                l_ = l_ * al + p;
                m_ = mn;
            }
        }
        const float inv = 1.f / l_;
        const float fa0 = x0 * inv, fa1 = x1 * inv;
        const size_t ob = (size_t)(b * SEQ + i) * DMODEL + h * HDIM;
        const __half h0 = __float2half_rn(fa0);
        const __half h1 = __float2half_rn(fa1);
        oh[ob + lane]      = h0;
        oh[ob + lane + 32] = h1;
        ol[ob + lane]      = __float2half_rn(fa0 - __half2float(h0));
        ol[ob + lane + 32] = __float2half_rn(fa1 - __half2float(h1));
    }
}

// ---------------- launcher ----------------
extern "C" void kernel_launch(void* const* d_in, const int* in_sizes, int n_in,
                              void* d_out, int out_size)
{
    const float* x      = (const float*)d_in[0];
    const float* qkv_w  = (const float*)d_in[1];
    const float* qkv_b  = (const float*)d_in[2];
    const float* out_w  = (const float*)d_in[3];
    const float* out_b  = (const float*)d_in[4];
    float* out = (float*)d_out;

    float* qkv; cudaGetSymbolAddress((void**)&qkv, g_qkv);
    __half *ah, *al, *bh, *owh, *xh, *xl;
    cudaGetSymbolAddress((void**)&ah,  g_ah);
    cudaGetSymbolAddress((void**)&al,  g_al);
    cudaGetSymbolAddress((void**)&bh,  g_bh);
    cudaGetSymbolAddress((void**)&owh, g_owh);
    cudaGetSymbolAddress((void**)&xh,  g_xh);
    cudaGetSymbolAddress((void**)&xl,  g_xl);

    cudaFuncSetAttribute(gemm_mma_kernel, cudaFuncAttributeMaxDynamicSharedMemorySize, GEMM_SMEM);
    cudaFuncSetAttribute(attn_mma_kernel, cudaFuncAttributeMaxDynamicSharedMemorySize, ATTN_SMEM);

    // fp16 splits of x (hi/lo) and weights (single)
    {
        int n4 = M_TOTAL * K_DIM / 4;
        conv_hilo_kernel<<<(n4 + 255) / 256, 256>>>(x, xh, xl, n4);
        n4 = N_QKV * K_DIM / 4;
        conv_h_kernel<<<(n4 + 255) / 256, 256>>>(qkv_w, bh, n4);
        n4 = DMODEL * K_DIM / 4;
        conv_h_kernel<<<(n4 + 255) / 256, 256>>>(out_w, owh, n4);
    }

    // 1) QKV projection (fp16 2-product)
    gemm_mma_kernel<<<dim3(N_QKV / 128, M_TOTAL / 128), 256, GEMM_SMEM>>>(
        xh, xl, bh, qkv_b, qkv, N_QKV);

    // 2) strided attention on tensor cores (bf16 3-product internals, fp16 hi/lo out)
    attn_mma_kernel<<<dim3(SEQ / QB, BATCH * NHEAD), 256, ATTN_SMEM>>>(qkv, ah, al);

    // 3) output projection (fp16 2-product)
    gemm_mma_kernel<<<dim3(DMODEL / 128, M_TOTAL / 128), 256, GEMM_SMEM>>>(
        ah, al, owh, out_b, out, DMODEL);
}

// round 10
// speedup vs baseline: 2.1515x; 1.3478x over previous
#include <cuda_runtime.h>
#include <cuda_bf16.h>
#include <cuda_fp16.h>
#include <cstdint>

// ---------------- problem constants ----------------
#define BATCH 2
#define SEQ   2048
#define DMODEL 768
#define NHEAD 12
#define HDIM  64
#define STRIDE_ 8
#define QB    128

#define M_TOTAL (BATCH*SEQ)   // 4096
#define K_DIM   DMODEL        // 768
#define N_QKV   (3*DMODEL)    // 2304

// ---------------- device scratch ----------------
__device__ float g_qkv[M_TOTAL * N_QKV];
__device__ __half g_ah[M_TOTAL * K_DIM];    // attention out (fp16)
__device__ __half g_bh[N_QKV * K_DIM];      // qkv_w fp16
__device__ __half g_owh[DMODEL * K_DIM];    // out_w fp16
__device__ __half g_xh[M_TOTAL * K_DIM];    // x fp16

// ---------------- PTX helpers (portable: sm_80+) ----------------
__device__ __forceinline__ uint32_t smem_u32(const void* p) {
    uint32_t a;
    asm("{ .reg .u64 t; cvta.to.shared.u64 t, %1; cvt.u32.u64 %0, t; }" : "=r"(a) : "l"(p));
    return a;
}

#define CP_ASYNC16(dst, src) \
    asm volatile("cp.async.cg.shared.global [%0], [%1], 16;" :: "r"(dst), "l"(src))
#define CP_COMMIT() asm volatile("cp.async.commit_group;" ::: "memory")
#define CP_WAIT1() asm volatile("cp.async.wait_group 1;" ::: "memory")
#define CP_WAIT0() asm volatile("cp.async.wait_group 0;" ::: "memory")

#define LDSM_X4(r0, r1, r2, r3, addr) \
    asm volatile("ldmatrix.sync.aligned.m8n8.x4.shared.b16 {%0,%1,%2,%3}, [%4];" \
        : "=r"(r0), "=r"(r1), "=r"(r2), "=r"(r3) : "r"(addr))

#define LDSM_X4_T(r0, r1, r2, r3, addr) \
    asm volatile("ldmatrix.sync.aligned.m8n8.x4.trans.shared.b16 {%0,%1,%2,%3}, [%4];" \
        : "=r"(r0), "=r"(r1), "=r"(r2), "=r"(r3) : "r"(addr))

#define MMA_BF16(c, a0, a1, a2, a3, b0, b1) \
    asm("mma.sync.aligned.m16n8k16.row.col.f32.bf16.bf16.f32 " \
        "{%0,%1,%2,%3}, {%4,%5,%6,%7}, {%8,%9}, {%0,%1,%2,%3};" \
        : "+f"((c)[0]), "+f"((c)[1]), "+f"((c)[2]), "+f"((c)[3]) \
        : "r"(a0), "r"(a1), "r"(a2), "r"(a3), "r"(b0), "r"(b1))

#define MMA_F16(c, a0, a1, a2, a3, b0, b1) \
    asm("mma.sync.aligned.m16n8k16.row.col.f32.f16.f16.f32 " \
        "{%0,%1,%2,%3}, {%4,%5,%6,%7}, {%8,%9}, {%0,%1,%2,%3};" \
        : "+f"((c)[0]), "+f"((c)[1]), "+f"((c)[2]), "+f"((c)[3]) \
        : "r"(a0), "r"(a1), "r"(a2), "r"(a3), "r"(b0), "r"(b1))

// bf16 hi/lo pack (attention internals)
__device__ __forceinline__ uint32_t pack_bf16x2(float a, float b) {
    uint32_t r;
    asm("cvt.rn.bf16x2.f32 %0, %1, %2;" : "=r"(r) : "f"(b), "f"(a));
    return r;
}
__device__ __forceinline__ void hilo2(float a, float b, uint32_t& hp, uint32_t& lp) {
    hp = pack_bf16x2(a, b);
    float fa = __uint_as_float(hp << 16);
    float fb = __uint_as_float(hp & 0xffff0000u);
    lp = pack_bf16x2(a - fa, b - fb);
}

// ---------------- fp32 -> fp16 convert ----------------
__global__ __launch_bounds__(256)
void conv_h_kernel(const float* __restrict__ in, __half* __restrict__ hi, int n4)
{
    int i = blockIdx.x * 256 + threadIdx.x;
    if (i >= n4) return;
    float4 v = ((const float4*)in)[i];
    __half2 a = __floats2half2_rn(v.x, v.y);
    __half2 b = __floats2half2_rn(v.z, v.w);
    ((uint2*)hi)[i] = make_uint2(*(uint32_t*)&a, *(uint32_t*)&b);
}

// ------- fp16 single-product GEMM: C = A[M,768] * (B[N,768])^T + bias -------
#define GBK 32
#define NCHUNK (K_DIM / GBK)          // 24
#define TPAD 40
#define TILE_BYTES (128 * TPAD * 2)   // 10240
#define STAGE_BYTES (2 * TILE_BYTES)  // 20480 (A, B)
#define GEMM_SMEM (2 * STAGE_BYTES)   // 40960 -> 2 CTAs/SM

__global__ __launch_bounds__(256, 2)
void gemm_mma_kernel(const __half* __restrict__ A, const __half* __restrict__ B,
                     const float* __restrict__ bias, float* __restrict__ C, int N)
{
    extern __shared__ char dsm[];
    const uint32_t sbase = smem_u32(dsm);
    const int tid = threadIdx.x;
    const int lane = tid & 31;
    const int wid = tid >> 5;
    const int wm = (wid & 1) * 64;
    const int wn = (wid >> 1) * 32;
    const int bm = blockIdx.y * 128;
    const int bn = blockIdx.x * 128;

    const __half* gp[2] = { A, B };

    float acc[4][4][4];
    #pragma unroll
    for (int i = 0; i < 4; i++)
        #pragma unroll
        for (int j = 0; j < 4; j++)
            #pragma unroll
            for (int r = 0; r < 4; r++) acc[i][j][r] = 0.f;

    auto issue = [&](int stage, int kc) {
        const uint32_t st = sbase + (uint32_t)stage * STAGE_BYTES;
        #pragma unroll
        for (int t = 0; t < 4; ++t) {
            int task = tid + t * 256;          // 0..1023
            int tile = task >> 9;              // 0..1
            int idx  = task & 511;
            int r = idx >> 2, q = idx & 3;
            int row = (tile == 0 ? bm : bn) + r;
            uint32_t dst = st + (uint32_t)tile * TILE_BYTES + (uint32_t)(r * TPAD + q * 8) * 2;
            CP_ASYNC16(dst, gp[tile] + (size_t)row * K_DIM + kc + q * 8);
        }
        CP_COMMIT();
    };

    issue(0, 0);
    issue(1, GBK);

    const int g = lane >> 3;
    const int arow = wm + (g & 1) * 8 + (lane & 7);
    const int acoff = (g >> 1) * 8;
    const int brow0 = wn + (g >> 1) * 8 + (lane & 7);
    const int bcoff = (g & 1) * 8;

    for (int c = 0; c < NCHUNK; ++c) {
        if (c + 1 < NCHUNK) { CP_WAIT1(); } else { CP_WAIT0(); }
        __syncthreads();

        const uint32_t st = sbase + (uint32_t)(c & 1) * STAGE_BYTES;
        const uint32_t aT = st;
        const uint32_t bT = st + TILE_BYTES;

        #pragma unroll
        for (int ks = 0; ks < 2; ++ks) {
            const int acol = ks * 16 + acoff;
            const int bcol = ks * 16 + bcoff;
            uint32_t a[4][4];
            #pragma unroll
            for (int mf = 0; mf < 4; ++mf) {
                uint32_t off = (uint32_t)((arow + mf * 16) * TPAD + acol) * 2;
                LDSM_X4(a[mf][0], a[mf][1], a[mf][2], a[mf][3], aT + off);
            }
            #pragma unroll
            for (int nf2 = 0; nf2 < 2; ++nf2) {
                uint32_t off = (uint32_t)((brow0 + nf2 * 16) * TPAD + bcol) * 2;
                uint32_t bf[2][2];
                LDSM_X4(bf[0][0], bf[0][1], bf[1][0], bf[1][1], bT + off);
                #pragma unroll
                for (int mf = 0; mf < 4; ++mf)
                    #pragma unroll
                    for (int q = 0; q < 2; ++q)
                        MMA_F16(acc[mf][2 * nf2 + q], a[mf][0], a[mf][1], a[mf][2], a[mf][3],
                                bf[q][0], bf[q][1]);
            }
        }
        __syncthreads();
        if (c + 2 < NCHUNK) issue(c & 1, (c + 2) * GBK);
    }

    #pragma unroll
    for (int mf = 0; mf < 4; ++mf) {
        const int m = bm + wm + mf * 16 + (lane >> 2);
        #pragma unroll
        for (int nf = 0; nf < 4; ++nf) {
            const int n = bn + wn + nf * 8 + (lane & 3) * 2;
            const float2 bv = *(const float2*)&bias[n];
            float2 v0 = { acc[mf][nf][0] + bv.x, acc[mf][nf][1] + bv.y };
            float2 v1 = { acc[mf][nf][2] + bv.x, acc[mf][nf][3] + bv.y };
            *(float2*)&C[(size_t)m * N + n]       = v0;
            *(float2*)&C[(size_t)(m + 8) * N + n] = v1;
        }
    }
}

// ================= MMA flash attention (strided mask, bf16 3-product) ========
#define TROWB 144
#define AT_KH 0
#define AT_KL 36864
#define AT_VH 73728
#define AT_VL 110592
#define AT_QH 147456
#define AT_QL 165888
#define ATTN_SMEM 184320

__global__ __launch_bounds__(256, 1)
void attn_mma_kernel(const float* __restrict__ qkv, __half* __restrict__ oh)
{
    extern __shared__ char smraw[];
    const uint32_t sb = smem_u32(smraw);
    const int tid = threadIdx.x;
    const int lane = tid & 31;
    const int w = tid >> 5;

    const int bh = blockIdx.y;
    const int b = bh / NHEAD;
    const int h = bh % NHEAD;
    const int qb = blockIdx.x;
    const int q0 = qb * QB;
    const int n_str = 16 * (qb + 1);
    const int n_pad = (n_str + 63) & ~63;

    // ---- stage K, V (strided rows) as bf16 hi/lo ----
    for (int task = tid; task < n_str * 16; task += 256) {
        const int t   = task >> 4;
        const int sel = (task >> 3) & 1;
        const int d8  = (task & 7) << 3;
        const size_t src = (size_t)(b * SEQ + t * STRIDE_) * (3 * DMODEL)
                         + (size_t)(1 + sel) * DMODEL + h * HDIM + d8;
        const float4 v0 = *(const float4*)&qkv[src];
        const float4 v1 = *(const float4*)&qkv[src + 4];
        uint32_t hp0, lp0, hp1, lp1, hp2, lp2, hp3, lp3;
        hilo2(v0.x, v0.y, hp0, lp0);
        hilo2(v0.z, v0.w, hp1, lp1);
        hilo2(v1.x, v1.y, hp2, lp2);
        hilo2(v1.z, v1.w, hp3, lp3);
        const int dst = t * TROWB + d8 * 2;
        *(uint4*)(smraw + (sel ? AT_VH : AT_KH) + dst) = make_uint4(hp0, hp1, hp2, hp3);
        *(uint4*)(smraw + (sel ? AT_VL : AT_KL) + dst) = make_uint4(lp0, lp1, lp2, lp3);
    }
    for (int task = tid; task < (n_pad - n_str) * 8; task += 256) {
        const int t  = n_str + (task >> 3);
        const int d8 = (task & 7) << 3;
        const int dst = t * TROWB + d8 * 2;
        const uint4 z = make_uint4(0, 0, 0, 0);
        *(uint4*)(smraw + AT_KH + dst) = z;
        *(uint4*)(smraw + AT_KL + dst) = z;
        *(uint4*)(smraw + AT_VH + dst) = z;
        *(uint4*)(smraw + AT_VL + dst) = z;
    }
    for (int task = tid; task < 128 * 8; task += 256) {
        const int r  = task >> 3;
        const int d8 = (task & 7) << 3;
        const size_t src = (size_t)(b * SEQ + q0 + r) * (3 * DMODEL) + h * HDIM + d8;
        float4 v0 = *(const float4*)&qkv[src];
        float4 v1 = *(const float4*)&qkv[src + 4];
        v0.x *= 0.125f; v0.y *= 0.125f; v0.z *= 0.125f; v0.w *= 0.125f;
        v1.x *= 0.125f; v1.y *= 0.125f; v1.z *= 0.125f; v1.w *= 0.125f;
        uint32_t hp0, lp0, hp1, lp1, hp2, lp2, hp3, lp3;
        hilo2(v0.x, v0.y, hp0, lp0);
        hilo2(v0.z, v0.w, hp1, lp1);
        hilo2(v1.x, v1.y, hp2, lp2);
        hilo2(v1.z, v1.w, hp3, lp3);
        const int dst = r * TROWB + d8 * 2;
        *(uint4*)(smraw + AT_QH + dst) = make_uint4(hp0, hp1, hp2, hp3);
        *(uint4*)(smraw + AT_QL + dst) = make_uint4(lp0, lp1, lp2, lp3);
    }
    __syncthreads();

    const int g = lane >> 3;
    const int tig = lane & 3;
    const int arow = 16 * w + (g & 1) * 8 + (lane & 7);
    const int acoff = (g >> 1) * 8;
    uint32_t qh[4][4], ql[4][4];
    #pragma unroll
    for (int kd = 0; kd < 4; ++kd) {
        const uint32_t off = (uint32_t)(arow * TROWB + (kd * 16 + acoff) * 2);
        LDSM_X4(qh[kd][0], qh[kd][1], qh[kd][2], qh[kd][3], sb + AT_QH + off);
        LDSM_X4(ql[kd][0], ql[kd][1], ql[kd][2], ql[kd][3], sb + AT_QL + off);
    }

    float ofr[8][4];
    #pragma unroll
    for (int i = 0; i < 8; i++) { ofr[i][0]=0.f; ofr[i][1]=0.f; ofr[i][2]=0.f; ofr[i][3]=0.f; }
    float m0 = -1e30f, m1 = -1e30f, l0 = 0.f, l1 = 0.f;

    const int row0q = q0 + 16 * w + (lane >> 2);
    const int nt0 = (row0q >> 3) + 1;
    const int nt1 = ((row0q + 8) >> 3) + 1;
    const int nchunks = (16 * qb + 2 * w + 2 + 63) >> 6;

    const int skrow = (g >> 1) * 8 + (lane & 7);
    const int sdcol = (g & 1) * 8;
    const int vkrow = (g & 1) * 8 + (lane & 7);
    const int vdcol = (g >> 1) * 8;

    for (int ch = 0; ch < nchunks; ++ch) {
        const int c0 = ch * 64;
        float sfr[8][4];
        #pragma unroll
        for (int i = 0; i < 8; i++) { sfr[i][0]=0.f; sfr[i][1]=0.f; sfr[i][2]=0.f; sfr[i][3]=0.f; }

        #pragma unroll
        for (int kd = 0; kd < 4; ++kd) {
            #pragma unroll
            for (int kg = 0; kg < 4; ++kg) {
                const uint32_t addr = sb + AT_KH +
                    (uint32_t)((c0 + kg * 16 + skrow) * TROWB + (kd * 16 + sdcol) * 2);
                uint32_t kh[4], kl[4];
                LDSM_X4(kh[0], kh[1], kh[2], kh[3], addr);
                LDSM_X4(kl[0], kl[1], kl[2], kl[3], addr + (AT_KL - AT_KH));
                MMA_BF16(sfr[2*kg],   qh[kd][0], qh[kd][1], qh[kd][2], qh[kd][3], kh[0], kh[1]);
                MMA_BF16(sfr[2*kg+1], qh[kd][0], qh[kd][1], qh[kd][2], qh[kd][3], kh[2], kh[3]);
                MMA_BF16(sfr[2*kg],   ql[kd][0], ql[kd][1], ql[kd][2], ql[kd][3], kh[0], kh[1]);
                MMA_BF16(sfr[2*kg+1], ql[kd][0], ql[kd][1], ql[kd][2], ql[kd][3], kh[2], kh[3]);
                MMA_BF16(sfr[2*kg],   qh[kd][0], qh[kd][1], qh[kd][2], qh[kd][3], kl[0], kl[1]);
                MMA_BF16(sfr[2*kg+1], qh[kd][0], qh[kd][1], qh[kd][2], qh[kd][3], kl[2], kl[3]);
            }
        }

        float mx0 = -1e30f, mx1 = -1e30f;
        #pragma unroll
        for (int nf = 0; nf < 8; ++nf) {
            const int tb = c0 + nf * 8 + 2 * tig;
            if (tb >= nt0)     sfr[nf][0] = -1e30f;
            if (tb + 1 >= nt0) sfr[nf][1] = -1e30f;
            if (tb >= nt1)     sfr[nf][2] = -1e30f;
            if (tb + 1 >= nt1) sfr[nf][3] = -1e30f;
            mx0 = fmaxf(mx0, fmaxf(sfr[nf][0], sfr[nf][1]));
            mx1 = fmaxf(mx1, fmaxf(sfr[nf][2], sfr[nf][3]));
        }
        mx0 = fmaxf(mx0, __shfl_xor_sync(0xFFFFFFFFu, mx0, 1));
        mx0 = fmaxf(mx0, __shfl_xor_sync(0xFFFFFFFFu, mx0, 2));
        mx1 = fmaxf(mx1, __shfl_xor_sync(0xFFFFFFFFu, mx1, 1));
        mx1 = fmaxf(mx1, __shfl_xor_sync(0xFFFFFFFFu, mx1, 2));
        const float mn0 = fmaxf(m0, mx0);
        const float mn1 = fmaxf(m1, mx1);
        const float al0 = __expf(m0 - mn0);
        const float al1 = __expf(m1 - mn1);
        float s0 = 0.f, s1 = 0.f;
        #pragma unroll
        for (int nf = 0; nf < 8; ++nf) {
            sfr[nf][0] = __expf(sfr[nf][0] - mn0);
            sfr[nf][1] = __expf(sfr[nf][1] - mn0);
            sfr[nf][2] = __expf(sfr[nf][2] - mn1);
            sfr[nf][3] = __expf(sfr[nf][3] - mn1);
            s0 += sfr[nf][0] + sfr[nf][1];
            s1 += sfr[nf][2] + sfr[nf][3];
        }
        s0 += __shfl_xor_sync(0xFFFFFFFFu, s0, 1);
        s0 += __shfl_xor_sync(0xFFFFFFFFu, s0, 2);
        s1 += __shfl_xor_sync(0xFFFFFFFFu, s1, 1);
        s1 += __shfl_xor_sync(0xFFFFFFFFu, s1, 2);
        l0 = l0 * al0 + s0;
        l1 = l1 * al1 + s1;
        m0 = mn0; m1 = mn1;
        #pragma unroll
        for (int nf = 0; nf < 8; ++nf) {
            ofr[nf][0] *= al0; ofr[nf][1] *= al0;
            ofr[nf][2] *= al1; ofr[nf][3] *= al1;
        }

        uint32_t ph[4][4], pl[4][4];
        #pragma unroll
        for (int kk = 0; kk < 4; ++kk) {
            hilo2(sfr[2*kk][0],   sfr[2*kk][1],   ph[kk][0], pl[kk][0]);
            hilo2(sfr[2*kk][2],   sfr[2*kk][3],   ph[kk][1], pl[kk][1]);
            hilo2(sfr[2*kk+1][0], sfr[2*kk+1][1], ph[kk][2], pl[kk][2]);
            hilo2(sfr[2*kk+1][2], sfr[2*kk+1][3], ph[kk][3], pl[kk][3]);
        }

        #pragma unroll
        for (int kk = 0; kk < 4; ++kk) {
            #pragma unroll
            for (int dd = 0; dd < 4; ++dd) {
                const uint32_t addr = sb + AT_VH +
                    (uint32_t)((c0 + kk * 16 + vkrow) * TROWB + (dd * 16 + vdcol) * 2);
                uint32_t vh[4], vl[4];
                LDSM_X4_T(vh[0], vh[1], vh[2], vh[3], addr);
                LDSM_X4_T(vl[0], vl[1], vl[2], vl[3], addr + (AT_VL - AT_VH));
                MMA_BF16(ofr[2*dd],   ph[kk][0], ph[kk][1], ph[kk][2], ph[kk][3], vh[0], vh[1]);
                MMA_BF16(ofr[2*dd+1], ph[kk][0], ph[kk][1], ph[kk][2], ph[kk][3], vh[2], vh[3]);
                MMA_BF16(ofr[2*dd],   pl[kk][0], pl[kk][1], pl[kk][2], pl[kk][3], vh[0], vh[1]);
                MMA_BF16(ofr[2*dd+1], pl[kk][0], pl[kk][1], pl[kk][2], pl[kk][3], vh[2], vh[3]);
                MMA_BF16(ofr[2*dd],   ph[kk][0], ph[kk][1], ph[kk][2], ph[kk][3], vl[0], vl[1]);
                MMA_BF16(ofr[2*dd+1], ph[kk][0], ph[kk][1], ph[kk][2], ph[kk][3], vl[2], vl[3]);
            }
        }
    }

    // ---- epilogue ----
    __syncthreads();
    float* sO = (float*)smraw;
    float* sM = (float*)(smraw + AT_VH);
    float* sL = sM + 128;
    {
        const int r0 = 16 * w + (lane >> 2);
        #pragma unroll
        for (int nf = 0; nf < 8; ++nf) {
            const int col = nf * 8 + 2 * tig;
            sO[r0 * 64 + col]       = ofr[nf][0];
            sO[r0 * 64 + col + 1]   = ofr[nf][1];
            sO[(r0+8) * 64 + col]   = ofr[nf][2];
            sO[(r0+8) * 64 + col+1] = ofr[nf][3];
        }
        if (tig == 0) {
            sM[r0] = m0; sL[r0] = l0;
            sM[r0 + 8] = m1; sL[r0 + 8] = l1;
        }
    }
    __syncwarp();

    for (int r = 0; r < 16; ++r) {
        const int srow = 16 * w + r;
        const int i = q0 + srow;
        float m_ = sM[srow], l_ = sL[srow];
        float x0 = sO[srow * 64 + lane];
        float x1 = sO[srow * 64 + lane + 32];
        const size_t qbase = (size_t)(b * SEQ + i) * (3 * DMODEL) + h * HDIM;
        const float q0v = qkv[qbase + lane];
        const float q1v = qkv[qbase + lane + 32];
        #pragma unroll
        for (int e = 0; e < 2; ++e) {
            const int j = i - e;
            if (j >= 0 && (j & 7) != 0) {
                const size_t kb = (size_t)(b * SEQ + j) * (3 * DMODEL) + h * HDIM + DMODEL;
                float part = q0v * qkv[kb + lane] + q1v * qkv[kb + lane + 32];
                #pragma unroll
                for (int off = 16; off; off >>= 1)
                    part += __shfl_xor_sync(0xFFFFFFFFu, part, off);
                const float s = part * 0.125f;
                const float mn = fmaxf(m_, s);
                const float al = __expf(m_ - mn);
                const float p = __expf(s - mn);
                x0 = x0 * al + p * qkv[kb + DMODEL + lane];
                x1 = x1 * al + p * qkv[kb + DMODEL + lane + 32];
                l_ = l_ * al + p;
                m_ = mn;
            }
        }
        const float inv = 1.f / l_;
        const size_t ob = (size_t)(b * SEQ + i) * DMODEL + h * HDIM;
        oh[ob + lane]      = __float2half_rn(x0 * inv);
        oh[ob + lane + 32] = __float2half_rn(x1 * inv);
    }
}

// ---------------- launcher ----------------
extern "C" void kernel_launch(void* const* d_in, const int* in_sizes, int n_in,
                              void* d_out, int out_size)
{
    const float* x      = (const float*)d_in[0];
    const float* qkv_w  = (const float*)d_in[1];
    const float* qkv_b  = (const float*)d_in[2];
    const float* out_w  = (const float*)d_in[3];
    const float* out_b  = (const float*)d_in[4];
    float* out = (float*)d_out;

    float* qkv; cudaGetSymbolAddress((void**)&qkv, g_qkv);
    __half *ah, *bh, *owh, *xh;
    cudaGetSymbolAddress((void**)&ah,  g_ah);
    cudaGetSymbolAddress((void**)&bh,  g_bh);
    cudaGetSymbolAddress((void**)&owh, g_owh);
    cudaGetSymbolAddress((void**)&xh,  g_xh);

    cudaFuncSetAttribute(gemm_mma_kernel, cudaFuncAttributeMaxDynamicSharedMemorySize, GEMM_SMEM);
    cudaFuncSetAttribute(attn_mma_kernel, cudaFuncAttributeMaxDynamicSharedMemorySize, ATTN_SMEM);

    // fp16 conversions
    {
        int n4 = M_TOTAL * K_DIM / 4;
        conv_h_kernel<<<(n4 + 255) / 256, 256>>>(x, xh, n4);
        n4 = N_QKV * K_DIM / 4;
        conv_h_kernel<<<(n4 + 255) / 256, 256>>>(qkv_w, bh, n4);
        n4 = DMODEL * K_DIM / 4;
        conv_h_kernel<<<(n4 + 255) / 256, 256>>>(out_w, owh, n4);
    }

    // 1) QKV projection (fp16 single-product)
    gemm_mma_kernel<<<dim3(N_QKV / 128, M_TOTAL / 128), 256, GEMM_SMEM>>>(
        xh, bh, qkv_b, qkv, N_QKV);

    // 2) strided attention (bf16 3-product internals, fp16 out)
    attn_mma_kernel<<<dim3(SEQ / QB, BATCH * NHEAD), 256, ATTN_SMEM>>>(qkv, ah);

    // 3) output projection (fp16 single-product)
    gemm_mma_kernel<<<dim3(DMODEL / 128, M_TOTAL / 128), 256, GEMM_SMEM>>>(
        ah, owh, out_b, out, DMODEL);
}

// round 11
// speedup vs baseline: 2.3811x; 1.1067x over previous
#include <cuda_runtime.h>
#include <cuda_bf16.h>
#include <cuda_fp16.h>
#include <cstdint>

// ---------------- problem constants ----------------
#define BATCH 2
#define SEQ   2048
#define DMODEL 768
#define NHEAD 12
#define HDIM  64
#define STRIDE_ 8
#define QB    128

#define M_TOTAL (BATCH*SEQ)   // 4096
#define K_DIM   DMODEL        // 768
#define N_QKV   (3*DMODEL)    // 2304

// ---------------- device scratch ----------------
__device__ float g_qkv[M_TOTAL * N_QKV];
__device__ __half g_ah[M_TOTAL * K_DIM];    // attention out (fp16)
__device__ __half g_bh[N_QKV * K_DIM];      // qkv_w fp16
__device__ __half g_owh[DMODEL * K_DIM];    // out_w fp16
__device__ __half g_xh[M_TOTAL * K_DIM];    // x fp16

// ---------------- PTX helpers (portable: sm_80+) ----------------
__device__ __forceinline__ uint32_t smem_u32(const void* p) {
    uint32_t a;
    asm("{ .reg .u64 t; cvta.to.shared.u64 t, %1; cvt.u32.u64 %0, t; }" : "=r"(a) : "l"(p));
    return a;
}

#define CP_ASYNC16(dst, src) \
    asm volatile("cp.async.cg.shared.global [%0], [%1], 16;" :: "r"(dst), "l"(src))
#define CP_COMMIT() asm volatile("cp.async.commit_group;" ::: "memory")
#define CP_WAIT1() asm volatile("cp.async.wait_group 1;" ::: "memory")
#define CP_WAIT0() asm volatile("cp.async.wait_group 0;" ::: "memory")

#define LDSM_X4(r0, r1, r2, r3, addr) \
    asm volatile("ldmatrix.sync.aligned.m8n8.x4.shared.b16 {%0,%1,%2,%3}, [%4];" \
        : "=r"(r0), "=r"(r1), "=r"(r2), "=r"(r3) : "r"(addr))

#define LDSM_X4_T(r0, r1, r2, r3, addr) \
    asm volatile("ldmatrix.sync.aligned.m8n8.x4.trans.shared.b16 {%0,%1,%2,%3}, [%4];" \
        : "=r"(r0), "=r"(r1), "=r"(r2), "=r"(r3) : "r"(addr))

#define MMA_F16(c, a0, a1, a2, a3, b0, b1) \
    asm("mma.sync.aligned.m16n8k16.row.col.f32.f16.f16.f32 " \
        "{%0,%1,%2,%3}, {%4,%5,%6,%7}, {%8,%9}, {%0,%1,%2,%3};" \
        : "+f"((c)[0]), "+f"((c)[1]), "+f"((c)[2]), "+f"((c)[3]) \
        : "r"(a0), "r"(a1), "r"(a2), "r"(a3), "r"(b0), "r"(b1))

// fp16 hi/lo pack
__device__ __forceinline__ void hilo2_f16(float a, float b, uint32_t& hp, uint32_t& lp) {
    __half2 h = __floats2half2_rn(a, b);
    hp = *(uint32_t*)&h;
    __half2 l = __floats2half2_rn(a - __half2float(__low2half(h)),
                                  b - __half2float(__high2half(h)));
    lp = *(uint32_t*)&l;
}
__device__ __forceinline__ uint32_t pack_f16x2(float a, float b) {
    __half2 h = __floats2half2_rn(a, b);
    return *(uint32_t*)&h;
}

// ---------------- fp32 -> fp16 convert ----------------
__global__ __launch_bounds__(256)
void conv_h_kernel(const float* __restrict__ in, __half* __restrict__ hi, int n4)
{
    int i = blockIdx.x * 256 + threadIdx.x;
    if (i >= n4) return;
    float4 v = ((const float4*)in)[i];
    __half2 a = __floats2half2_rn(v.x, v.y);
    __half2 b = __floats2half2_rn(v.z, v.w);
    ((uint2*)hi)[i] = make_uint2(*(uint32_t*)&a, *(uint32_t*)&b);
}

// ------- fp16 single-product GEMM: C = A[M,768] * (B[N,768])^T + bias -------
#define GBK 32
#define NCHUNK (K_DIM / GBK)          // 24
#define TPAD 40
#define TILE_BYTES (128 * TPAD * 2)   // 10240
#define STAGE_BYTES (2 * TILE_BYTES)  // 20480 (A, B)
#define GEMM_SMEM (2 * STAGE_BYTES)   // 40960

__global__ __launch_bounds__(256, 2)
void gemm_mma_kernel(const __half* __restrict__ A, const __half* __restrict__ B,
                     const float* __restrict__ bias, float* __restrict__ C, int N)
{
    extern __shared__ char dsm[];
    const uint32_t sbase = smem_u32(dsm);
    const int tid = threadIdx.x;
    const int lane = tid & 31;
    const int wid = tid >> 5;
    const int wm = (wid & 1) * 64;
    const int wn = (wid >> 1) * 32;
    const int bm = blockIdx.y * 128;
    const int bn = blockIdx.x * 128;

    const __half* gp[2] = { A, B };

    float acc[4][4][4];
    #pragma unroll
    for (int i = 0; i < 4; i++)
        #pragma unroll
        for (int j = 0; j < 4; j++)
            #pragma unroll
            for (int r = 0; r < 4; r++) acc[i][j][r] = 0.f;

    auto issue = [&](int stage, int kc) {
        const uint32_t st = sbase + (uint32_t)stage * STAGE_BYTES;
        #pragma unroll
        for (int t = 0; t < 4; ++t) {
            int task = tid + t * 256;
            int tile = task >> 9;
            int idx  = task & 511;
            int r = idx >> 2, q = idx & 3;
            int row = (tile == 0 ? bm : bn) + r;
            uint32_t dst = st + (uint32_t)tile * TILE_BYTES + (uint32_t)(r * TPAD + q * 8) * 2;
            CP_ASYNC16(dst, gp[tile] + (size_t)row * K_DIM + kc + q * 8);
        }
        CP_COMMIT();
    };

    issue(0, 0);
    issue(1, GBK);

    const int g = lane >> 3;
    const int arow = wm + (g & 1) * 8 + (lane & 7);
    const int acoff = (g >> 1) * 8;
    const int brow0 = wn + (g >> 1) * 8 + (lane & 7);
    const int bcoff = (g & 1) * 8;

    for (int c = 0; c < NCHUNK; ++c) {
        if (c + 1 < NCHUNK) { CP_WAIT1(); } else { CP_WAIT0(); }
        __syncthreads();

        const uint32_t st = sbase + (uint32_t)(c & 1) * STAGE_BYTES;
        const uint32_t aT = st;
        const uint32_t bT = st + TILE_BYTES;

        #pragma unroll
        for (int ks = 0; ks < 2; ++ks) {
            const int acol = ks * 16 + acoff;
            const int bcol = ks * 16 + bcoff;
            uint32_t a[4][4];
            #pragma unroll
            for (int mf = 0; mf < 4; ++mf) {
                uint32_t off = (uint32_t)((arow + mf * 16) * TPAD + acol) * 2;
                LDSM_X4(a[mf][0], a[mf][1], a[mf][2], a[mf][3], aT + off);
            }
            #pragma unroll
            for (int nf2 = 0; nf2 < 2; ++nf2) {
                uint32_t off = (uint32_t)((brow0 + nf2 * 16) * TPAD + bcol) * 2;
                uint32_t bf[2][2];
                LDSM_X4(bf[0][0], bf[0][1], bf[1][0], bf[1][1], bT + off);
                #pragma unroll
                for (int mf = 0; mf < 4; ++mf)
                    #pragma unroll
                    for (int q = 0; q < 2; ++q)
                        MMA_F16(acc[mf][2 * nf2 + q], a[mf][0], a[mf][1], a[mf][2], a[mf][3],
                                bf[q][0], bf[q][1]);
            }
        }
        __syncthreads();
        if (c + 2 < NCHUNK) issue(c & 1, (c + 2) * GBK);
    }

    #pragma unroll
    for (int mf = 0; mf < 4; ++mf) {
        const int m = bm + wm + mf * 16 + (lane >> 2);
        #pragma unroll
        for (int nf = 0; nf < 4; ++nf) {
            const int n = bn + wn + nf * 8 + (lane & 3) * 2;
            const float2 bv = *(const float2*)&bias[n];
            float2 v0 = { acc[mf][nf][0] + bv.x, acc[mf][nf][1] + bv.y };
            float2 v1 = { acc[mf][nf][2] + bv.x, acc[mf][nf][3] + bv.y };
            *(float2*)&C[(size_t)m * N + n]       = v0;
            *(float2*)&C[(size_t)(m + 8) * N + n] = v1;
        }
    }
}

// ======== MMA flash attention (strided mask, fp16 2-product internals) =======
// smem: K [256][72]h, V [256][72]h, Qh [128][72]h, Ql [128][72]h
#define TROWB 144
#define AT_K  0
#define AT_V  36864
#define AT_QH 73728
#define AT_QL 92160
#define ATTN_SMEM 110592

__global__ __launch_bounds__(256, 2)
void attn_mma_kernel(const float* __restrict__ qkv, __half* __restrict__ oh)
{
    extern __shared__ char smraw[];
    const uint32_t sb = smem_u32(smraw);
    const int tid = threadIdx.x;
    const int lane = tid & 31;
    const int w = tid >> 5;

    const int bh = blockIdx.y;
    const int b = bh / NHEAD;
    const int h = bh % NHEAD;
    const int qb = gridDim.x - 1 - blockIdx.x;   // heaviest blocks first
    const int q0 = qb * QB;
    const int n_str = 16 * (qb + 1);
    const int n_pad = (n_str + 63) & ~63;

    // ---- stage K, V (strided rows) as single fp16 ----
    for (int task = tid; task < n_str * 16; task += 256) {
        const int t   = task >> 4;
        const int sel = (task >> 3) & 1;            // 0 = K, 1 = V
        const int d8  = (task & 7) << 3;
        const size_t src = (size_t)(b * SEQ + t * STRIDE_) * (3 * DMODEL)
                         + (size_t)(1 + sel) * DMODEL + h * HDIM + d8;
        const float4 v0 = *(const float4*)&qkv[src];
        const float4 v1 = *(const float4*)&qkv[src + 4];
        uint4 pk;
        pk.x = pack_f16x2(v0.x, v0.y);
        pk.y = pack_f16x2(v0.z, v0.w);
        pk.z = pack_f16x2(v1.x, v1.y);
        pk.w = pack_f16x2(v1.z, v1.w);
        *(uint4*)(smraw + (sel ? AT_V : AT_K) + t * TROWB + d8 * 2) = pk;
    }
    for (int task = tid; task < (n_pad - n_str) * 8; task += 256) {
        const int t  = n_str + (task >> 3);
        const int d8 = (task & 7) << 3;
        const uint4 z = make_uint4(0, 0, 0, 0);
        *(uint4*)(smraw + AT_K + t * TROWB + d8 * 2) = z;
        *(uint4*)(smraw + AT_V + t * TROWB + d8 * 2) = z;
    }
    // stage Q (pre-scaled by 1/8) as fp16 hi/lo
    for (int task = tid; task < 128 * 8; task += 256) {
        const int r  = task >> 3;
        const int d8 = (task & 7) << 3;
        const size_t src = (size_t)(b * SEQ + q0 + r) * (3 * DMODEL) + h * HDIM + d8;
        float4 v0 = *(const float4*)&qkv[src];
        float4 v1 = *(const float4*)&qkv[src + 4];
        v0.x *= 0.125f; v0.y *= 0.125f; v0.z *= 0.125f; v0.w *= 0.125f;
        v1.x *= 0.125f; v1.y *= 0.125f; v1.z *= 0.125f; v1.w *= 0.125f;
        uint32_t hp0, lp0, hp1, lp1, hp2, lp2, hp3, lp3;
        hilo2_f16(v0.x, v0.y, hp0, lp0);
        hilo2_f16(v0.z, v0.w, hp1, lp1);
        hilo2_f16(v1.x, v1.y, hp2, lp2);
        hilo2_f16(v1.z, v1.w, hp3, lp3);
        const int dst = r * TROWB + d8 * 2;
        *(uint4*)(smraw + AT_QH + dst) = make_uint4(hp0, hp1, hp2, hp3);
        *(uint4*)(smraw + AT_QL + dst) = make_uint4(lp0, lp1, lp2, lp3);
    }
    __syncthreads();

    const int g = lane >> 3;
    const int tig = lane & 3;
    const int arow = 16 * w + (g & 1) * 8 + (lane & 7);
    const int acoff = (g >> 1) * 8;
    uint32_t qh[4][4], ql[4][4];
    #pragma unroll
    for (int kd = 0; kd < 4; ++kd) {
        const uint32_t off = (uint32_t)(arow * TROWB + (kd * 16 + acoff) * 2);
        LDSM_X4(qh[kd][0], qh[kd][1], qh[kd][2], qh[kd][3], sb + AT_QH + off);
        LDSM_X4(ql[kd][0], ql[kd][1], ql[kd][2], ql[kd][3], sb + AT_QL + off);
    }

    float ofr[8][4];
    #pragma unroll
    for (int i = 0; i < 8; i++) { ofr[i][0]=0.f; ofr[i][1]=0.f; ofr[i][2]=0.f; ofr[i][3]=0.f; }
    float m0 = -1e30f, m1 = -1e30f, l0 = 0.f, l1 = 0.f;

    const int row0q = q0 + 16 * w + (lane >> 2);
    const int nt0 = (row0q >> 3) + 1;
    const int nt1 = ((row0q + 8) >> 3) + 1;
    const int nchunks = (16 * qb + 2 * w + 2 + 63) >> 6;

    const int skrow = (g >> 1) * 8 + (lane & 7);
    const int sdcol = (g & 1) * 8;
    const int vkrow = (g & 1) * 8 + (lane & 7);
    const int vdcol = (g >> 1) * 8;

    for (int ch = 0; ch < nchunks; ++ch) {
        const int c0 = ch * 64;
        float sfr[8][4];
        #pragma unroll
        for (int i = 0; i < 8; i++) { sfr[i][0]=0.f; sfr[i][1]=0.f; sfr[i][2]=0.f; sfr[i][3]=0.f; }

        // S = (Qh + Ql) * K
        #pragma unroll
        for (int kd = 0; kd < 4; ++kd) {
            #pragma unroll
            for (int kg = 0; kg < 4; ++kg) {
                const uint32_t addr = sb + AT_K +
                    (uint32_t)((c0 + kg * 16 + skrow) * TROWB + (kd * 16 + sdcol) * 2);
                uint32_t kf[4];
                LDSM_X4(kf[0], kf[1], kf[2], kf[3], addr);
                MMA_F16(sfr[2*kg],   qh[kd][0], qh[kd][1], qh[kd][2], qh[kd][3], kf[0], kf[1]);
                MMA_F16(sfr[2*kg+1], qh[kd][0], qh[kd][1], qh[kd][2], qh[kd][3], kf[2], kf[3]);
                MMA_F16(sfr[2*kg],   ql[kd][0], ql[kd][1], ql[kd][2], ql[kd][3], kf[0], kf[1]);
                MMA_F16(sfr[2*kg+1], ql[kd][0], ql[kd][1], ql[kd][2], ql[kd][3], kf[2], kf[3]);
            }
        }

        // mask + online softmax
        float mx0 = -1e30f, mx1 = -1e30f;
        #pragma unroll
        for (int nf = 0; nf < 8; ++nf) {
            const int tb = c0 + nf * 8 + 2 * tig;
            if (tb >= nt0)     sfr[nf][0] = -1e30f;
            if (tb + 1 >= nt0) sfr[nf][1] = -1e30f;
            if (tb >= nt1)     sfr[nf][2] = -1e30f;
            if (tb + 1 >= nt1) sfr[nf][3] = -1e30f;
            mx0 = fmaxf(mx0, fmaxf(sfr[nf][0], sfr[nf][1]));
            mx1 = fmaxf(mx1, fmaxf(sfr[nf][2], sfr[nf][3]));
        }
        mx0 = fmaxf(mx0, __shfl_xor_sync(0xFFFFFFFFu, mx0, 1));
        mx0 = fmaxf(mx0, __shfl_xor_sync(0xFFFFFFFFu, mx0, 2));
        mx1 = fmaxf(mx1, __shfl_xor_sync(0xFFFFFFFFu, mx1, 1));
        mx1 = fmaxf(mx1, __shfl_xor_sync(0xFFFFFFFFu, mx1, 2));
        const float mn0 = fmaxf(m0, mx0);
        const float mn1 = fmaxf(m1, mx1);
        const float al0 = __expf(m0 - mn0);
        const float al1 = __expf(m1 - mn1);
        float s0 = 0.f, s1 = 0.f;
        #pragma unroll
        for (int nf = 0; nf < 8; ++nf) {
            sfr[nf][0] = __expf(sfr[nf][0] - mn0);
            sfr[nf][1] = __expf(sfr[nf][1] - mn0);
            sfr[nf][2] = __expf(sfr[nf][2] - mn1);
            sfr[nf][3] = __expf(sfr[nf][3] - mn1);
            s0 += sfr[nf][0] + sfr[nf][1];
            s1 += sfr[nf][2] + sfr[nf][3];
        }
        s0 += __shfl_xor_sync(0xFFFFFFFFu, s0, 1);
        s0 += __shfl_xor_sync(0xFFFFFFFFu, s0, 2);
        s1 += __shfl_xor_sync(0xFFFFFFFFu, s1, 1);
        s1 += __shfl_xor_sync(0xFFFFFFFFu, s1, 2);
        l0 = l0 * al0 + s0;
        l1 = l1 * al1 + s1;
        m0 = mn0; m1 = mn1;
        #pragma unroll
        for (int nf = 0; nf < 8; ++nf) {
            ofr[nf][0] *= al0; ofr[nf][1] *= al0;
            ofr[nf][2] *= al1; ofr[nf][3] *= al1;
        }

        // pack P (hi + residual, fp16)
        uint32_t ph[4][4], pl[4][4];
        #pragma unroll
        for (int kk = 0; kk < 4; ++kk) {
            hilo2_f16(sfr[2*kk][0],   sfr[2*kk][1],   ph[kk][0], pl[kk][0]);
            hilo2_f16(sfr[2*kk][2],   sfr[2*kk][3],   ph[kk][1], pl[kk][1]);
            hilo2_f16(sfr[2*kk+1][0], sfr[2*kk+1][1], ph[kk][2], pl[kk][2]);
            hilo2_f16(sfr[2*kk+1][2], sfr[2*kk+1][3], ph[kk][3], pl[kk][3]);
        }

        // O += (Ph + Pl) * V
        #pragma unroll
        for (int kk = 0; kk < 4; ++kk) {
            #pragma unroll
            for (int dd = 0; dd < 4; ++dd) {
                const uint32_t addr = sb + AT_V +
                    (uint32_t)((c0 + kk * 16 + vkrow) * TROWB + (dd * 16 + vdcol) * 2);
                uint32_t vf[4];
                LDSM_X4_T(vf[0], vf[1], vf[2], vf[3], addr);
                MMA_F16(ofr[2*dd],   ph[kk][0], ph[kk][1], ph[kk][2], ph[kk][3], vf[0], vf[1]);
                MMA_F16(ofr[2*dd+1], ph[kk][0], ph[kk][1], ph[kk][2], ph[kk][3], vf[2], vf[3]);
                MMA_F16(ofr[2*dd],   pl[kk][0], pl[kk][1], pl[kk][2], pl[kk][3], vf[0], vf[1]);
                MMA_F16(ofr[2*dd+1], pl[kk][0], pl[kk][1], pl[kk][2], pl[kk][3], vf[2], vf[3]);
            }
        }
    }

    // ---- epilogue: dump O + stats, scalar local keys, write fp16 ----
    __syncthreads();
    float* sO = (float*)smraw;                 // [128][64] fp32, overlays K region
    float* sM = (float*)(smraw + AT_V);        // [128]
    float* sL = sM + 128;
    {
        const int r0 = 16 * w + (lane >> 2);
        #pragma unroll
        for (int nf = 0; nf < 8; ++nf) {
            const int col = nf * 8 + 2 * tig;
            sO[r0 * 64 + col]       = ofr[nf][0];
            sO[r0 * 64 + col + 1]   = ofr[nf][1];
            sO[(r0+8) * 64 + col]   = ofr[nf][2];
            sO[(r0+8) * 64 + col+1] = ofr[nf][3];
        }
        if (tig == 0) {
            sM[r0] = m0; sL[r0] = l0;
            sM[r0 + 8] = m1; sL[r0 + 8] = l1;
        }
    }
    __syncwarp();

    for (int r = 0; r < 16; ++r) {
        const int srow = 16 * w + r;
        const int i = q0 + srow;
        float m_ = sM[srow], l_ = sL[srow];
        float x0 = sO[srow * 64 + lane];
        float x1 = sO[srow * 64 + lane + 32];
        const size_t qbase = (size_t)(b * SEQ + i) * (3 * DMODEL) + h * HDIM;
        const float q0v = qkv[qbase + lane];
        const float q1v = qkv[qbase + lane + 32];
        #pragma unroll
        for (int e = 0; e < 2; ++e) {
            const int j = i - e;
            if (j >= 0 && (j & 7) != 0) {
                const size_t kb = (size_t)(b * SEQ + j) * (3 * DMODEL) + h * HDIM + DMODEL;
                float part = q0v * qkv[kb + lane] + q1v * qkv[kb + lane + 32];
                #pragma unroll
                for (int off = 16; off; off >>= 1)
                    part += __shfl_xor_sync(0xFFFFFFFFu, part, off);
                const float s = part * 0.125f;
                const float mn = fmaxf(m_, s);
                const float al = __expf(m_ - mn);
                const float p = __expf(s - mn);
                x0 = x0 * al + p * qkv[kb + DMODEL + lane];
                x1 = x1 * al + p * qkv[kb + DMODEL + lane + 32];
                l_ = l_ * al + p;
                m_ = mn;
            }
        }
        const float inv = 1.f / l_;
        const size_t ob = (size_t)(b * SEQ + i) * DMODEL + h * HDIM;
        oh[ob + lane]      = __float2half_rn(x0 * inv);
        oh[ob + lane + 32] = __float2half_rn(x1 * inv);
    }
}

// ---------------- launcher ----------------
extern "C" void kernel_launch(void* const* d_in, const int* in_sizes, int n_in,
                              void* d_out, int out_size)
{
    const float* x      = (const float*)d_in[0];
    const float* qkv_w  = (const float*)d_in[1];
    const float* qkv_b  = (const float*)d_in[2];
    const float* out_w  = (const float*)d_in[3];
    const float* out_b  = (const float*)d_in[4];
    float* out = (float*)d_out;

    float* qkv; cudaGetSymbolAddress((void**)&qkv, g_qkv);
    __half *ah, *bh, *owh, *xh;
    cudaGetSymbolAddress((void**)&ah,  g_ah);
    cudaGetSymbolAddress((void**)&bh,  g_bh);
    cudaGetSymbolAddress((void**)&owh, g_owh);
    cudaGetSymbolAddress((void**)&xh,  g_xh);

    cudaFuncSetAttribute(gemm_mma_kernel, cudaFuncAttributeMaxDynamicSharedMemorySize, GEMM_SMEM);
    cudaFuncSetAttribute(attn_mma_kernel, cudaFuncAttributeMaxDynamicSharedMemorySize, ATTN_SMEM);

    // fp16 conversions
    {
        int n4 = M_TOTAL * K_DIM / 4;
        conv_h_kernel<<<(n4 + 255) / 256, 256>>>(x, xh, n4);
        n4 = N_QKV * K_DIM / 4;
        conv_h_kernel<<<(n4 + 255) / 256, 256>>>(qkv_w, bh, n4);
        n4 = DMODEL * K_DIM / 4;
        conv_h_kernel<<<(n4 + 255) / 256, 256>>>(out_w, owh, n4);
    }

    // 1) QKV projection (fp16 single-product)
    gemm_mma_kernel<<<dim3(N_QKV / 128, M_TOTAL / 128), 256, GEMM_SMEM>>>(
        xh, bh, qkv_b, qkv, N_QKV);

    // 2) strided attention (fp16 2-product internals, 2 CTAs/SM)
    attn_mma_kernel<<<dim3(SEQ / QB, BATCH * NHEAD), 256, ATTN_SMEM>>>(qkv, ah);

    // 3) output projection (fp16 single-product)
    gemm_mma_kernel<<<dim3(DMODEL / 128, M_TOTAL / 128), 256, GEMM_SMEM>>>(
        ah, owh, out_b, out, DMODEL);
}

// round 12
// speedup vs baseline: 2.7233x; 1.1437x over previous
#include <cuda_runtime.h>
#include <cuda_bf16.h>
#include <cuda_fp16.h>
#include <cstdint>

// ---------------- problem constants ----------------
#define BATCH 2
#define SEQ   2048
#define DMODEL 768
#define NHEAD 12
#define HDIM  64
#define STRIDE_ 8
#define QB    128

#define M_TOTAL (BATCH*SEQ)   // 4096
#define K_DIM   DMODEL        // 768
#define N_QKV   (3*DMODEL)    // 2304

// ---------------- device scratch ----------------
__device__ float g_qkv[M_TOTAL * N_QKV];
__device__ __half g_ah[M_TOTAL * K_DIM];
__device__ __half g_bh[N_QKV * K_DIM];
__device__ __half g_owh[DMODEL * K_DIM];
__device__ __half g_xh[M_TOTAL * K_DIM];

// ---------------- PTX helpers ----------------
__device__ __forceinline__ uint32_t smem_u32(const void* p) {
    uint32_t a;
    asm("{ .reg .u64 t; cvta.to.shared.u64 t, %1; cvt.u32.u64 %0, t; }" : "=r"(a) : "l"(p));
    return a;
}

#define CP_ASYNC16(dst, src) \
    asm volatile("cp.async.cg.shared.global [%0], [%1], 16;" :: "r"(dst), "l"(src))
#define CP_COMMIT() asm volatile("cp.async.commit_group;" ::: "memory")
#define CP_WAIT1() asm volatile("cp.async.wait_group 1;" ::: "memory")
#define CP_WAIT0() asm volatile("cp.async.wait_group 0;" ::: "memory")

#define LDSM_X4(r0, r1, r2, r3, addr) \
    asm volatile("ldmatrix.sync.aligned.m8n8.x4.shared.b16 {%0,%1,%2,%3}, [%4];" \
        : "=r"(r0), "=r"(r1), "=r"(r2), "=r"(r3) : "r"(addr))

#define LDSM_X4_T(r0, r1, r2, r3, addr) \
    asm volatile("ldmatrix.sync.aligned.m8n8.x4.trans.shared.b16 {%0,%1,%2,%3}, [%4];" \
        : "=r"(r0), "=r"(r1), "=r"(r2), "=r"(r3) : "r"(addr))

#define MMA_F16(c, a0, a1, a2, a3, b0, b1) \
    asm("mma.sync.aligned.m16n8k16.row.col.f32.f16.f16.f32 " \
        "{%0,%1,%2,%3}, {%4,%5,%6,%7}, {%8,%9}, {%0,%1,%2,%3};" \
        : "+f"((c)[0]), "+f"((c)[1]), "+f"((c)[2]), "+f"((c)[3]) \
        : "r"(a0), "r"(a1), "r"(a2), "r"(a3), "r"(b0), "r"(b1))

__device__ __forceinline__ void hilo2_f16(float a, float b, uint32_t& hp, uint32_t& lp) {
    __half2 h = __floats2half2_rn(a, b);
    hp = *(uint32_t*)&h;
    __half2 l = __floats2half2_rn(a - __half2float(__low2half(h)),
                                  b - __half2float(__high2half(h)));
    lp = *(uint32_t*)&l;
}
__device__ __forceinline__ uint32_t pack_f16x2(float a, float b) {
    __half2 h = __floats2half2_rn(a, b);
    return *(uint32_t*)&h;
}

// ---------------- fp32 -> fp16 convert ----------------
__global__ __launch_bounds__(256)
void conv_h_kernel(const float* __restrict__ in, __half* __restrict__ hi, int n4)
{
    int i = blockIdx.x * 256 + threadIdx.x;
    if (i >= n4) return;
    float4 v = ((const float4*)in)[i];
    __half2 a = __floats2half2_rn(v.x, v.y);
    __half2 b = __floats2half2_rn(v.z, v.w);
    ((uint2*)hi)[i] = make_uint2(*(uint32_t*)&a, *(uint32_t*)&b);
}

// ------- fp16 single-product GEMM (unchanged from R11) -------
#define GBK 32
#define NCHUNK (K_DIM / GBK)
#define TPAD 40
#define TILE_BYTES (128 * TPAD * 2)
#define STAGE_BYTES (2 * TILE_BYTES)
#define GEMM_SMEM (2 * STAGE_BYTES)

__global__ __launch_bounds__(256, 2)
void gemm_mma_kernel(const __half* __restrict__ A, const __half* __restrict__ B,
                     const float* __restrict__ bias, float* __restrict__ C, int N)
{
    extern __shared__ char dsm[];
    const uint32_t sbase = smem_u32(dsm);
    const int tid = threadIdx.x;
    const int lane = tid & 31;
    const int wid = tid >> 5;
    const int wm = (wid & 1) * 64;
    const int wn = (wid >> 1) * 32;
    const int bm = blockIdx.y * 128;
    const int bn = blockIdx.x * 128;

    const __half* gp[2] = { A, B };

    float acc[4][4][4];
    #pragma unroll
    for (int i = 0; i < 4; i++)
        #pragma unroll
        for (int j = 0; j < 4; j++)
            #pragma unroll
            for (int r = 0; r < 4; r++) acc[i][j][r] = 0.f;

    auto issue = [&](int stage, int kc) {
        const uint32_t st = sbase + (uint32_t)stage * STAGE_BYTES;
        #pragma unroll
        for (int t = 0; t < 4; ++t) {
            int task = tid + t * 256;
            int tile = task >> 9;
            int idx  = task & 511;
            int r = idx >> 2, q = idx & 3;
            int row = (tile == 0 ? bm : bn) + r;
            uint32_t dst = st + (uint32_t)tile * TILE_BYTES + (uint32_t)(r * TPAD + q * 8) * 2;
            CP_ASYNC16(dst, gp[tile] + (size_t)row * K_DIM + kc + q * 8);
        }
        CP_COMMIT();
    };

    issue(0, 0);
    issue(1, GBK);

    const int g = lane >> 3;
    const int arow = wm + (g & 1) * 8 + (lane & 7);
    const int acoff = (g >> 1) * 8;
    const int brow0 = wn + (g >> 1) * 8 + (lane & 7);
    const int bcoff = (g & 1) * 8;

    for (int c = 0; c < NCHUNK; ++c) {
        if (c + 1 < NCHUNK) { CP_WAIT1(); } else { CP_WAIT0(); }
        __syncthreads();

        const uint32_t st = sbase + (uint32_t)(c & 1) * STAGE_BYTES;
        const uint32_t aT = st;
        const uint32_t bT = st + TILE_BYTES;

        #pragma unroll
        for (int ks = 0; ks < 2; ++ks) {
            const int acol = ks * 16 + acoff;
            const int bcol = ks * 16 + bcoff;
            uint32_t a[4][4];
            #pragma unroll
            for (int mf = 0; mf < 4; ++mf) {
                uint32_t off = (uint32_t)((arow + mf * 16) * TPAD + acol) * 2;
                LDSM_X4(a[mf][0], a[mf][1], a[mf][2], a[mf][3], aT + off);
            }
            #pragma unroll
            for (int nf2 = 0; nf2 < 2; ++nf2) {
                uint32_t off = (uint32_t)((brow0 + nf2 * 16) * TPAD + bcol) * 2;
                uint32_t bf[2][2];
                LDSM_X4(bf[0][0], bf[0][1], bf[1][0], bf[1][1], bT + off);
                #pragma unroll
                for (int mf = 0; mf < 4; ++mf)
                    #pragma unroll
                    for (int q = 0; q < 2; ++q)
                        MMA_F16(acc[mf][2 * nf2 + q], a[mf][0], a[mf][1], a[mf][2], a[mf][3],
                                bf[q][0], bf[q][1]);
            }
        }
        __syncthreads();
        if (c + 2 < NCHUNK) issue(c & 1, (c + 2) * GBK);
    }

    #pragma unroll
    for (int mf = 0; mf < 4; ++mf) {
        const int m = bm + wm + mf * 16 + (lane >> 2);
        #pragma unroll
        for (int nf = 0; nf < 4; ++nf) {
            const int n = bn + wn + nf * 8 + (lane & 3) * 2;
            const float2 bv = *(const float2*)&bias[n];
            float2 v0 = { acc[mf][nf][0] + bv.x, acc[mf][nf][1] + bv.y };
            float2 v1 = { acc[mf][nf][2] + bv.x, acc[mf][nf][3] + bv.y };
            *(float2*)&C[(size_t)m * N + n]       = v0;
            *(float2*)&C[(size_t)(m + 8) * N + n] = v1;
        }
    }
}

// ======== MMA flash attention: strided mask, local band fused via MMA ========
#define TROWB 144
#define AT_K  0
#define AT_V  36864
#define AT_QH 73728
#define AT_QL 92160
#define ATTN_SMEM 110592

__global__ __launch_bounds__(256, 2)
void attn_mma_kernel(const float* __restrict__ qkv, __half* __restrict__ oh)
{
    extern __shared__ char smraw[];
    const uint32_t sb = smem_u32(smraw);
    const int tid = threadIdx.x;
    const int lane = tid & 31;
    const int w = tid >> 5;

    const int bh = blockIdx.y;
    const int b = bh / NHEAD;
    const int h = bh % NHEAD;
    const int qb = gridDim.x - 1 - blockIdx.x;   // heaviest blocks first
    const int q0 = qb * QB;
    const int n_str = 16 * (qb + 1);
    const int n_pad = (n_str + 63) & ~63;

    // ================= Phase A: local band (144 rows, j = q0-16 .. q0+127) ===
    for (int task = tid; task < 144 * 16; task += 256) {
        const int lrow = task >> 4;
        const int sel  = (task >> 3) & 1;           // 0=K, 1=V
        const int d8   = (task & 7) << 3;
        const int j    = q0 - 16 + lrow;
        uint4 pk = make_uint4(0, 0, 0, 0);
        if (j >= 0) {
            const size_t src = (size_t)(b * SEQ + j) * (3 * DMODEL)
                             + (size_t)(1 + sel) * DMODEL + h * HDIM + d8;
            const float4 v0 = *(const float4*)&qkv[src];
            const float4 v1 = *(const float4*)&qkv[src + 4];
            pk.x = pack_f16x2(v0.x, v0.y);
            pk.y = pack_f16x2(v0.z, v0.w);
            pk.z = pack_f16x2(v1.x, v1.y);
            pk.w = pack_f16x2(v1.z, v1.w);
        }
        *(uint4*)(smraw + (sel ? AT_V : AT_K) + lrow * TROWB + d8 * 2) = pk;
    }
    // stage Q (pre-scaled by 1/8) as fp16 hi/lo
    for (int task = tid; task < 128 * 8; task += 256) {
        const int r  = task >> 3;
        const int d8 = (task & 7) << 3;
        const size_t src = (size_t)(b * SEQ + q0 + r) * (3 * DMODEL) + h * HDIM + d8;
        float4 v0 = *(const float4*)&qkv[src];
        float4 v1 = *(const float4*)&qkv[src + 4];
        v0.x *= 0.125f; v0.y *= 0.125f; v0.z *= 0.125f; v0.w *= 0.125f;
        v1.x *= 0.125f; v1.y *= 0.125f; v1.z *= 0.125f; v1.w *= 0.125f;
        uint32_t hp0, lp0, hp1, lp1, hp2, lp2, hp3, lp3;
        hilo2_f16(v0.x, v0.y, hp0, lp0);
        hilo2_f16(v0.z, v0.w, hp1, lp1);
        hilo2_f16(v1.x, v1.y, hp2, lp2);
        hilo2_f16(v1.z, v1.w, hp3, lp3);
        const int dst = r * TROWB + d8 * 2;
        *(uint4*)(smraw + AT_QH + dst) = make_uint4(hp0, hp1, hp2, hp3);
        *(uint4*)(smraw + AT_QL + dst) = make_uint4(lp0, lp1, lp2, lp3);
    }
    __syncthreads();

    const int g = lane >> 3;
    const int tig = lane & 3;
    const int arow = 16 * w + (g & 1) * 8 + (lane & 7);
    const int acoff = (g >> 1) * 8;
    uint32_t qh[4][4], ql[4][4];
    #pragma unroll
    for (int kd = 0; kd < 4; ++kd) {
        const uint32_t off = (uint32_t)(arow * TROWB + (kd * 16 + acoff) * 2);
        LDSM_X4(qh[kd][0], qh[kd][1], qh[kd][2], qh[kd][3], sb + AT_QH + off);
        LDSM_X4(ql[kd][0], ql[kd][1], ql[kd][2], ql[kd][3], sb + AT_QL + off);
    }

    float ofr[8][4];
    #pragma unroll
    for (int i = 0; i < 8; i++) { ofr[i][0]=0.f; ofr[i][1]=0.f; ofr[i][2]=0.f; ofr[i][3]=0.f; }
    float m0 = -1e30f, m1 = -1e30f, l0 = 0.f, l1 = 0.f;

    const int skrow = (g >> 1) * 8 + (lane & 7);
    const int sdcol = (g & 1) * 8;
    const int vkrow = (g & 1) * 8 + (lane & 7);
    const int vdcol = (g >> 1) * 8;
    const int qrow = lane >> 2;

    // ---- band S2: 16 queries x 32 keys (lrows 16w .. 16w+32) ----
    {
        const int lbase = 16 * w;
        float sfr[4][4];
        #pragma unroll
        for (int i = 0; i < 4; i++) { sfr[i][0]=0.f; sfr[i][1]=0.f; sfr[i][2]=0.f; sfr[i][3]=0.f; }

        #pragma unroll
        for (int kd = 0; kd < 4; ++kd) {
            #pragma unroll
            for (int kg = 0; kg < 2; ++kg) {
                const uint32_t addr = sb + AT_K +
                    (uint32_t)((lbase + kg * 16 + skrow) * TROWB + (kd * 16 + sdcol) * 2);
                uint32_t kf[4];
                LDSM_X4(kf[0], kf[1], kf[2], kf[3], addr);
                MMA_F16(sfr[2*kg],   qh[kd][0], qh[kd][1], qh[kd][2], qh[kd][3], kf[0], kf[1]);
                MMA_F16(sfr[2*kg+1], qh[kd][0], qh[kd][1], qh[kd][2], qh[kd][3], kf[2], kf[3]);
                MMA_F16(sfr[2*kg],   ql[kd][0], ql[kd][1], ql[kd][2], ql[kd][3], kf[0], kf[1]);
                MMA_F16(sfr[2*kg+1], ql[kd][0], ql[kd][1], ql[kd][2], ql[kd][3], kf[2], kf[3]);
            }
        }

        // mask: key col c valid for query row qr iff (c==qr+16 || c==qr+15)
        //       && ((j0+c)&7)!=0 && (j0+c)>=0, with j0 = q0+16w-16
        const int j0 = q0 + 16 * w - 16;
        float mx0 = -1e30f, mx1 = -1e30f;
        #pragma unroll
        for (int nf = 0; nf < 4; ++nf) {
            #pragma unroll
            for (int r = 0; r < 2; ++r) {
                const int c = nf * 8 + 2 * tig + r;
                const int j = j0 + c;
                const bool ok = (((j & 7) != 0) && (j >= 0));
                const bool v0 = ok && (c == qrow + 16 || c == qrow + 15);
                const bool v1 = ok && (c == qrow + 24 || c == qrow + 23);
                if (!v0) sfr[nf][r]     = -1e30f;
                if (!v1) sfr[nf][r + 2] = -1e30f;
            }
            mx0 = fmaxf(mx0, fmaxf(sfr[nf][0], sfr[nf][1]));
            mx1 = fmaxf(mx1, fmaxf(sfr[nf][2], sfr[nf][3]));
        }
        mx0 = fmaxf(mx0, __shfl_xor_sync(0xFFFFFFFFu, mx0, 1));
        mx0 = fmaxf(mx0, __shfl_xor_sync(0xFFFFFFFFu, mx0, 2));
        mx1 = fmaxf(mx1, __shfl_xor_sync(0xFFFFFFFFu, mx1, 1));
        mx1 = fmaxf(mx1, __shfl_xor_sync(0xFFFFFFFFu, mx1, 2));
        // clamp so fully-masked rows produce p=0 (not exp(0))
        const float mn0 = fmaxf(fmaxf(m0, mx0), -1e29f);
        const float mn1 = fmaxf(fmaxf(m1, mx1), -1e29f);
        float s0 = 0.f, s1 = 0.f;
        #pragma unroll
        for (int nf = 0; nf < 4; ++nf) {
            sfr[nf][0] = __expf(sfr[nf][0] - mn0);
            sfr[nf][1] = __expf(sfr[nf][1] - mn0);
            sfr[nf][2] = __expf(sfr[nf][2] - mn1);
            sfr[nf][3] = __expf(sfr[nf][3] - mn1);
            s0 += sfr[nf][0] + sfr[nf][1];
            s1 += sfr[nf][2] + sfr[nf][3];
        }
        s0 += __shfl_xor_sync(0xFFFFFFFFu, s0, 1);
        s0 += __shfl_xor_sync(0xFFFFFFFFu, s0, 2);
        s1 += __shfl_xor_sync(0xFFFFFFFFu, s1, 1);
        s1 += __shfl_xor_sync(0xFFFFFFFFu, s1, 2);
        l0 = s0; l1 = s1;
        m0 = mn0; m1 = mn1;

        uint32_t ph[2][4], pl[2][4];
        #pragma unroll
        for (int kk = 0; kk < 2; ++kk) {
            hilo2_f16(sfr[2*kk][0],   sfr[2*kk][1],   ph[kk][0], pl[kk][0]);
            hilo2_f16(sfr[2*kk][2],   sfr[2*kk][3],   ph[kk][1], pl[kk][1]);
            hilo2_f16(sfr[2*kk+1][0], sfr[2*kk+1][1], ph[kk][2], pl[kk][2]);
            hilo2_f16(sfr[2*kk+1][2], sfr[2*kk+1][3], ph[kk][3], pl[kk][3]);
        }
        #pragma unroll
        for (int kk = 0; kk < 2; ++kk) {
            #pragma unroll
            for (int dd = 0; dd < 4; ++dd) {
                const uint32_t addr = sb + AT_V +
                    (uint32_t)((lbase + kk * 16 + vkrow) * TROWB + (dd * 16 + vdcol) * 2);
                uint32_t vf[4];
                LDSM_X4_T(vf[0], vf[1], vf[2], vf[3], addr);
                MMA_F16(ofr[2*dd],   ph[kk][0], ph[kk][1], ph[kk][2], ph[kk][3], vf[0], vf[1]);
                MMA_F16(ofr[2*dd+1], ph[kk][0], ph[kk][1], ph[kk][2], ph[kk][3], vf[2], vf[3]);
                MMA_F16(ofr[2*dd],   pl[kk][0], pl[kk][1], pl[kk][2], pl[kk][3], vf[0], vf[1]);
                MMA_F16(ofr[2*dd+1], pl[kk][0], pl[kk][1], pl[kk][2], pl[kk][3], vf[2], vf[3]);
            }
        }
    }

    // ================= Phase B: strided K/V (overwrites band) ================
    __syncthreads();
    for (int task = tid; task < n_str * 16; task += 256) {
        const int t   = task >> 4;
        const int sel = (task >> 3) & 1;
        const int d8  = (task & 7) << 3;
        const size_t src = (size_t)(b * SEQ + t * STRIDE_) * (3 * DMODEL)
                         + (size_t)(1 + sel) * DMODEL + h * HDIM + d8;
        const float4 v0 = *(const float4*)&qkv[src];
        const float4 v1 = *(const float4*)&qkv[src + 4];
        uint4 pk;
        pk.x = pack_f16x2(v0.x, v0.y);
        pk.y = pack_f16x2(v0.z, v0.w);
        pk.z = pack_f16x2(v1.x, v1.y);
        pk.w = pack_f16x2(v1.z, v1.w);
        *(uint4*)(smraw + (sel ? AT_V : AT_K) + t * TROWB + d8 * 2) = pk;
    }
    for (int task = tid; task < (n_pad - n_str) * 8; task += 256) {
        const int t  = n_str + (task >> 3);
        const int d8 = (task & 7) << 3;
        const uint4 z = make_uint4(0, 0, 0, 0);
        *(uint4*)(smraw + AT_K + t * TROWB + d8 * 2) = z;
        *(uint4*)(smraw + AT_V + t * TROWB + d8 * 2) = z;
    }
    __syncthreads();

    const int row0q = q0 + 16 * w + qrow;
    const int nt0 = (row0q >> 3) + 1;
    const int nt1 = ((row0q + 8) >> 3) + 1;
    const int nchunks = (16 * qb + 2 * w + 2 + 63) >> 6;

    for (int ch = 0; ch < nchunks; ++ch) {
        const int c0 = ch * 64;
        float sfr[8][4];
        #pragma unroll
        for (int i = 0; i < 8; i++) { sfr[i][0]=0.f; sfr[i][1]=0.f; sfr[i][2]=0.f; sfr[i][3]=0.f; }

        #pragma unroll
        for (int kd = 0; kd < 4; ++kd) {
            #pragma unroll
            for (int kg = 0; kg < 4; ++kg) {
                const uint32_t addr = sb + AT_K +
                    (uint32_t)((c0 + kg * 16 + skrow) * TROWB + (kd * 16 + sdcol) * 2);
                uint32_t kf[4];
                LDSM_X4(kf[0], kf[1], kf[2], kf[3], addr);
                MMA_F16(sfr[2*kg],   qh[kd][0], qh[kd][1], qh[kd][2], qh[kd][3], kf[0], kf[1]);
                MMA_F16(sfr[2*kg+1], qh[kd][0], qh[kd][1], qh[kd][2], qh[kd][3], kf[2], kf[3]);
                MMA_F16(sfr[2*kg],   ql[kd][0], ql[kd][1], ql[kd][2], ql[kd][3], kf[0], kf[1]);
                MMA_F16(sfr[2*kg+1], ql[kd][0], ql[kd][1], ql[kd][2], ql[kd][3], kf[2], kf[3]);
            }
        }

        float mx0 = -1e30f, mx1 = -1e30f;
        #pragma unroll
        for (int nf = 0; nf < 8; ++nf) {
            const int tb = c0 + nf * 8 + 2 * tig;
            if (tb >= nt0)     sfr[nf][0] = -1e30f;
            if (tb + 1 >= nt0) sfr[nf][1] = -1e30f;
            if (tb >= nt1)     sfr[nf][2] = -1e30f;
            if (tb + 1 >= nt1) sfr[nf][3] = -1e30f;
            mx0 = fmaxf(mx0, fmaxf(sfr[nf][0], sfr[nf][1]));
            mx1 = fmaxf(mx1, fmaxf(sfr[nf][2], sfr[nf][3]));
        }
        mx0 = fmaxf(mx0, __shfl_xor_sync(0xFFFFFFFFu, mx0, 1));
        mx0 = fmaxf(mx0, __shfl_xor_sync(0xFFFFFFFFu, mx0, 2));
        mx1 = fmaxf(mx1, __shfl_xor_sync(0xFFFFFFFFu, mx1, 1));
        mx1 = fmaxf(mx1, __shfl_xor_sync(0xFFFFFFFFu, mx1, 2));
        const float mn0 = fmaxf(m0, mx0);
        const float mn1 = fmaxf(m1, mx1);
        const float al0 = __expf(m0 - mn0);
        const float al1 = __expf(m1 - mn1);
        float s0 = 0.f, s1 = 0.f;
        #pragma unroll
        for (int nf = 0; nf < 8; ++nf) {
            sfr[nf][0] = __expf(sfr[nf][0] - mn0);
            sfr[nf][1] = __expf(sfr[nf][1] - mn0);
            sfr[nf][2] = __expf(sfr[nf][2] - mn1);
            sfr[nf][3] = __expf(sfr[nf][3] - mn1);
            s0 += sfr[nf][0] + sfr[nf][1];
            s1 += sfr[nf][2] + sfr[nf][3];
        }
        s0 += __shfl_xor_sync(0xFFFFFFFFu, s0, 1);
        s0 += __shfl_xor_sync(0xFFFFFFFFu, s0, 2);
        s1 += __shfl_xor_sync(0xFFFFFFFFu, s1, 1);
        s1 += __shfl_xor_sync(0xFFFFFFFFu, s1, 2);
        l0 = l0 * al0 + s0;
        l1 = l1 * al1 + s1;
        m0 = mn0; m1 = mn1;
        #pragma unroll
        for (int nf = 0; nf < 8; ++nf) {
            ofr[nf][0] *= al0; ofr[nf][1] *= al0;
            ofr[nf][2] *= al1; ofr[nf][3] *= al1;
        }

        uint32_t ph[4][4], pl[4][4];
        #pragma unroll
        for (int kk = 0; kk < 4; ++kk) {
            hilo2_f16(sfr[2*kk][0],   sfr[2*kk][1],   ph[kk][0], pl[kk][0]);
            hilo2_f16(sfr[2*kk][2],   sfr[2*kk][3],   ph[kk][1], pl[kk][1]);
            hilo2_f16(sfr[2*kk+1][0], sfr[2*kk+1][1], ph[kk][2], pl[kk][2]);
            hilo2_f16(sfr[2*kk+1][2], sfr[2*kk+1][3], ph[kk][3], pl[kk][3]);
        }
        #pragma unroll
        for (int kk = 0; kk < 4; ++kk) {
            #pragma unroll
            for (int dd = 0; dd < 4; ++dd) {
                const uint32_t addr = sb + AT_V +
                    (uint32_t)((c0 + kk * 16 + vkrow) * TROWB + (dd * 16 + vdcol) * 2);
                uint32_t vf[4];
                LDSM_X4_T(vf[0], vf[1], vf[2], vf[3], addr);
                MMA_F16(ofr[2*dd],   ph[kk][0], ph[kk][1], ph[kk][2], ph[kk][3], vf[0], vf[1]);
                MMA_F16(ofr[2*dd+1], ph[kk][0], ph[kk][1], ph[kk][2], ph[kk][3], vf[2], vf[3]);
                MMA_F16(ofr[2*dd],   pl[kk][0], pl[kk][1], pl[kk][2], pl[kk][3], vf[0], vf[1]);
                MMA_F16(ofr[2*dd+1], pl[kk][0], pl[kk][1], pl[kk][2], pl[kk][3], vf[2], vf[3]);
            }
        }
    }

    // ================= normalize in-register, coalesced write ================
    const float inv0 = 1.f / l0;
    const float inv1 = 1.f / l1;
    __syncthreads();                       // all warps done reading K/V smem
    {
        const int r0 = 16 * w + qrow;
        #pragma unroll
        for (int nf = 0; nf < 8; ++nf) {
            const int colb = (nf * 8 + 2 * tig) * 2;
            *(__half2*)(smraw + AT_K + r0 * TROWB + colb) =
                __floats2half2_rn(ofr[nf][0] * inv0, ofr[nf][1] * inv0);
            *(__half2*)(smraw + AT_K + (r0 + 8) * TROWB + colb) =
                __floats2half2_rn(ofr[nf][2] * inv1, ofr[nf][3] * inv1);
        }
    }
    __syncwarp();
    #pragma unroll
    for (int t = 0; t < 4; ++t) {
        const int task = lane + t * 32;    // 0..127
        const int r16 = task >> 3;
        const int q = task & 7;
        const int srow = 16 * w + r16;
        const uint4 v = *(const uint4*)(smraw + AT_K + srow * TROWB + q * 16);
        const size_t ob = (size_t)(b * SEQ + q0 + srow) * DMODEL + h * HDIM + q * 8;
        *(uint4*)&oh[ob] = v;
    }
}

// ---------------- launcher ----------------
extern "C" void kernel_launch(void* const* d_in, const int* in_sizes, int n_in,
                              void* d_out, int out_size)
{
    const float* x      = (const float*)d_in[0];
    const float* qkv_w  = (const float*)d_in[1];
    const float* qkv_b  = (const float*)d_in[2];
    const float* out_w  = (const float*)d_in[3];
    const float* out_b  = (const float*)d_in[4];
    float* out = (float*)d_out;

    float* qkv; cudaGetSymbolAddress((void**)&qkv, g_qkv);
    __half *ah, *bh, *owh, *xh;
    cudaGetSymbolAddress((void**)&ah,  g_ah);
    cudaGetSymbolAddress((void**)&bh,  g_bh);
    cudaGetSymbolAddress((void**)&owh, g_owh);
    cudaGetSymbolAddress((void**)&xh,  g_xh);

    cudaFuncSetAttribute(gemm_mma_kernel, cudaFuncAttributeMaxDynamicSharedMemorySize, GEMM_SMEM);
    cudaFuncSetAttribute(attn_mma_kernel, cudaFuncAttributeMaxDynamicSharedMemorySize, ATTN_SMEM);

    // fp16 conversions
    {
        int n4 = M_TOTAL * K_DIM / 4;
        conv_h_kernel<<<(n4 + 255) / 256, 256>>>(x, xh, n4);
        n4 = N_QKV * K_DIM / 4;
        conv_h_kernel<<<(n4 + 255) / 256, 256>>>(qkv_w, bh, n4);
        n4 = DMODEL * K_DIM / 4;
        conv_h_kernel<<<(n4 + 255) / 256, 256>>>(out_w, owh, n4);
    }

    // 1) QKV projection (fp16 single-product)
    gemm_mma_kernel<<<dim3(N_QKV / 128, M_TOTAL / 128), 256, GEMM_SMEM>>>(
        xh, bh, qkv_b, qkv, N_QKV);

    // 2) strided attention (fp16 2-product, band fused via MMA)
    attn_mma_kernel<<<dim3(SEQ / QB, BATCH * NHEAD), 256, ATTN_SMEM>>>(qkv, ah);

    // 3) output projection (fp16 single-product)
    gemm_mma_kernel<<<dim3(DMODEL / 128, M_TOTAL / 128), 256, GEMM_SMEM>>>(
        ah, owh, out_b, out, DMODEL);
}

// round 13
// speedup vs baseline: 2.9697x; 1.0905x over previous
#include <cuda_runtime.h>
#include <cuda_bf16.h>
#include <cuda_fp16.h>
#include <cstdint>

// ---------------- problem constants ----------------
#define BATCH 2
#define SEQ   2048
#define DMODEL 768
#define NHEAD 12
#define HDIM  64
#define STRIDE_ 8
#define QB    128

#define M_TOTAL (BATCH*SEQ)   // 4096
#define K_DIM   DMODEL        // 768
#define N_QKV   (3*DMODEL)    // 2304

// ---------------- device scratch ----------------
__device__ __half g_qkvh[M_TOTAL * N_QKV];  // fp16 QKV intermediate
__device__ __half g_ah[M_TOTAL * K_DIM];    // attention out (fp16)
__device__ __half g_bh[N_QKV * K_DIM];      // qkv_w fp16
__device__ __half g_owh[DMODEL * K_DIM];    // out_w fp16
__device__ __half g_xh[M_TOTAL * K_DIM];    // x fp16

// ---------------- PTX helpers ----------------
__device__ __forceinline__ uint32_t smem_u32(const void* p) {
    uint32_t a;
    asm("{ .reg .u64 t; cvta.to.shared.u64 t, %1; cvt.u32.u64 %0, t; }" : "=r"(a) : "l"(p));
    return a;
}

#define CP_ASYNC16(dst, src) \
    asm volatile("cp.async.cg.shared.global [%0], [%1], 16;" :: "r"(dst), "l"(src))
#define CP_COMMIT() asm volatile("cp.async.commit_group;" ::: "memory")
#define CP_WAIT1() asm volatile("cp.async.wait_group 1;" ::: "memory")
#define CP_WAIT0() asm volatile("cp.async.wait_group 0;" ::: "memory")

#define LDSM_X4(r0, r1, r2, r3, addr) \
    asm volatile("ldmatrix.sync.aligned.m8n8.x4.shared.b16 {%0,%1,%2,%3}, [%4];" \
        : "=r"(r0), "=r"(r1), "=r"(r2), "=r"(r3) : "r"(addr))

#define LDSM_X4_T(r0, r1, r2, r3, addr) \
    asm volatile("ldmatrix.sync.aligned.m8n8.x4.trans.shared.b16 {%0,%1,%2,%3}, [%4];" \
        : "=r"(r0), "=r"(r1), "=r"(r2), "=r"(r3) : "r"(addr))

#define MMA_F16(c, a0, a1, a2, a3, b0, b1) \
    asm("mma.sync.aligned.m16n8k16.row.col.f32.f16.f16.f32 " \
        "{%0,%1,%2,%3}, {%4,%5,%6,%7}, {%8,%9}, {%0,%1,%2,%3};" \
        : "+f"((c)[0]), "+f"((c)[1]), "+f"((c)[2]), "+f"((c)[3]) \
        : "r"(a0), "r"(a1), "r"(a2), "r"(a3), "r"(b0), "r"(b1))

__device__ __forceinline__ uint32_t pack_f16x2(float a, float b) {
    __half2 h = __floats2half2_rn(a, b);
    return *(uint32_t*)&h;
}

__device__ __forceinline__ void store2(float* p, float a, float b) {
    *(float2*)p = make_float2(a, b);
}
__device__ __forceinline__ void store2(__half* p, float a, float b) {
    *(__half2*)p = __floats2half2_rn(a, b);
}

// ---------------- fp32 -> fp16 convert ----------------
__global__ __launch_bounds__(256)
void conv_h_kernel(const float* __restrict__ in, __half* __restrict__ hi, int n4)
{
    int i = blockIdx.x * 256 + threadIdx.x;
    if (i >= n4) return;
    float4 v = ((const float4*)in)[i];
    __half2 a = __floats2half2_rn(v.x, v.y);
    __half2 b = __floats2half2_rn(v.z, v.w);
    ((uint2*)hi)[i] = make_uint2(*(uint32_t*)&a, *(uint32_t*)&b);
}

// ------- fp16 single-product GEMM: C = A[M,768] * (B[N,768])^T + bias -------
#define GBK 32
#define NCHUNK (K_DIM / GBK)
#define TPAD 40
#define TILE_BYTES (128 * TPAD * 2)
#define STAGE_BYTES (2 * TILE_BYTES)
#define GEMM_SMEM (2 * STAGE_BYTES)

template <typename OT>
__global__ __launch_bounds__(256, 2)
void gemm_mma_kernel(const __half* __restrict__ A, const __half* __restrict__ B,
                     const float* __restrict__ bias, OT* __restrict__ C, int N)
{
    extern __shared__ char dsm[];
    const uint32_t sbase = smem_u32(dsm);
    const int tid = threadIdx.x;
    const int lane = tid & 31;
    const int wid = tid >> 5;
    const int wm = (wid & 1) * 64;
    const int wn = (wid >> 1) * 32;
    const int bm = blockIdx.y * 128;
    const int bn = blockIdx.x * 128;

    const __half* gp[2] = { A, B };

    float acc[4][4][4];
    #pragma unroll
    for (int i = 0; i < 4; i++)
        #pragma unroll
        for (int j = 0; j < 4; j++)
            #pragma unroll
            for (int r = 0; r < 4; r++) acc[i][j][r] = 0.f;

    auto issue = [&](int stage, int kc) {
        const uint32_t st = sbase + (uint32_t)stage * STAGE_BYTES;
        #pragma unroll
        for (int t = 0; t < 4; ++t) {
            int task = tid + t * 256;
            int tile = task >> 9;
            int idx  = task & 511;
            int r = idx >> 2, q = idx & 3;
            int row = (tile == 0 ? bm : bn) + r;
            uint32_t dst = st + (uint32_t)tile * TILE_BYTES + (uint32_t)(r * TPAD + q * 8) * 2;
            CP_ASYNC16(dst, gp[tile] + (size_t)row * K_DIM + kc + q * 8);
        }
        CP_COMMIT();
    };

    issue(0, 0);
    issue(1, GBK);

    const int g = lane >> 3;
    const int arow = wm + (g & 1) * 8 + (lane & 7);
    const int acoff = (g >> 1) * 8;
    const int brow0 = wn + (g >> 1) * 8 + (lane & 7);
    const int bcoff = (g & 1) * 8;

    for (int c = 0; c < NCHUNK; ++c) {
        if (c + 1 < NCHUNK) { CP_WAIT1(); } else { CP_WAIT0(); }
        __syncthreads();

        const uint32_t st = sbase + (uint32_t)(c & 1) * STAGE_BYTES;
        const uint32_t aT = st;
        const uint32_t bT = st + TILE_BYTES;

        #pragma unroll
        for (int ks = 0; ks < 2; ++ks) {
            const int acol = ks * 16 + acoff;
            const int bcol = ks * 16 + bcoff;
            uint32_t a[4][4];
            #pragma unroll
            for (int mf = 0; mf < 4; ++mf) {
                uint32_t off = (uint32_t)((arow + mf * 16) * TPAD + acol) * 2;
                LDSM_X4(a[mf][0], a[mf][1], a[mf][2], a[mf][3], aT + off);
            }
            #pragma unroll
            for (int nf2 = 0; nf2 < 2; ++nf2) {
                uint32_t off = (uint32_t)((brow0 + nf2 * 16) * TPAD + bcol) * 2;
                uint32_t bf[2][2];
                LDSM_X4(bf[0][0], bf[0][1], bf[1][0], bf[1][1], bT + off);
                #pragma unroll
                for (int mf = 0; mf < 4; ++mf)
                    #pragma unroll
                    for (int q = 0; q < 2; ++q)
                        MMA_F16(acc[mf][2 * nf2 + q], a[mf][0], a[mf][1], a[mf][2], a[mf][3],
                                bf[q][0], bf[q][1]);
            }
        }
        __syncthreads();
        if (c + 2 < NCHUNK) issue(c & 1, (c + 2) * GBK);
    }

    #pragma unroll
    for (int mf = 0; mf < 4; ++mf) {
        const int m = bm + wm + mf * 16 + (lane >> 2);
        #pragma unroll
        for (int nf = 0; nf < 4; ++nf) {
            const int n = bn + wn + nf * 8 + (lane & 3) * 2;
            const float2 bv = *(const float2*)&bias[n];
            store2(&C[(size_t)m * N + n],       acc[mf][nf][0] + bv.x, acc[mf][nf][1] + bv.y);
            store2(&C[(size_t)(m + 8) * N + n], acc[mf][nf][2] + bv.x, acc[mf][nf][3] + bv.y);
        }
    }
}

// ==== MMA flash attention: all-fp16 single-product, band fused via MMA ====
#define TROWB 144
#define AT_K  0
#define AT_V  36864
#define AT_Q  73728
#define ATTN_SMEM 92160

__global__ __launch_bounds__(256, 2)
void attn_mma_kernel(const __half* __restrict__ qkvh, __half* __restrict__ oh)
{
    extern __shared__ char smraw[];
    const uint32_t sb = smem_u32(smraw);
    const int tid = threadIdx.x;
    const int lane = tid & 31;
    const int w = tid >> 5;

    const int bh = blockIdx.y;
    const int b = bh / NHEAD;
    const int h = bh % NHEAD;
    const int qb = gridDim.x - 1 - blockIdx.x;   // heaviest blocks first
    const int q0 = qb * QB;
    const int n_str = 16 * (qb + 1);
    const int n_pad = (n_str + 63) & ~63;
    const __half2 hscale = __float2half2_rn(0.125f);

    // ======= Phase A: local band (144 rows, j = q0-16 .. q0+127) =======
    for (int task = tid; task < 144 * 16; task += 256) {
        const int lrow = task >> 4;
        const int sel  = (task >> 3) & 1;           // 0=K, 1=V
        const int d8   = (task & 7) << 3;
        const int j    = q0 - 16 + lrow;
        uint4 pk = make_uint4(0, 0, 0, 0);
        if (j >= 0) {
            const size_t src = (size_t)(b * SEQ + j) * (3 * DMODEL)
                             + (size_t)(1 + sel) * DMODEL + h * HDIM + d8;
            pk = *(const uint4*)&qkvh[src];
        }
        *(uint4*)(smraw + (sel ? AT_V : AT_K) + lrow * TROWB + d8 * 2) = pk;
    }
    // stage Q (pre-scaled by 1/8, exact power-of-two)
    for (int task = tid; task < 128 * 8; task += 256) {
        const int r  = task >> 3;
        const int d8 = (task & 7) << 3;
        const size_t src = (size_t)(b * SEQ + q0 + r) * (3 * DMODEL) + h * HDIM + d8;
        uint4 v = *(const uint4*)&qkvh[src];
        __half2* pv = (__half2*)&v;
        #pragma unroll
        for (int k = 0; k < 4; ++k) pv[k] = __hmul2(pv[k], hscale);
        *(uint4*)(smraw + AT_Q + r * TROWB + d8 * 2) = v;
    }
    __syncthreads();

    const int g = lane >> 3;
    const int tig = lane & 3;
    const int arow = 16 * w + (g & 1) * 8 + (lane & 7);
    const int acoff = (g >> 1) * 8;
    uint32_t qf[4][4];
    #pragma unroll
    for (int kd = 0; kd < 4; ++kd) {
        const uint32_t off = (uint32_t)(arow * TROWB + (kd * 16 + acoff) * 2);
        LDSM_X4(qf[kd][0], qf[kd][1], qf[kd][2], qf[kd][3], sb + AT_Q + off);
    }

    float ofr[8][4];
    #pragma unroll
    for (int i = 0; i < 8; i++) { ofr[i][0]=0.f; ofr[i][1]=0.f; ofr[i][2]=0.f; ofr[i][3]=0.f; }
    float m0 = -1e30f, m1 = -1e30f, l0 = 0.f, l1 = 0.f;

    const int skrow = (g >> 1) * 8 + (lane & 7);
    const int sdcol = (g & 1) * 8;
    const int vkrow = (g & 1) * 8 + (lane & 7);
    const int vdcol = (g >> 1) * 8;
    const int qrow = lane >> 2;

    // ---- band S2: 16 queries x 32 keys ----
    {
        const int lbase = 16 * w;
        float sfr[4][4];
        #pragma unroll
        for (int i = 0; i < 4; i++) { sfr[i][0]=0.f; sfr[i][1]=0.f; sfr[i][2]=0.f; sfr[i][3]=0.f; }

        #pragma unroll
        for (int kd = 0; kd < 4; ++kd) {
            #pragma unroll
            for (int kg = 0; kg < 2; ++kg) {
                const uint32_t addr = sb + AT_K +
                    (uint32_t)((lbase + kg * 16 + skrow) * TROWB + (kd * 16 + sdcol) * 2);
                uint32_t kf[4];
                LDSM_X4(kf[0], kf[1], kf[2], kf[3], addr);
                MMA_F16(sfr[2*kg],   qf[kd][0], qf[kd][1], qf[kd][2], qf[kd][3], kf[0], kf[1]);
                MMA_F16(sfr[2*kg+1], qf[kd][0], qf[kd][1], qf[kd][2], qf[kd][3], kf[2], kf[3]);
            }
        }

        // mask: col c valid for row qr iff (c==qr+16 || c==qr+15) && j%8!=0 && j>=0
        const int j0 = q0 + 16 * w - 16;
        float mx0 = -1e30f, mx1 = -1e30f;
        #pragma unroll
        for (int nf = 0; nf < 4; ++nf) {
            #pragma unroll
            for (int r = 0; r < 2; ++r) {
                const int c = nf * 8 + 2 * tig + r;
                const int j = j0 + c;
                const bool ok = (((j & 7) != 0) && (j >= 0));
                const bool v0 = ok && (c == qrow + 16 || c == qrow + 15);
                const bool v1 = ok && (c == qrow + 24 || c == qrow + 23);
                if (!v0) sfr[nf][r]     = -1e30f;
                if (!v1) sfr[nf][r + 2] = -1e30f;
            }
            mx0 = fmaxf(mx0, fmaxf(sfr[nf][0], sfr[nf][1]));
            mx1 = fmaxf(mx1, fmaxf(sfr[nf][2], sfr[nf][3]));
        }
        mx0 = fmaxf(mx0, __shfl_xor_sync(0xFFFFFFFFu, mx0, 1));
        mx0 = fmaxf(mx0, __shfl_xor_sync(0xFFFFFFFFu, mx0, 2));
        mx1 = fmaxf(mx1, __shfl_xor_sync(0xFFFFFFFFu, mx1, 1));
        mx1 = fmaxf(mx1, __shfl_xor_sync(0xFFFFFFFFu, mx1, 2));
        const float mn0 = fmaxf(fmaxf(m0, mx0), -1e29f);
        const float mn1 = fmaxf(fmaxf(m1, mx1), -1e29f);
        float s0 = 0.f, s1 = 0.f;
        #pragma unroll
        for (int nf = 0; nf < 4; ++nf) {
            sfr[nf][0] = __expf(sfr[nf][0] - mn0);
            sfr[nf][1] = __expf(sfr[nf][1] - mn0);
            sfr[nf][2] = __expf(sfr[nf][2] - mn1);
            sfr[nf][3] = __expf(sfr[nf][3] - mn1);
            s0 += sfr[nf][0] + sfr[nf][1];
            s1 += sfr[nf][2] + sfr[nf][3];
        }
        s0 += __shfl_xor_sync(0xFFFFFFFFu, s0, 1);
        s0 += __shfl_xor_sync(0xFFFFFFFFu, s0, 2);
        s1 += __shfl_xor_sync(0xFFFFFFFFu, s1, 1);
        s1 += __shfl_xor_sync(0xFFFFFFFFu, s1, 2);
        l0 = s0; l1 = s1;
        m0 = mn0; m1 = mn1;

        uint32_t ph[2][4];
        #pragma unroll
        for (int kk = 0; kk < 2; ++kk) {
            ph[kk][0] = pack_f16x2(sfr[2*kk][0],   sfr[2*kk][1]);
            ph[kk][1] = pack_f16x2(sfr[2*kk][2],   sfr[2*kk][3]);
            ph[kk][2] = pack_f16x2(sfr[2*kk+1][0], sfr[2*kk+1][1]);
            ph[kk][3] = pack_f16x2(sfr[2*kk+1][2], sfr[2*kk+1][3]);
        }
        #pragma unroll
        for (int kk = 0; kk < 2; ++kk) {
            #pragma unroll
            for (int dd = 0; dd < 4; ++dd) {
                const uint32_t addr = sb + AT_V +
                    (uint32_t)((lbase + kk * 16 + vkrow) * TROWB + (dd * 16 + vdcol) * 2);
                uint32_t vf[4];
                LDSM_X4_T(vf[0], vf[1], vf[2], vf[3], addr);
                MMA_F16(ofr[2*dd],   ph[kk][0], ph[kk][1], ph[kk][2], ph[kk][3], vf[0], vf[1]);
                MMA_F16(ofr[2*dd+1], ph[kk][0], ph[kk][1], ph[kk][2], ph[kk][3], vf[2], vf[3]);
            }
        }
    }

    // ======= Phase B: strided K/V (overwrites band) =======
    __syncthreads();
    for (int task = tid; task < n_str * 16; task += 256) {
        const int t   = task >> 4;
        const int sel = (task >> 3) & 1;
        const int d8  = (task & 7) << 3;
        const size_t src = (size_t)(b * SEQ + t * STRIDE_) * (3 * DMODEL)
                         + (size_t)(1 + sel) * DMODEL + h * HDIM + d8;
        *(uint4*)(smraw + (sel ? AT_V : AT_K) + t * TROWB + d8 * 2) =
            *(const uint4*)&qkvh[src];
    }
    for (int task = tid; task < (n_pad - n_str) * 8; task += 256) {
        const int t  = n_str + (task >> 3);
        const int d8 = (task & 7) << 3;
        const uint4 z = make_uint4(0, 0, 0, 0);
        *(uint4*)(smraw + AT_K + t * TROWB + d8 * 2) = z;
        *(uint4*)(smraw + AT_V + t * TROWB + d8 * 2) = z;
    }
    __syncthreads();

    const int row0q = q0 + 16 * w + qrow;
    const int nt0 = (row0q >> 3) + 1;
    const int nt1 = ((row0q + 8) >> 3) + 1;
    const int nchunks = (16 * qb + 2 * w + 2 + 63) >> 6;

    for (int ch = 0; ch < nchunks; ++ch) {
        const int c0 = ch * 64;
        float sfr[8][4];
        #pragma unroll
        for (int i = 0; i < 8; i++) { sfr[i][0]=0.f; sfr[i][1]=0.f; sfr[i][2]=0.f; sfr[i][3]=0.f; }

        #pragma unroll
        for (int kd = 0; kd < 4; ++kd) {
            #pragma unroll
            for (int kg = 0; kg < 4; ++kg) {
                const uint32_t addr = sb + AT_K +
                    (uint32_t)((c0 + kg * 16 + skrow) * TROWB + (kd * 16 + sdcol) * 2);
                uint32_t kf[4];
                LDSM_X4(kf[0], kf[1], kf[2], kf[3], addr);
                MMA_F16(sfr[2*kg],   qf[kd][0], qf[kd][1], qf[kd][2], qf[kd][3], kf[0], kf[1]);
                MMA_F16(sfr[2*kg+1], qf[kd][0], qf[kd][1], qf[kd][2], qf[kd][3], kf[2], kf[3]);
            }
        }

        float mx0 = -1e30f, mx1 = -1e30f;
        #pragma unroll
        for (int nf = 0; nf < 8; ++nf) {
            const int tb = c0 + nf * 8 + 2 * tig;
            if (tb >= nt0)     sfr[nf][0] = -1e30f;
            if (tb + 1 >= nt0) sfr[nf][1] = -1e30f;
            if (tb >= nt1)     sfr[nf][2] = -1e30f;
            if (tb + 1 >= nt1) sfr[nf][3] = -1e30f;
            mx0 = fmaxf(mx0, fmaxf(sfr[nf][0], sfr[nf][1]));
            mx1 = fmaxf(mx1, fmaxf(sfr[nf][2], sfr[nf][3]));
        }
        mx0 = fmaxf(mx0, __shfl_xor_sync(0xFFFFFFFFu, mx0, 1));
        mx0 = fmaxf(mx0, __shfl_xor_sync(0xFFFFFFFFu, mx0, 2));
        mx1 = fmaxf(mx1, __shfl_xor_sync(0xFFFFFFFFu, mx1, 1));
        mx1 = fmaxf(mx1, __shfl_xor_sync(0xFFFFFFFFu, mx1, 2));
        const float mn0 = fmaxf(m0, mx0);
        const float mn1 = fmaxf(m1, mx1);
        const float al0 = __expf(m0 - mn0);
        const float al1 = __expf(m1 - mn1);
        float s0 = 0.f, s1 = 0.f;
        #pragma unroll
        for (int nf = 0; nf < 8; ++nf) {
            sfr[nf][0] = __expf(sfr[nf][0] - mn0);
            sfr[nf][1] = __expf(sfr[nf][1] - mn0);
            sfr[nf][2] = __expf(sfr[nf][2] - mn1);
            sfr[nf][3] = __expf(sfr[nf][3] - mn1);
            s0 += sfr[nf][0] + sfr[nf][1];
            s1 += sfr[nf][2] + sfr[nf][3];
        }
        s0 += __shfl_xor_sync(0xFFFFFFFFu, s0, 1);
        s0 += __shfl_xor_sync(0xFFFFFFFFu, s0, 2);
        s1 += __shfl_xor_sync(0xFFFFFFFFu, s1, 1);
        s1 += __shfl_xor_sync(0xFFFFFFFFu, s1, 2);
        l0 = l0 * al0 + s0;
        l1 = l1 * al1 + s1;
        m0 = mn0; m1 = mn1;
        #pragma unroll
        for (int nf = 0; nf < 8; ++nf) {
            ofr[nf][0] *= al0; ofr[nf][1] *= al0;
            ofr[nf][2] *= al1; ofr[nf][3] *= al1;
        }

        uint32_t ph[4][4];
        #pragma unroll
        for (int kk = 0; kk < 4; ++kk) {
            ph[kk][0] = pack_f16x2(sfr[2*kk][0],   sfr[2*kk][1]);
            ph[kk][1] = pack_f16x2(sfr[2*kk][2],   sfr[2*kk][3]);
            ph[kk][2] = pack_f16x2(sfr[2*kk+1][0], sfr[2*kk+1][1]);
            ph[kk][3] = pack_f16x2(sfr[2*kk+1][2], sfr[2*kk+1][3]);
        }
        #pragma unroll
        for (int kk = 0; kk < 4; ++kk) {
            #pragma unroll
            for (int dd = 0; dd < 4; ++dd) {
                const uint32_t addr = sb + AT_V +
                    (uint32_t)((c0 + kk * 16 + vkrow) * TROWB + (dd * 16 + vdcol) * 2);
                uint32_t vf[4];
                LDSM_X4_T(vf[0], vf[1], vf[2], vf[3], addr);
                MMA_F16(ofr[2*dd],   ph[kk][0], ph[kk][1], ph[kk][2], ph[kk][3], vf[0], vf[1]);
                MMA_F16(ofr[2*dd+1], ph[kk][0], ph[kk][1], ph[kk][2], ph[kk][3], vf[2], vf[3]);
            }
        }
    }

    // ======= normalize in-register, coalesced write =======
    const float inv0 = 1.f / l0;
    const float inv1 = 1.f / l1;
    __syncthreads();
    {
        const int r0 = 16 * w + qrow;
        #pragma unroll
        for (int nf = 0; nf < 8; ++nf) {
            const int colb = (nf * 8 + 2 * tig) * 2;
            *(__half2*)(smraw + AT_K + r0 * TROWB + colb) =
                __floats2half2_rn(ofr[nf][0] * inv0, ofr[nf][1] * inv0);
            *(__half2*)(smraw + AT_K + (r0 + 8) * TROWB + colb) =
                __floats2half2_rn(ofr[nf][2] * inv1, ofr[nf][3] * inv1);
        }
    }
    __syncwarp();
    #pragma unroll
    for (int t = 0; t < 4; ++t) {
        const int task = lane + t * 32;
        const int r16 = task >> 3;
        const int q = task & 7;
        const int srow = 16 * w + r16;
        const uint4 v = *(const uint4*)(smraw + AT_K + srow * TROWB + q * 16);
        const size_t ob = (size_t)(b * SEQ + q0 + srow) * DMODEL + h * HDIM + q * 8;
        *(uint4*)&oh[ob] = v;
    }
}

// ---------------- launcher ----------------
extern "C" void kernel_launch(void* const* d_in, const int* in_sizes, int n_in,
                              void* d_out, int out_size)
{
    const float* x      = (const float*)d_in[0];
    const float* qkv_w  = (const float*)d_in[1];
    const float* qkv_b  = (const float*)d_in[2];
    const float* out_w  = (const float*)d_in[3];
    const float* out_b  = (const float*)d_in[4];
    float* out = (float*)d_out;

    __half *qkvh, *ah, *bh, *owh, *xh;
    cudaGetSymbolAddress((void**)&qkvh, g_qkvh);
    cudaGetSymbolAddress((void**)&ah,   g_ah);
    cudaGetSymbolAddress((void**)&bh,   g_bh);
    cudaGetSymbolAddress((void**)&owh,  g_owh);
    cudaGetSymbolAddress((void**)&xh,   g_xh);

    cudaFuncSetAttribute(gemm_mma_kernel<__half>,
                         cudaFuncAttributeMaxDynamicSharedMemorySize, GEMM_SMEM);
    cudaFuncSetAttribute(gemm_mma_kernel<float>,
                         cudaFuncAttributeMaxDynamicSharedMemorySize, GEMM_SMEM);
    cudaFuncSetAttribute(attn_mma_kernel,
                         cudaFuncAttributeMaxDynamicSharedMemorySize, ATTN_SMEM);

    // fp16 conversions
    {
        int n4 = M_TOTAL * K_DIM / 4;
        conv_h_kernel<<<(n4 + 255) / 256, 256>>>(x, xh, n4);
        n4 = N_QKV * K_DIM / 4;
        conv_h_kernel<<<(n4 + 255) / 256, 256>>>(qkv_w, bh, n4);
        n4 = DMODEL * K_DIM / 4;
        conv_h_kernel<<<(n4 + 255) / 256, 256>>>(out_w, owh, n4);
    }

    // 1) QKV projection -> fp16 directly
    gemm_mma_kernel<__half><<<dim3(N_QKV / 128, M_TOTAL / 128), 256, GEMM_SMEM>>>(
        xh, bh, qkv_b, qkvh, N_QKV);

    // 2) strided attention (all-fp16 single-product, band fused)
    attn_mma_kernel<<<dim3(SEQ / QB, BATCH * NHEAD), 256, ATTN_SMEM>>>(qkvh, ah);

    // 3) output projection -> fp32 final
    gemm_mma_kernel<float><<<dim3(DMODEL / 128, M_TOTAL / 128), 256, GEMM_SMEM>>>(
        ah, owh, out_b, out, DMODEL);
}

// round 14
// speedup vs baseline: 3.3614x; 1.1319x over previous
#include <cuda_runtime.h>
#include <cuda_bf16.h>
#include <cuda_fp16.h>
#include <cstdint>

// ---------------- problem constants ----------------
#define BATCH 2
#define SEQ   2048
#define DMODEL 768
#define NHEAD 12
#define HDIM  64
#define STRIDE_ 8
#define QB    128

#define M_TOTAL (BATCH*SEQ)   // 4096
#define K_DIM   DMODEL        // 768
#define N_QKV   (3*DMODEL)    // 2304

// ---------------- device scratch ----------------
__device__ __half g_qkvh[M_TOTAL * N_QKV];  // fp16 QKV intermediate
__device__ __half g_ah[M_TOTAL * K_DIM];    // attention out (fp16)
__device__ __half g_bh[N_QKV * K_DIM];      // qkv_w fp16
__device__ __half g_owh[DMODEL * K_DIM];    // out_w fp16
__device__ __half g_xh[M_TOTAL * K_DIM];    // x fp16

// ---------------- PTX helpers ----------------
__device__ __forceinline__ uint32_t smem_u32(const void* p) {
    uint32_t a;
    asm("{ .reg .u64 t; cvta.to.shared.u64 t, %1; cvt.u32.u64 %0, t; }" : "=r"(a) : "l"(p));
    return a;
}

#define CP_ASYNC16(dst, src) \
    asm volatile("cp.async.cg.shared.global [%0], [%1], 16;" :: "r"(dst), "l"(src))
#define CP_COMMIT() asm volatile("cp.async.commit_group;" ::: "memory")
#define CP_WAIT1() asm volatile("cp.async.wait_group 1;" ::: "memory")
#define CP_WAIT0() asm volatile("cp.async.wait_group 0;" ::: "memory")

#define LDSM_X4(r0, r1, r2, r3, addr) \
    asm volatile("ldmatrix.sync.aligned.m8n8.x4.shared.b16 {%0,%1,%2,%3}, [%4];" \
        : "=r"(r0), "=r"(r1), "=r"(r2), "=r"(r3) : "r"(addr))

#define LDSM_X4_T(r0, r1, r2, r3, addr) \
    asm volatile("ldmatrix.sync.aligned.m8n8.x4.trans.shared.b16 {%0,%1,%2,%3}, [%4];" \
        : "=r"(r0), "=r"(r1), "=r"(r2), "=r"(r3) : "r"(addr))

#define MMA_F16(c, a0, a1, a2, a3, b0, b1) \
    asm("mma.sync.aligned.m16n8k16.row.col.f32.f16.f16.f32 " \
        "{%0,%1,%2,%3}, {%4,%5,%6,%7}, {%8,%9}, {%0,%1,%2,%3};" \
        : "+f"((c)[0]), "+f"((c)[1]), "+f"((c)[2]), "+f"((c)[3]) \
        : "r"(a0), "r"(a1), "r"(a2), "r"(a3), "r"(b0), "r"(b1))

__device__ __forceinline__ uint32_t pack_f16x2(float a, float b) {
    __half2 h = __floats2half2_rn(a, b);
    return *(uint32_t*)&h;
}

__device__ __forceinline__ void store2(float* p, float a, float b) {
    *(float2*)p = make_float2(a, b);
}
__device__ __forceinline__ void store2(__half* p, float a, float b) {
    *(__half2*)p = __floats2half2_rn(a, b);
}

// ---------------- fused fp32 -> fp16 convert (x, qkv_w, out_w) ----------------
__global__ __launch_bounds__(256)
void conv_all_kernel(const float* __restrict__ x, const float* __restrict__ w1,
                     const float* __restrict__ w2,
                     __half* __restrict__ xh, __half* __restrict__ bh,
                     __half* __restrict__ owh, int n1, int n2, int n3)
{
    int i = blockIdx.x * 256 + threadIdx.x;
    const float* src;
    __half* dst;
    int off;
    if (i < n1)            { src = x;  dst = xh;  off = i; }
    else if (i < n1 + n2)  { src = w1; dst = bh;  off = i - n1; }
    else if (i < n1+n2+n3) { src = w2; dst = owh; off = i - n1 - n2; }
    else return;
    float4 v = ((const float4*)src)[off];
    __half2 a = __floats2half2_rn(v.x, v.y);
    __half2 b = __floats2half2_rn(v.z, v.w);
    ((uint2*)dst)[off] = make_uint2(*(uint32_t*)&a, *(uint32_t*)&b);
}

// ------- fp16 single-product GEMM, GBK=64: C = A[M,768] * (B[N,768])^T + bias --
#define GBK 64
#define NCHUNK (K_DIM / GBK)          // 12
#define TPAD 72                        // row stride in fp16 (144 B)
#define TILE_BYTES (128 * TPAD * 2)    // 18432
#define STAGE_BYTES (2 * TILE_BYTES)   // 36864 (A, B)
#define GEMM_SMEM (2 * STAGE_BYTES)    // 73728 -> 2 CTAs/SM

template <typename OT>
__global__ __launch_bounds__(256, 2)
void gemm_mma_kernel(const __half* __restrict__ A, const __half* __restrict__ B,
                     const float* __restrict__ bias, OT* __restrict__ C, int N)
{
    extern __shared__ char dsm[];
    const uint32_t sbase = smem_u32(dsm);
    const int tid = threadIdx.x;
    const int lane = tid & 31;
    const int wid = tid >> 5;
    const int wm = (wid & 1) * 64;
    const int wn = (wid >> 1) * 32;
    const int bm = blockIdx.y * 128;
    const int bn = blockIdx.x * 128;

    const __half* gp[2] = { A, B };

    float acc[4][4][4];
    #pragma unroll
    for (int i = 0; i < 4; i++)
        #pragma unroll
        for (int j = 0; j < 4; j++)
            #pragma unroll
            for (int r = 0; r < 4; r++) acc[i][j][r] = 0.f;

    auto issue = [&](int stage, int kc) {
        const uint32_t st = sbase + (uint32_t)stage * STAGE_BYTES;
        #pragma unroll
        for (int t = 0; t < 8; ++t) {
            int task = tid + t * 256;          // 0..2047
            int tile = task >> 10;             // 0..1
            int idx  = task & 1023;
            int r = idx >> 3, q = idx & 7;
            int row = (tile == 0 ? bm : bn) + r;
            uint32_t dst = st + (uint32_t)tile * TILE_BYTES + (uint32_t)(r * TPAD + q * 8) * 2;
            CP_ASYNC16(dst, gp[tile] + (size_t)row * K_DIM + kc + q * 8);
        }
        CP_COMMIT();
    };

    issue(0, 0);
    issue(1, GBK);

    const int g = lane >> 3;
    const int arow = wm + (g & 1) * 8 + (lane & 7);
    const int acoff = (g >> 1) * 8;
    const int brow0 = wn + (g >> 1) * 8 + (lane & 7);
    const int bcoff = (g & 1) * 8;

    for (int c = 0; c < NCHUNK; ++c) {
        if (c + 1 < NCHUNK) { CP_WAIT1(); } else { CP_WAIT0(); }
        __syncthreads();

        const uint32_t st = sbase + (uint32_t)(c & 1) * STAGE_BYTES;
        const uint32_t aT = st;
        const uint32_t bT = st + TILE_BYTES;

        #pragma unroll
        for (int ks = 0; ks < 4; ++ks) {
            const int acol = ks * 16 + acoff;
            const int bcol = ks * 16 + bcoff;
            uint32_t a[4][4];
            #pragma unroll
            for (int mf = 0; mf < 4; ++mf) {
                uint32_t off = (uint32_t)((arow + mf * 16) * TPAD + acol) * 2;
                LDSM_X4(a[mf][0], a[mf][1], a[mf][2], a[mf][3], aT + off);
            }
            #pragma unroll
            for (int nf2 = 0; nf2 < 2; ++nf2) {
                uint32_t off = (uint32_t)((brow0 + nf2 * 16) * TPAD + bcol) * 2;
                uint32_t bf[2][2];
                LDSM_X4(bf[0][0], bf[0][1], bf[1][0], bf[1][1], bT + off);
                #pragma unroll
                for (int mf = 0; mf < 4; ++mf)
                    #pragma unroll
                    for (int q = 0; q < 2; ++q)
                        MMA_F16(acc[mf][2 * nf2 + q], a[mf][0], a[mf][1], a[mf][2], a[mf][3],
                                bf[q][0], bf[q][1]);
            }
        }
        __syncthreads();
        if (c + 2 < NCHUNK) issue(c & 1, (c + 2) * GBK);
    }

    #pragma unroll
    for (int mf = 0; mf < 4; ++mf) {
        const int m = bm + wm + mf * 16 + (lane >> 2);
        #pragma unroll
        for (int nf = 0; nf < 4; ++nf) {
            const int n = bn + wn + nf * 8 + (lane & 3) * 2;
            const float2 bv = *(const float2*)&bias[n];
            store2(&C[(size_t)m * N + n],       acc[mf][nf][0] + bv.x, acc[mf][nf][1] + bv.y);
            store2(&C[(size_t)(m + 8) * N + n], acc[mf][nf][2] + bv.x, acc[mf][nf][3] + bv.y);
        }
    }
}

// ==== MMA flash attention: all-fp16 single-product, band fused via MMA ====
#define TROWB 144
#define AT_K  0
#define AT_V  36864
#define AT_Q  73728
#define ATTN_SMEM 92160

__global__ __launch_bounds__(256, 2)
void attn_mma_kernel(const __half* __restrict__ qkvh, __half* __restrict__ oh)
{
    extern __shared__ char smraw[];
    const uint32_t sb = smem_u32(smraw);
    const int tid = threadIdx.x;
    const int lane = tid & 31;
    const int w = tid >> 5;

    const int bh = blockIdx.y;
    const int b = bh / NHEAD;
    const int h = bh % NHEAD;
    const int qb = gridDim.x - 1 - blockIdx.x;   // heaviest blocks first
    const int q0 = qb * QB;
    const int n_str = 16 * (qb + 1);
    const int n_pad = (n_str + 63) & ~63;
    const __half2 hscale = __float2half2_rn(0.125f);

    // ======= Phase A: local band (144 rows, j = q0-16 .. q0+127) =======
    for (int task = tid; task < 144 * 16; task += 256) {
        const int lrow = task >> 4;
        const int sel  = (task >> 3) & 1;           // 0=K, 1=V
        const int d8   = (task & 7) << 3;
        const int j    = q0 - 16 + lrow;
        uint4 pk = make_uint4(0, 0, 0, 0);
        if (j >= 0) {
            const size_t src = (size_t)(b * SEQ + j) * (3 * DMODEL)
                             + (size_t)(1 + sel) * DMODEL + h * HDIM + d8;
            pk = *(const uint4*)&qkvh[src];
        }
        *(uint4*)(smraw + (sel ? AT_V : AT_K) + lrow * TROWB + d8 * 2) = pk;
    }
    // stage Q (pre-scaled by 1/8, exact power-of-two)
    for (int task = tid; task < 128 * 8; task += 256) {
        const int r  = task >> 3;
        const int d8 = (task & 7) << 3;
        const size_t src = (size_t)(b * SEQ + q0 + r) * (3 * DMODEL) + h * HDIM + d8;
        uint4 v = *(const uint4*)&qkvh[src];
        __half2* pv = (__half2*)&v;
        #pragma unroll
        for (int k = 0; k < 4; ++k) pv[k] = __hmul2(pv[k], hscale);
        *(uint4*)(smraw + AT_Q + r * TROWB + d8 * 2) = v;
    }
    __syncthreads();

    const int g = lane >> 3;
    const int tig = lane & 3;
    const int arow = 16 * w + (g & 1) * 8 + (lane & 7);
    const int acoff = (g >> 1) * 8;
    uint32_t qf[4][4];
    #pragma unroll
    for (int kd = 0; kd < 4; ++kd) {
        const uint32_t off = (uint32_t)(arow * TROWB + (kd * 16 + acoff) * 2);
        LDSM_X4(qf[kd][0], qf[kd][1], qf[kd][2], qf[kd][3], sb + AT_Q + off);
    }

    float ofr[8][4];
    #pragma unroll
    for (int i = 0; i < 8; i++) { ofr[i][0]=0.f; ofr[i][1]=0.f; ofr[i][2]=0.f; ofr[i][3]=0.f; }
    float m0 = -1e30f, m1 = -1e30f, l0 = 0.f, l1 = 0.f;

    const int skrow = (g >> 1) * 8 + (lane & 7);
    const int sdcol = (g & 1) * 8;
    const int vkrow = (g & 1) * 8 + (lane & 7);
    const int vdcol = (g >> 1) * 8;
    const int qrow = lane >> 2;

    // ---- band S2: 16 queries x 32 keys ----
    {
        const int lbase = 16 * w;
        float sfr[4][4];
        #pragma unroll
        for (int i = 0; i < 4; i++) { sfr[i][0]=0.f; sfr[i][1]=0.f; sfr[i][2]=0.f; sfr[i][3]=0.f; }

        #pragma unroll
        for (int kd = 0; kd < 4; ++kd) {
            #pragma unroll
            for (int kg = 0; kg < 2; ++kg) {
                const uint32_t addr = sb + AT_K +
                    (uint32_t)((lbase + kg * 16 + skrow) * TROWB + (kd * 16 + sdcol) * 2);
                uint32_t kf[4];
                LDSM_X4(kf[0], kf[1], kf[2], kf[3], addr);
                MMA_F16(sfr[2*kg],   qf[kd][0], qf[kd][1], qf[kd][2], qf[kd][3], kf[0], kf[1]);
                MMA_F16(sfr[2*kg+1], qf[kd][0], qf[kd][1], qf[kd][2], qf[kd][3], kf[2], kf[3]);
            }
        }

        // mask: col c valid for row qr iff (c==qr+16 || c==qr+15) && j%8!=0 && j>=0
        const int j0 = q0 + 16 * w - 16;
        float mx0 = -1e30f, mx1 = -1e30f;
        #pragma unroll
        for (int nf = 0; nf < 4; ++nf) {
            #pragma unroll
            for (int r = 0; r < 2; ++r) {
                const int c = nf * 8 + 2 * tig + r;
                const int j = j0 + c;
                const bool ok = (((j & 7) != 0) && (j >= 0));
                const bool v0 = ok && (c == qrow + 16 || c == qrow + 15);
                const bool v1 = ok && (c == qrow + 24 || c == qrow + 23);
                if (!v0) sfr[nf][r]     = -1e30f;
                if (!v1) sfr[nf][r + 2] = -1e30f;
            }
            mx0 = fmaxf(mx0, fmaxf(sfr[nf][0], sfr[nf][1]));
            mx1 = fmaxf(mx1, fmaxf(sfr[nf][2], sfr[nf][3]));
        }
        mx0 = fmaxf(mx0, __shfl_xor_sync(0xFFFFFFFFu, mx0, 1));
        mx0 = fmaxf(mx0, __shfl_xor_sync(0xFFFFFFFFu, mx0, 2));
        mx1 = fmaxf(mx1, __shfl_xor_sync(0xFFFFFFFFu, mx1, 1));
        mx1 = fmaxf(mx1, __shfl_xor_sync(0xFFFFFFFFu, mx1, 2));
        const float mn0 = fmaxf(fmaxf(m0, mx0), -1e29f);
        const float mn1 = fmaxf(fmaxf(m1, mx1), -1e29f);
        float s0 = 0.f, s1 = 0.f;
        #pragma unroll
        for (int nf = 0; nf < 4; ++nf) {
            sfr[nf][0] = __expf(sfr[nf][0] - mn0);
            sfr[nf][1] = __expf(sfr[nf][1] - mn0);
            sfr[nf][2] = __expf(sfr[nf][2] - mn1);
            sfr[nf][3] = __expf(sfr[nf][3] - mn1);
            s0 += sfr[nf][0] + sfr[nf][1];
            s1 += sfr[nf][2] + sfr[nf][3];
        }
        s0 += __shfl_xor_sync(0xFFFFFFFFu, s0, 1);
        s0 += __shfl_xor_sync(0xFFFFFFFFu, s0, 2);
        s1 += __shfl_xor_sync(0xFFFFFFFFu, s1, 1);
        s1 += __shfl_xor_sync(0xFFFFFFFFu, s1, 2);
        l0 = s0; l1 = s1;
        m0 = mn0; m1 = mn1;

        uint32_t ph[2][4];
        #pragma unroll
        for (int kk = 0; kk < 2; ++kk) {
            ph[kk][0] = pack_f16x2(sfr[2*kk][0],   sfr[2*kk][1]);
            ph[kk][1] = pack_f16x2(sfr[2*kk][2],   sfr[2*kk][3]);
            ph[kk][2] = pack_f16x2(sfr[2*kk+1][0], sfr[2*kk+1][1]);
            ph[kk][3] = pack_f16x2(sfr[2*kk+1][2], sfr[2*kk+1][3]);
        }
        #pragma unroll
        for (int kk = 0; kk < 2; ++kk) {
            #pragma unroll
            for (int dd = 0; dd < 4; ++dd) {
                const uint32_t addr = sb + AT_V +
                    (uint32_t)((lbase + kk * 16 + vkrow) * TROWB + (dd * 16 + vdcol) * 2);
                uint32_t vf[4];
                LDSM_X4_T(vf[0], vf[1], vf[2], vf[3], addr);
                MMA_F16(ofr[2*dd],   ph[kk][0], ph[kk][1], ph[kk][2], ph[kk][3], vf[0], vf[1]);
                MMA_F16(ofr[2*dd+1], ph[kk][0], ph[kk][1], ph[kk][2], ph[kk][3], vf[2], vf[3]);
            }
        }
    }

    // ======= Phase B: strided K/V (overwrites band) =======
    __syncthreads();
    for (int task = tid; task < n_str * 16; task += 256) {
        const int t   = task >> 4;
        const int sel = (task >> 3) & 1;
        const int d8  = (task & 7) << 3;
        const size_t src = (size_t)(b * SEQ + t * STRIDE_) * (3 * DMODEL)
                         + (size_t)(1 + sel) * DMODEL + h * HDIM + d8;
        *(uint4*)(smraw + (sel ? AT_V : AT_K) + t * TROWB + d8 * 2) =
            *(const uint4*)&qkvh[src];
    }
    for (int task = tid; task < (n_pad - n_str) * 8; task += 256) {
        const int t  = n_str + (task >> 3);
        const int d8 = (task & 7) << 3;
        const uint4 z = make_uint4(0, 0, 0, 0);
        *(uint4*)(smraw + AT_K + t * TROWB + d8 * 2) = z;
        *(uint4*)(smraw + AT_V + t * TROWB + d8 * 2) = z;
    }
    __syncthreads();

    const int row0q = q0 + 16 * w + qrow;
    const int nt0 = (row0q >> 3) + 1;
    const int nt1 = ((row0q + 8) >> 3) + 1;
    const int nchunks = (16 * qb + 2 * w + 2 + 63) >> 6;

    for (int ch = 0; ch < nchunks; ++ch) {
        const int c0 = ch * 64;
        float sfr[8][4];
        #pragma unroll
        for (int i = 0; i < 8; i++) { sfr[i][0]=0.f; sfr[i][1]=0.f; sfr[i][2]=0.f; sfr[i][3]=0.f; }

        #pragma unroll
        for (int kd = 0; kd < 4; ++kd) {
            #pragma unroll
            for (int kg = 0; kg < 4; ++kg) {
                const uint32_t addr = sb + AT_K +
                    (uint32_t)((c0 + kg * 16 + skrow) * TROWB + (kd * 16 + sdcol) * 2);
                uint32_t kf[4];
                LDSM_X4(kf[0], kf[1], kf[2], kf[3], addr);
                MMA_F16(sfr[2*kg],   qf[kd][0], qf[kd][1], qf[kd][2], qf[kd][3], kf[0], kf[1]);
                MMA_F16(sfr[2*kg+1], qf[kd][0], qf[kd][1], qf[kd][2], qf[kd][3], kf[2], kf[3]);
            }
        }

        float mx0 = -1e30f, mx1 = -1e30f;
        #pragma unroll
        for (int nf = 0; nf < 8; ++nf) {
            const int tb = c0 + nf * 8 + 2 * tig;
            if (tb >= nt0)     sfr[nf][0] = -1e30f;
            if (tb + 1 >= nt0) sfr[nf][1] = -1e30f;
            if (tb >= nt1)     sfr[nf][2] = -1e30f;
            if (tb + 1 >= nt1) sfr[nf][3] = -1e30f;
            mx0 = fmaxf(mx0, fmaxf(sfr[nf][0], sfr[nf][1]));
            mx1 = fmaxf(mx1, fmaxf(sfr[nf][2], sfr[nf][3]));
        }
        mx0 = fmaxf(mx0, __shfl_xor_sync(0xFFFFFFFFu, mx0, 1));
        mx0 = fmaxf(mx0, __shfl_xor_sync(0xFFFFFFFFu, mx0, 2));
        mx1 = fmaxf(mx1, __shfl_xor_sync(0xFFFFFFFFu, mx1, 1));
        mx1 = fmaxf(mx1, __shfl_xor_sync(0xFFFFFFFFu, mx1, 2));
        const float mn0 = fmaxf(m0, mx0);
        const float mn1 = fmaxf(m1, mx1);
        const float al0 = __expf(m0 - mn0);
        const float al1 = __expf(m1 - mn1);
        float s0 = 0.f, s1 = 0.f;
        #pragma unroll
        for (int nf = 0; nf < 8; ++nf) {
            sfr[nf][0] = __expf(sfr[nf][0] - mn0);
            sfr[nf][1] = __expf(sfr[nf][1] - mn0);
            sfr[nf][2] = __expf(sfr[nf][2] - mn1);
            sfr[nf][3] = __expf(sfr[nf][3] - mn1);
            s0 += sfr[nf][0] + sfr[nf][1];
            s1 += sfr[nf][2] + sfr[nf][3];
        }
        s0 += __shfl_xor_sync(0xFFFFFFFFu, s0, 1);
        s0 += __shfl_xor_sync(0xFFFFFFFFu, s0, 2);
        s1 += __shfl_xor_sync(0xFFFFFFFFu, s1, 1);
        s1 += __shfl_xor_sync(0xFFFFFFFFu, s1, 2);
        l0 = l0 * al0 + s0;
        l1 = l1 * al1 + s1;
        m0 = mn0; m1 = mn1;
        #pragma unroll
        for (int nf = 0; nf < 8; ++nf) {
            ofr[nf][0] *= al0; ofr[nf][1] *= al0;
            ofr[nf][2] *= al1; ofr[nf][3] *= al1;
        }

        uint32_t ph[4][4];
        #pragma unroll
        for (int kk = 0; kk < 4; ++kk) {
            ph[kk][0] = pack_f16x2(sfr[2*kk][0],   sfr[2*kk][1]);
            ph[kk][1] = pack_f16x2(sfr[2*kk][2],   sfr[2*kk][3]);
            ph[kk][2] = pack_f16x2(sfr[2*kk+1][0], sfr[2*kk+1][1]);
            ph[kk][3] = pack_f16x2(sfr[2*kk+1][2], sfr[2*kk+1][3]);
        }
        #pragma unroll
        for (int kk = 0; kk < 4; ++kk) {
            #pragma unroll
            for (int dd = 0; dd < 4; ++dd) {
                const uint32_t addr = sb + AT_V +
                    (uint32_t)((c0 + kk * 16 + vkrow) * TROWB + (dd * 16 + vdcol) * 2);
                uint32_t vf[4];
                LDSM_X4_T(vf[0], vf[1], vf[2], vf[3], addr);
                MMA_F16(ofr[2*dd],   ph[kk][0], ph[kk][1], ph[kk][2], ph[kk][3], vf[0], vf[1]);
                MMA_F16(ofr[2*dd+1], ph[kk][0], ph[kk][1], ph[kk][2], ph[kk][3], vf[2], vf[3]);
            }
        }
    }

    // ======= normalize in-register, coalesced write =======
    const float inv0 = 1.f / l0;
    const float inv1 = 1.f / l1;
    __syncthreads();
    {
        const int r0 = 16 * w + qrow;
        #pragma unroll
        for (int nf = 0; nf < 8; ++nf) {
            const int colb = (nf * 8 + 2 * tig) * 2;
            *(__half2*)(smraw + AT_K + r0 * TROWB + colb) =
                __floats2half2_rn(ofr[nf][0] * inv0, ofr[nf][1] * inv0);
            *(__half2*)(smraw + AT_K + (r0 + 8) * TROWB + colb) =
                __floats2half2_rn(ofr[nf][2] * inv1, ofr[nf][3] * inv1);
        }
    }
    __syncwarp();
    #pragma unroll
    for (int t = 0; t < 4; ++t) {
        const int task = lane + t * 32;
        const int r16 = task >> 3;
        const int q = task & 7;
        const int srow = 16 * w + r16;
        const uint4 v = *(const uint4*)(smraw + AT_K + srow * TROWB + q * 16);
        const size_t ob = (size_t)(b * SEQ + q0 + srow) * DMODEL + h * HDIM + q * 8;
        *(uint4*)&oh[ob] = v;
    }
}

// ---------------- launcher ----------------
extern "C" void kernel_launch(void* const* d_in, const int* in_sizes, int n_in,
                              void* d_out, int out_size)
{
    const float* x      = (const float*)d_in[0];
    const float* qkv_w  = (const float*)d_in[1];
    const float* qkv_b  = (const float*)d_in[2];
    const float* out_w  = (const float*)d_in[3];
    const float* out_b  = (const float*)d_in[4];
    float* out = (float*)d_out;

    __half *qkvh, *ah, *bh, *owh, *xh;
    cudaGetSymbolAddress((void**)&qkvh, g_qkvh);
    cudaGetSymbolAddress((void**)&ah,   g_ah);
    cudaGetSymbolAddress((void**)&bh,   g_bh);
    cudaGetSymbolAddress((void**)&owh,  g_owh);
    cudaGetSymbolAddress((void**)&xh,   g_xh);

    cudaFuncSetAttribute(gemm_mma_kernel<__half>,
                         cudaFuncAttributeMaxDynamicSharedMemorySize, GEMM_SMEM);
    cudaFuncSetAttribute(gemm_mma_kernel<float>,
                         cudaFuncAttributeMaxDynamicSharedMemorySize, GEMM_SMEM);
    cudaFuncSetAttribute(attn_mma_kernel,
                         cudaFuncAttributeMaxDynamicSharedMemorySize, ATTN_SMEM);

    // fused fp16 conversions (one launch)
    {
        const int n1 = M_TOTAL * K_DIM / 4;
        const int n2 = N_QKV * K_DIM / 4;
        const int n3 = DMODEL * K_DIM / 4;
        const int nt = n1 + n2 + n3;
        conv_all_kernel<<<(nt + 255) / 256, 256>>>(x, qkv_w, out_w, xh, bh, owh, n1, n2, n3);
    }

    // 1) QKV projection -> fp16 directly
    gemm_mma_kernel<__half><<<dim3(N_QKV / 128, M_TOTAL / 128), 256, GEMM_SMEM>>>(
        xh, bh, qkv_b, qkvh, N_QKV);

    // 2) strided attention (all-fp16 single-product, band fused)
    attn_mma_kernel<<<dim3(SEQ / QB, BATCH * NHEAD), 256, ATTN_SMEM>>>(qkvh, ah);

    // 3) output projection -> fp32 final
    gemm_mma_kernel<float><<<dim3(DMODEL / 128, M_TOTAL / 128), 256, GEMM_SMEM>>>(
        ah, owh, out_b, out, DMODEL);
}

// round 15
// speedup vs baseline: 3.4076x; 1.0137x over previous
#include <cuda_runtime.h>
#include <cuda_bf16.h>
#include <cuda_fp16.h>
#include <cstdint>

// ---------------- problem constants ----------------
#define BATCH 2
#define SEQ   2048
#define DMODEL 768
#define NHEAD 12
#define HDIM  64
#define STRIDE_ 8
#define QB    128

#define M_TOTAL (BATCH*SEQ)   // 4096
#define K_DIM   DMODEL        // 768
#define N_QKV   (3*DMODEL)    // 2304

// ---------------- device scratch ----------------
__device__ __half g_qkvh[M_TOTAL * N_QKV];
__device__ __half g_ah[M_TOTAL * K_DIM];
__device__ __half g_bh[N_QKV * K_DIM];
__device__ __half g_owh[DMODEL * K_DIM];
__device__ __half g_xh[M_TOTAL * K_DIM];

// ---------------- PTX helpers ----------------
__device__ __forceinline__ uint32_t smem_u32(const void* p) {
    uint32_t a;
    asm("{ .reg .u64 t; cvta.to.shared.u64 t, %1; cvt.u32.u64 %0, t; }" : "=r"(a) : "l"(p));
    return a;
}

#define CP_ASYNC16(dst, src) \
    asm volatile("cp.async.cg.shared.global [%0], [%1], 16;" :: "r"(dst), "l"(src))
#define CP_COMMIT() asm volatile("cp.async.commit_group;" ::: "memory")
#define CP_WAIT1() asm volatile("cp.async.wait_group 1;" ::: "memory")
#define CP_WAIT0() asm volatile("cp.async.wait_group 0;" ::: "memory")

#define LDSM_X4(r0, r1, r2, r3, addr) \
    asm volatile("ldmatrix.sync.aligned.m8n8.x4.shared.b16 {%0,%1,%2,%3}, [%4];" \
        : "=r"(r0), "=r"(r1), "=r"(r2), "=r"(r3) : "r"(addr))

#define LDSM_X4_T(r0, r1, r2, r3, addr) \
    asm volatile("ldmatrix.sync.aligned.m8n8.x4.trans.shared.b16 {%0,%1,%2,%3}, [%4];" \
        : "=r"(r0), "=r"(r1), "=r"(r2), "=r"(r3) : "r"(addr))

#define MMA_F16(c, a0, a1, a2, a3, b0, b1) \
    asm("mma.sync.aligned.m16n8k16.row.col.f32.f16.f16.f32 " \
        "{%0,%1,%2,%3}, {%4,%5,%6,%7}, {%8,%9}, {%0,%1,%2,%3};" \
        : "+f"((c)[0]), "+f"((c)[1]), "+f"((c)[2]), "+f"((c)[3]) \
        : "r"(a0), "r"(a1), "r"(a2), "r"(a3), "r"(b0), "r"(b1))

__device__ __forceinline__ uint32_t pack_f16x2(float a, float b) {
    __half2 h = __floats2half2_rn(a, b);
    return *(uint32_t*)&h;
}
__device__ __forceinline__ void store2(float* p, float a, float b) {
    *(float2*)p = make_float2(a, b);
}
__device__ __forceinline__ void store2(__half* p, float a, float b) {
    *(__half2*)p = __floats2half2_rn(a, b);
}

// ---------------- fused fp32 -> fp16 convert ----------------
__global__ __launch_bounds__(256)
void conv_all_kernel(const float* __restrict__ x, const float* __restrict__ w1,
                     const float* __restrict__ w2,
                     __half* __restrict__ xh, __half* __restrict__ bh,
                     __half* __restrict__ owh, int n1, int n2, int n3)
{
    int i = blockIdx.x * 256 + threadIdx.x;
    const float* src;
    __half* dst;
    int off;
    if (i < n1)            { src = x;  dst = xh;  off = i; }
    else if (i < n1 + n2)  { src = w1; dst = bh;  off = i - n1; }
    else if (i < n1+n2+n3) { src = w2; dst = owh; off = i - n1 - n2; }
    else return;
    float4 v = ((const float4*)src)[off];
    __half2 a = __floats2half2_rn(v.x, v.y);
    __half2 b = __floats2half2_rn(v.z, v.w);
    ((uint2*)dst)[off] = make_uint2(*(uint32_t*)&a, *(uint32_t*)&b);
}

// ------- fp16 GEMM 128x128, GBK=64 (QKV) -------
#define GBK 64
#define NCHUNK (K_DIM / GBK)          // 12
#define TPAD 72
#define TILE_BYTES (128 * TPAD * 2)   // 18432
#define STAGE_BYTES (2 * TILE_BYTES)  // 36864
#define GEMM_SMEM (2 * STAGE_BYTES)   // 73728

template <typename OT>
__global__ __launch_bounds__(256, 2)
void gemm_mma_kernel(const __half* __restrict__ A, const __half* __restrict__ B,
                     const float* __restrict__ bias, OT* __restrict__ C, int N)
{
    extern __shared__ char dsm[];
    const uint32_t sbase = smem_u32(dsm);
    const int tid = threadIdx.x;
    const int lane = tid & 31;
    const int wid = tid >> 5;
    const int wm = (wid & 1) * 64;
    const int wn = (wid >> 1) * 32;
    const int bm = blockIdx.y * 128;
    const int bn = blockIdx.x * 128;

    const __half* gp[2] = { A, B };

    float acc[4][4][4];
    #pragma unroll
    for (int i = 0; i < 4; i++)
        #pragma unroll
        for (int j = 0; j < 4; j++)
            #pragma unroll
            for (int r = 0; r < 4; r++) acc[i][j][r] = 0.f;

    auto issue = [&](int stage, int kc) {
        const uint32_t st = sbase + (uint32_t)stage * STAGE_BYTES;
        #pragma unroll
        for (int t = 0; t < 8; ++t) {
            int task = tid + t * 256;
            int tile = task >> 10;
            int idx  = task & 1023;
            int r = idx >> 3, q = idx & 7;
            int row = (tile == 0 ? bm : bn) + r;
            uint32_t dst = st + (uint32_t)tile * TILE_BYTES + (uint32_t)(r * TPAD + q * 8) * 2;
            CP_ASYNC16(dst, gp[tile] + (size_t)row * K_DIM + kc + q * 8);
        }
        CP_COMMIT();
    };

    issue(0, 0);
    issue(1, GBK);

    const int g = lane >> 3;
    const int arow = wm + (g & 1) * 8 + (lane & 7);
    const int acoff = (g >> 1) * 8;
    const int brow0 = wn + (g >> 1) * 8 + (lane & 7);
    const int bcoff = (g & 1) * 8;

    for (int c = 0; c < NCHUNK; ++c) {
        if (c + 1 < NCHUNK) { CP_WAIT1(); } else { CP_WAIT0(); }
        __syncthreads();

        const uint32_t st = sbase + (uint32_t)(c & 1) * STAGE_BYTES;
        const uint32_t aT = st;
        const uint32_t bT = st + TILE_BYTES;

        #pragma unroll
        for (int ks = 0; ks < 4; ++ks) {
            const int acol = ks * 16 + acoff;
            const int bcol = ks * 16 + bcoff;
            uint32_t a[4][4];
            #pragma unroll
            for (int mf = 0; mf < 4; ++mf) {
                uint32_t off = (uint32_t)((arow + mf * 16) * TPAD + acol) * 2;
                LDSM_X4(a[mf][0], a[mf][1], a[mf][2], a[mf][3], aT + off);
            }
            #pragma unroll
            for (int nf2 = 0; nf2 < 2; ++nf2) {
                uint32_t off = (uint32_t)((brow0 + nf2 * 16) * TPAD + bcol) * 2;
                uint32_t bf[2][2];
                LDSM_X4(bf[0][0], bf[0][1], bf[1][0], bf[1][1], bT + off);
                #pragma unroll
                for (int mf = 0; mf < 4; ++mf)
                    #pragma unroll
                    for (int q = 0; q < 2; ++q)
                        MMA_F16(acc[mf][2 * nf2 + q], a[mf][0], a[mf][1], a[mf][2], a[mf][3],
                                bf[q][0], bf[q][1]);
            }
        }
        __syncthreads();
        if (c + 2 < NCHUNK) issue(c & 1, (c + 2) * GBK);
    }

    #pragma unroll
    for (int mf = 0; mf < 4; ++mf) {
        const int m = bm + wm + mf * 16 + (lane >> 2);
        #pragma unroll
        for (int nf = 0; nf < 4; ++nf) {
            const int n = bn + wn + nf * 8 + (lane & 3) * 2;
            const float2 bv = *(const float2*)&bias[n];
            store2(&C[(size_t)m * N + n],       acc[mf][nf][0] + bv.x, acc[mf][nf][1] + bv.y);
            store2(&C[(size_t)(m + 8) * N + n], acc[mf][nf][2] + bv.x, acc[mf][nf][3] + bv.y);
        }
    }
}

// ------- fp16 GEMM 64x128, GBK=64 (proj: better wave balance, 384 CTAs) -------
#define A64_TILE (64 * TPAD * 2)              // 9216
#define STAGE64  (A64_TILE + TILE_BYTES)      // 27648
#define GEMM64_SMEM (2 * STAGE64)             // 55296

__global__ __launch_bounds__(256, 2)
void gemm_mma64_kernel(const __half* __restrict__ A, const __half* __restrict__ B,
                       const float* __restrict__ bias, float* __restrict__ C, int N)
{
    extern __shared__ char dsm[];
    const uint32_t sbase = smem_u32(dsm);
    const int tid = threadIdx.x;
    const int lane = tid & 31;
    const int wid = tid >> 5;
    const int wm = (wid & 1) * 32;       // 2 M groups of 32
    const int wn = (wid >> 1) * 32;      // 4 N groups of 32
    const int bm = blockIdx.y * 64;
    const int bn = blockIdx.x * 128;

    float acc[2][4][4];
    #pragma unroll
    for (int i = 0; i < 2; i++)
        #pragma unroll
        for (int j = 0; j < 4; j++)
            #pragma unroll
            for (int r = 0; r < 4; r++) acc[i][j][r] = 0.f;

    auto issue = [&](int stage, int kc) {
        const uint32_t st = sbase + (uint32_t)stage * STAGE64;
        #pragma unroll
        for (int t = 0; t < 6; ++t) {
            int task = tid + t * 256;          // 0..1535
            int tile, idx;
            if (task < 512) { tile = 0; idx = task; }
            else            { tile = 1; idx = task - 512; }
            int r = idx >> 3, q = idx & 7;
            int row = (tile == 0 ? bm : bn) + r;
            uint32_t dst = st + (tile ? A64_TILE : 0u) + (uint32_t)(r * TPAD + q * 8) * 2;
            CP_ASYNC16(dst, (tile == 0 ? A : B) + (size_t)row * K_DIM + kc + q * 8);
        }
        CP_COMMIT();
    };

    issue(0, 0);
    issue(1, GBK);

    const int g = lane >> 3;
    const int arow = wm + (g & 1) * 8 + (lane & 7);
    const int acoff = (g >> 1) * 8;
    const int brow0 = wn + (g >> 1) * 8 + (lane & 7);
    const int bcoff = (g & 1) * 8;

    for (int c = 0; c < NCHUNK; ++c) {
        if (c + 1 < NCHUNK) { CP_WAIT1(); } else { CP_WAIT0(); }
        __syncthreads();

        const uint32_t st = sbase + (uint32_t)(c & 1) * STAGE64;
        const uint32_t aT = st;
        const uint32_t bT = st + A64_TILE;

        #pragma unroll
        for (int ks = 0; ks < 4; ++ks) {
            const int acol = ks * 16 + acoff;
            const int bcol = ks * 16 + bcoff;
            uint32_t a[2][4];
            #pragma unroll
            for (int mf = 0; mf < 2; ++mf) {
                uint32_t off = (uint32_t)((arow + mf * 16) * TPAD + acol) * 2;
                LDSM_X4(a[mf][0], a[mf][1], a[mf][2], a[mf][3], aT + off);
            }
            #pragma unroll
            for (int nf2 = 0; nf2 < 2; ++nf2) {
                uint32_t off = (uint32_t)((brow0 + nf2 * 16) * TPAD + bcol) * 2;
                uint32_t bf[2][2];
                LDSM_X4(bf[0][0], bf[0][1], bf[1][0], bf[1][1], bT + off);
                #pragma unroll
                for (int mf = 0; mf < 2; ++mf)
                    #pragma unroll
                    for (int q = 0; q < 2; ++q)
                        MMA_F16(acc[mf][2 * nf2 + q], a[mf][0], a[mf][1], a[mf][2], a[mf][3],
                                bf[q][0], bf[q][1]);
            }
        }
        __syncthreads();
        if (c + 2 < NCHUNK) issue(c & 1, (c + 2) * GBK);
    }

    #pragma unroll
    for (int mf = 0; mf < 2; ++mf) {
        const int m = bm + wm + mf * 16 + (lane >> 2);
        #pragma unroll
        for (int nf = 0; nf < 4; ++nf) {
            const int n = bn + wn + nf * 8 + (lane & 3) * 2;
            const float2 bv = *(const float2*)&bias[n];
            store2(&C[(size_t)m * N + n],       acc[mf][nf][0] + bv.x, acc[mf][nf][1] + bv.y);
            store2(&C[(size_t)(m + 8) * N + n], acc[mf][nf][2] + bv.x, acc[mf][nf][3] + bv.y);
        }
    }
}

// ==== MMA flash attention: all-fp16 single-product, band fused via MMA ====
#define TROWB 144
#define AT_K  0
#define AT_V  36864
#define AT_Q  73728
#define ATTN_SMEM 92160

__global__ __launch_bounds__(256, 2)
void attn_mma_kernel(const __half* __restrict__ qkvh, __half* __restrict__ oh)
{
    extern __shared__ char smraw[];
    const uint32_t sb = smem_u32(smraw);
    const int tid = threadIdx.x;
    const int lane = tid & 31;
    const int w = tid >> 5;

    const int bh = blockIdx.y;
    const int b = bh / NHEAD;
    const int h = bh % NHEAD;
    const int qb = gridDim.x - 1 - blockIdx.x;
    const int q0 = qb * QB;
    const int n_str = 16 * (qb + 1);
    const int n_pad = (n_str + 63) & ~63;
    const __half2 hscale = __float2half2_rn(0.125f);

    // Phase A: local band
    for (int task = tid; task < 144 * 16; task += 256) {
        const int lrow = task >> 4;
        const int sel  = (task >> 3) & 1;
        const int d8   = (task & 7) << 3;
        const int j    = q0 - 16 + lrow;
        uint4 pk = make_uint4(0, 0, 0, 0);
        if (j >= 0) {
            const size_t src = (size_t)(b * SEQ + j) * (3 * DMODEL)
                             + (size_t)(1 + sel) * DMODEL + h * HDIM + d8;
            pk = *(const uint4*)&qkvh[src];
        }
        *(uint4*)(smraw + (sel ? AT_V : AT_K) + lrow * TROWB + d8 * 2) = pk;
    }
    for (int task = tid; task < 128 * 8; task += 256) {
        const int r  = task >> 3;
        const int d8 = (task & 7) << 3;
        const size_t src = (size_t)(b * SEQ + q0 + r) * (3 * DMODEL) + h * HDIM + d8;
        uint4 v = *(const uint4*)&qkvh[src];
        __half2* pv = (__half2*)&v;
        #pragma unroll
        for (int k = 0; k < 4; ++k) pv[k] = __hmul2(pv[k], hscale);
        *(uint4*)(smraw + AT_Q + r * TROWB + d8 * 2) = v;
    }
    __syncthreads();

    const int g = lane >> 3;
    const int tig = lane & 3;
    const int arow = 16 * w + (g & 1) * 8 + (lane & 7);
    const int acoff = (g >> 1) * 8;
    uint32_t qf[4][4];
    #pragma unroll
    for (int kd = 0; kd < 4; ++kd) {
        const uint32_t off = (uint32_t)(arow * TROWB + (kd * 16 + acoff) * 2);
        LDSM_X4(qf[kd][0], qf[kd][1], qf[kd][2], qf[kd][3], sb + AT_Q + off);
    }

    float ofr[8][4];
    #pragma unroll
    for (int i = 0; i < 8; i++) { ofr[i][0]=0.f; ofr[i][1]=0.f; ofr[i][2]=0.f; ofr[i][3]=0.f; }
    float m0 = -1e30f, m1 = -1e30f, l0 = 0.f, l1 = 0.f;

    const int skrow = (g >> 1) * 8 + (lane & 7);
    const int sdcol = (g & 1) * 8;
    const int vkrow = (g & 1) * 8 + (lane & 7);
    const int vdcol = (g >> 1) * 8;
    const int qrow = lane >> 2;

    // band S2
    {
        const int lbase = 16 * w;
        float sfr[4][4];
        #pragma unroll
        for (int i = 0; i < 4; i++) { sfr[i][0]=0.f; sfr[i][1]=0.f; sfr[i][2]=0.f; sfr[i][3]=0.f; }

        #pragma unroll
        for (int kd = 0; kd < 4; ++kd) {
            #pragma unroll
            for (int kg = 0; kg < 2; ++kg) {
                const uint32_t addr = sb + AT_K +
                    (uint32_t)((lbase + kg * 16 + skrow) * TROWB + (kd * 16 + sdcol) * 2);
                uint32_t kf[4];
                LDSM_X4(kf[0], kf[1], kf[2], kf[3], addr);
                MMA_F16(sfr[2*kg],   qf[kd][0], qf[kd][1], qf[kd][2], qf[kd][3], kf[0], kf[1]);
                MMA_F16(sfr[2*kg+1], qf[kd][0], qf[kd][1], qf[kd][2], qf[kd][3], kf[2], kf[3]);
            }
        }

        const int j0 = q0 + 16 * w - 16;
        float mx0 = -1e30f, mx1 = -1e30f;
        #pragma unroll
        for (int nf = 0; nf < 4; ++nf) {
            #pragma unroll
            for (int r = 0; r < 2; ++r) {
                const int c = nf * 8 + 2 * tig + r;
                const int j = j0 + c;
                const bool ok = (((j & 7) != 0) && (j >= 0));
                const bool v0 = ok && (c == qrow + 16 || c == qrow + 15);
                const bool v1 = ok && (c == qrow + 24 || c == qrow + 23);
                if (!v0) sfr[nf][r]     = -1e30f;
                if (!v1) sfr[nf][r + 2] = -1e30f;
            }
            mx0 = fmaxf(mx0, fmaxf(sfr[nf][0], sfr[nf][1]));
            mx1 = fmaxf(mx1, fmaxf(sfr[nf][2], sfr[nf][3]));
        }
        mx0 = fmaxf(mx0, __shfl_xor_sync(0xFFFFFFFFu, mx0, 1));
        mx0 = fmaxf(mx0, __shfl_xor_sync(0xFFFFFFFFu, mx0, 2));
        mx1 = fmaxf(mx1, __shfl_xor_sync(0xFFFFFFFFu, mx1, 1));
        mx1 = fmaxf(mx1, __shfl_xor_sync(0xFFFFFFFFu, mx1, 2));
        const float mn0 = fmaxf(fmaxf(m0, mx0), -1e29f);
        const float mn1 = fmaxf(fmaxf(m1, mx1), -1e29f);
        float s0 = 0.f, s1 = 0.f;
        #pragma unroll
        for (int nf = 0; nf < 4; ++nf) {
            sfr[nf][0] = __expf(sfr[nf][0] - mn0);
            sfr[nf][1] = __expf(sfr[nf][1] - mn0);
            sfr[nf][2] = __expf(sfr[nf][2] - mn1);
            sfr[nf][3] = __expf(sfr[nf][3] - mn1);
            s0 += sfr[nf][0] + sfr[nf][1];
            s1 += sfr[nf][2] + sfr[nf][3];
        }
        s0 += __shfl_xor_sync(0xFFFFFFFFu, s0, 1);
        s0 += __shfl_xor_sync(0xFFFFFFFFu, s0, 2);
        s1 += __shfl_xor_sync(0xFFFFFFFFu, s1, 1);
        s1 += __shfl_xor_sync(0xFFFFFFFFu, s1, 2);
        l0 = s0; l1 = s1;
        m0 = mn0; m1 = mn1;

        uint32_t ph[2][4];
        #pragma unroll
        for (int kk = 0; kk < 2; ++kk) {
            ph[kk][0] = pack_f16x2(sfr[2*kk][0],   sfr[2*kk][1]);
            ph[kk][1] = pack_f16x2(sfr[2*kk][2],   sfr[2*kk][3]);
            ph[kk][2] = pack_f16x2(sfr[2*kk+1][0], sfr[2*kk+1][1]);
            ph[kk][3] = pack_f16x2(sfr[2*kk+1][2], sfr[2*kk+1][3]);
        }
        #pragma unroll
        for (int kk = 0; kk < 2; ++kk) {
            #pragma unroll
            for (int dd = 0; dd < 4; ++dd) {
                const uint32_t addr = sb + AT_V +
                    (uint32_t)((lbase + kk * 16 + vkrow) * TROWB + (dd * 16 + vdcol) * 2);
                uint32_t vf[4];
                LDSM_X4_T(vf[0], vf[1], vf[2], vf[3], addr);
                MMA_F16(ofr[2*dd],   ph[kk][0], ph[kk][1], ph[kk][2], ph[kk][3], vf[0], vf[1]);
                MMA_F16(ofr[2*dd+1], ph[kk][0], ph[kk][1], ph[kk][2], ph[kk][3], vf[2], vf[3]);
            }
        }
    }

    // Phase B: strided K/V
    __syncthreads();
    for (int task = tid; task < n_str * 16; task += 256) {
        const int t   = task >> 4;
        const int sel = (task >> 3) & 1;
        const int d8  = (task & 7) << 3;
        const size_t src = (size_t)(b * SEQ + t * STRIDE_) * (3 * DMODEL)
                         + (size_t)(1 + sel) * DMODEL + h * HDIM + d8;
        *(uint4*)(smraw + (sel ? AT_V : AT_K) + t * TROWB + d8 * 2) =
            *(const uint4*)&qkvh[src];
    }
    for (int task = tid; task < (n_pad - n_str) * 8; task += 256) {
        const int t  = n_str + (task >> 3);
        const int d8 = (task & 7) << 3;
        const uint4 z = make_uint4(0, 0, 0, 0);
        *(uint4*)(smraw + AT_K + t * TROWB + d8 * 2) = z;
        *(uint4*)(smraw + AT_V + t * TROWB + d8 * 2) = z;
    }
    __syncthreads();

    const int row0q = q0 + 16 * w + qrow;
    const int nt0 = (row0q >> 3) + 1;
    const int nt1 = ((row0q + 8) >> 3) + 1;
    const int nchunks = (16 * qb + 2 * w + 2 + 63) >> 6;

    for (int ch = 0; ch < nchunks; ++ch) {
        const int c0 = ch * 64;
        float sfr[8][4];
        #pragma unroll
        for (int i = 0; i < 8; i++) { sfr[i][0]=0.f; sfr[i][1]=0.f; sfr[i][2]=0.f; sfr[i][3]=0.f; }

        #pragma unroll
        for (int kd = 0; kd < 4; ++kd) {
            #pragma unroll
            for (int kg = 0; kg < 4; ++kg) {
                const uint32_t addr = sb + AT_K +
                    (uint32_t)((c0 + kg * 16 + skrow) * TROWB + (kd * 16 + sdcol) * 2);
                uint32_t kf[4];
                LDSM_X4(kf[0], kf[1], kf[2], kf[3], addr);
                MMA_F16(sfr[2*kg],   qf[kd][0], qf[kd][1], qf[kd][2], qf[kd][3], kf[0], kf[1]);
                MMA_F16(sfr[2*kg+1], qf[kd][0], qf[kd][1], qf[kd][2], qf[kd][3], kf[2], kf[3]);
            }
        }

        float mx0 = -1e30f, mx1 = -1e30f;
        #pragma unroll
        for (int nf = 0; nf < 8; ++nf) {
            const int tb = c0 + nf * 8 + 2 * tig;
            if (tb >= nt0)     sfr[nf][0] = -1e30f;
            if (tb + 1 >= nt0) sfr[nf][1] = -1e30f;
            if (tb >= nt1)     sfr[nf][2] = -1e30f;
            if (tb + 1 >= nt1) sfr[nf][3] = -1e30f;
            mx0 = fmaxf(mx0, fmaxf(sfr[nf][0], sfr[nf][1]));
            mx1 = fmaxf(mx1, fmaxf(sfr[nf][2], sfr[nf][3]));
        }
        mx0 = fmaxf(mx0, __shfl_xor_sync(0xFFFFFFFFu, mx0, 1));
        mx0 = fmaxf(mx0, __shfl_xor_sync(0xFFFFFFFFu, mx0, 2));
        mx1 = fmaxf(mx1, __shfl_xor_sync(0xFFFFFFFFu, mx1, 1));
        mx1 = fmaxf(mx1, __shfl_xor_sync(0xFFFFFFFFu, mx1, 2));
        const float mn0 = fmaxf(m0, mx0);
        const float mn1 = fmaxf(m1, mx1);
        const float al0 = __expf(m0 - mn0);
        const float al1 = __expf(m1 - mn1);
        float s0 = 0.f, s1 = 0.f;
        #pragma unroll
        for (int nf = 0; nf < 8; ++nf) {
            sfr[nf][0] = __expf(sfr[nf][0] - mn0);
            sfr[nf][1] = __expf(sfr[nf][1] - mn0);
            sfr[nf][2] = __expf(sfr[nf][2] - mn1);
            sfr[nf][3] = __expf(sfr[nf][3] - mn1);
            s0 += sfr[nf][0] + sfr[nf][1];
            s1 += sfr[nf][2] + sfr[nf][3];
        }
        s0 += __shfl_xor_sync(0xFFFFFFFFu, s0, 1);
        s0 += __shfl_xor_sync(0xFFFFFFFFu, s0, 2);
        s1 += __shfl_xor_sync(0xFFFFFFFFu, s1, 1);
        s1 += __shfl_xor_sync(0xFFFFFFFFu, s1, 2);
        l0 = l0 * al0 + s0;
        l1 = l1 * al1 + s1;
        m0 = mn0; m1 = mn1;
        #pragma unroll
        for (int nf = 0; nf < 8; ++nf) {
            ofr[nf][0] *= al0; ofr[nf][1] *= al0;
            ofr[nf][2] *= al1; ofr[nf][3] *= al1;
        }

        uint32_t ph[4][4];
        #pragma unroll
        for (int kk = 0; kk < 4; ++kk) {
            ph[kk][0] = pack_f16x2(sfr[2*kk][0],   sfr[2*kk][1]);
            ph[kk][1] = pack_f16x2(sfr[2*kk][2],   sfr[2*kk][3]);
            ph[kk][2] = pack_f16x2(sfr[2*kk+1][0], sfr[2*kk+1][1]);
            ph[kk][3] = pack_f16x2(sfr[2*kk+1][2], sfr[2*kk+1][3]);
        }
        #pragma unroll
        for (int kk = 0; kk < 4; ++kk) {
            #pragma unroll
            for (int dd = 0; dd < 4; ++dd) {
                const uint32_t addr = sb + AT_V +
                    (uint32_t)((c0 + kk * 16 + vkrow) * TROWB + (dd * 16 + vdcol) * 2);
                uint32_t vf[4];
                LDSM_X4_T(vf[0], vf[1], vf[2], vf[3], addr);
                MMA_F16(ofr[2*dd],   ph[kk][0], ph[kk][1], ph[kk][2], ph[kk][3], vf[0], vf[1]);
                MMA_F16(ofr[2*dd+1], ph[kk][0], ph[kk][1], ph[kk][2], ph[kk][3], vf[2], vf[3]);
            }
        }
    }

    // normalize + coalesced write
    const float inv0 = 1.f / l0;
    const float inv1 = 1.f / l1;
    __syncthreads();
    {
        const int r0 = 16 * w + qrow;
        #pragma unroll
        for (int nf = 0; nf < 8; ++nf) {
            const int colb = (nf * 8 + 2 * tig) * 2;
            *(__half2*)(smraw + AT_K + r0 * TROWB + colb) =
                __floats2half2_rn(ofr[nf][0] * inv0, ofr[nf][1] * inv0);
            *(__half2*)(smraw + AT_K + (r0 + 8) * TROWB + colb) =
                __floats2half2_rn(ofr[nf][2] * inv1, ofr[nf][3] * inv1);
        }
    }
    __syncwarp();
    #pragma unroll
    for (int t = 0; t < 4; ++t) {
        const int task = lane + t * 32;
        const int r16 = task >> 3;
        const int q = task & 7;
        const int srow = 16 * w + r16;
        const uint4 v = *(const uint4*)(smraw + AT_K + srow * TROWB + q * 16);
        const size_t ob = (size_t)(b * SEQ + q0 + srow) * DMODEL + h * HDIM + q * 8;
        *(uint4*)&oh[ob] = v;
    }
}

// ---------------- launcher ----------------
extern "C" void kernel_launch(void* const* d_in, const int* in_sizes, int n_in,
                              void* d_out, int out_size)
{
    const float* x      = (const float*)d_in[0];
    const float* qkv_w  = (const float*)d_in[1];
    const float* qkv_b  = (const float*)d_in[2];
    const float* out_w  = (const float*)d_in[3];
    const float* out_b  = (const float*)d_in[4];
    float* out = (float*)d_out;

    __half *qkvh, *ah, *bh, *owh, *xh;
    cudaGetSymbolAddress((void**)&qkvh, g_qkvh);
    cudaGetSymbolAddress((void**)&ah,   g_ah);
    cudaGetSymbolAddress((void**)&bh,   g_bh);
    cudaGetSymbolAddress((void**)&owh,  g_owh);
    cudaGetSymbolAddress((void**)&xh,   g_xh);

    cudaFuncSetAttribute(gemm_mma_kernel<__half>,
                         cudaFuncAttributeMaxDynamicSharedMemorySize, GEMM_SMEM);
    cudaFuncSetAttribute(gemm_mma64_kernel,
                         cudaFuncAttributeMaxDynamicSharedMemorySize, GEMM64_SMEM);
    cudaFuncSetAttribute(attn_mma_kernel,
                         cudaFuncAttributeMaxDynamicSharedMemorySize, ATTN_SMEM);

    // fused fp16 conversions (one launch)
    {
        const int n1 = M_TOTAL * K_DIM / 4;
        const int n2 = N_QKV * K_DIM / 4;
        const int n3 = DMODEL * K_DIM / 4;
        const int nt = n1 + n2 + n3;
        conv_all_kernel<<<(nt + 255) / 256, 256>>>(x, qkv_w, out_w, xh, bh, owh, n1, n2, n3);
    }

    // 1) QKV projection -> fp16 (128x128 tiles, 576 CTAs)
    gemm_mma_kernel<__half><<<dim3(N_QKV / 128, M_TOTAL / 128), 256, GEMM_SMEM>>>(
        xh, bh, qkv_b, qkvh, N_QKV);

    // 2) strided attention
    attn_mma_kernel<<<dim3(SEQ / QB, BATCH * NHEAD), 256, ATTN_SMEM>>>(qkvh, ah);

    // 3) output projection -> fp32 (64x128 tiles, 384 CTAs: better wave balance)
    gemm_mma64_kernel<<<dim3(DMODEL / 128, M_TOTAL / 64), 256, GEMM64_SMEM>>>(
        ah, owh, out_b, out, DMODEL);
}

// round 16
// speedup vs baseline: 3.4853x; 1.0228x over previous
#include <cuda_runtime.h>
#include <cuda_bf16.h>
#include <cuda_fp16.h>
#include <cstdint>

// ---------------- problem constants ----------------
#define BATCH 2
#define SEQ   2048
#define DMODEL 768
#define NHEAD 12
#define HDIM  64
#define STRIDE_ 8
#define QB    128

#define M_TOTAL (BATCH*SEQ)   // 4096
#define K_DIM   DMODEL        // 768
#define N_QKV   (3*DMODEL)    // 2304

// ---------------- device scratch ----------------
__device__ __half g_qkvh[M_TOTAL * N_QKV];
__device__ __half g_ah[M_TOTAL * K_DIM];
__device__ __half g_bh[N_QKV * K_DIM];
__device__ __half g_owh[DMODEL * K_DIM];
__device__ __half g_xh[M_TOTAL * K_DIM];

// ---------------- PTX helpers ----------------
__device__ __forceinline__ uint32_t smem_u32(const void* p) {
    uint32_t a;
    asm("{ .reg .u64 t; cvta.to.shared.u64 t, %1; cvt.u32.u64 %0, t; }" : "=r"(a) : "l"(p));
    return a;
}

#define CP_ASYNC16(dst, src) \
    asm volatile("cp.async.cg.shared.global [%0], [%1], 16;" :: "r"(dst), "l"(src))
#define CP_COMMIT() asm volatile("cp.async.commit_group;" ::: "memory")
#define CP_WAIT2() asm volatile("cp.async.wait_group 2;" ::: "memory")
#define CP_WAIT1() asm volatile("cp.async.wait_group 1;" ::: "memory")
#define CP_WAIT0() asm volatile("cp.async.wait_group 0;" ::: "memory")

#define LDSM_X4(r0, r1, r2, r3, addr) \
    asm volatile("ldmatrix.sync.aligned.m8n8.x4.shared.b16 {%0,%1,%2,%3}, [%4];" \
        : "=r"(r0), "=r"(r1), "=r"(r2), "=r"(r3) : "r"(addr))

#define LDSM_X4_T(r0, r1, r2, r3, addr) \
    asm volatile("ldmatrix.sync.aligned.m8n8.x4.trans.shared.b16 {%0,%1,%2,%3}, [%4];" \
        : "=r"(r0), "=r"(r1), "=r"(r2), "=r"(r3) : "r"(addr))

#define MMA_F16(c, a0, a1, a2, a3, b0, b1) \
    asm("mma.sync.aligned.m16n8k16.row.col.f32.f16.f16.f32 " \
        "{%0,%1,%2,%3}, {%4,%5,%6,%7}, {%8,%9}, {%0,%1,%2,%3};" \
        : "+f"((c)[0]), "+f"((c)[1]), "+f"((c)[2]), "+f"((c)[3]) \
        : "r"(a0), "r"(a1), "r"(a2), "r"(a3), "r"(b0), "r"(b1))

__device__ __forceinline__ uint32_t pack_f16x2(float a, float b) {
    __half2 h = __floats2half2_rn(a, b);
    return *(uint32_t*)&h;
}
__device__ __forceinline__ void store2(float* p, float a, float b) {
    *(float2*)p = make_float2(a, b);
}
__device__ __forceinline__ void store2(__half* p, float a, float b) {
    *(__half2*)p = __floats2half2_rn(a, b);
}

// ---------------- fused fp32 -> fp16 convert ----------------
__global__ __launch_bounds__(256)
void conv_all_kernel(const float* __restrict__ x, const float* __restrict__ w1,
                     const float* __restrict__ w2,
                     __half* __restrict__ xh, __half* __restrict__ bh,
                     __half* __restrict__ owh, int n1, int n2, int n3)
{
    int i = blockIdx.x * 256 + threadIdx.x;
    const float* src;
    __half* dst;
    int off;
    if (i < n1)            { src = x;  dst = xh;  off = i; }
    else if (i < n1 + n2)  { src = w1; dst = bh;  off = i - n1; }
    else if (i < n1+n2+n3) { src = w2; dst = owh; off = i - n1 - n2; }
    else return;
    float4 v = ((const float4*)src)[off];
    __half2 a = __floats2half2_rn(v.x, v.y);
    __half2 b = __floats2half2_rn(v.z, v.w);
    ((uint2*)dst)[off] = make_uint2(*(uint32_t*)&a, *(uint32_t*)&b);
}

// ------- fp16 GEMM 128x128, GBK=64, 3-stage (QKV) -------
#define GBK 64
#define NCHUNK (K_DIM / GBK)          // 12
#define TPAD 72
#define TILE_BYTES (128 * TPAD * 2)   // 18432
#define STAGE_BYTES (2 * TILE_BYTES)  // 36864
#define GEMM_SMEM (3 * STAGE_BYTES)   // 110592 -> 2 CTAs/SM (221KB)

template <typename OT>
__global__ __launch_bounds__(256, 2)
void gemm_mma_kernel(const __half* __restrict__ A, const __half* __restrict__ B,
                     const float* __restrict__ bias, OT* __restrict__ C, int N)
{
    extern __shared__ char dsm[];
    const uint32_t sbase = smem_u32(dsm);
    const int tid = threadIdx.x;
    const int lane = tid & 31;
    const int wid = tid >> 5;
    const int wm = (wid & 1) * 64;
    const int wn = (wid >> 1) * 32;
    const int bm = blockIdx.y * 128;
    const int bn = blockIdx.x * 128;

    const __half* gp[2] = { A, B };

    float acc[4][4][4];
    #pragma unroll
    for (int i = 0; i < 4; i++)
        #pragma unroll
        for (int j = 0; j < 4; j++)
            #pragma unroll
            for (int r = 0; r < 4; r++) acc[i][j][r] = 0.f;

    auto issue = [&](int stage, int kc) {
        const uint32_t st = sbase + (uint32_t)stage * STAGE_BYTES;
        #pragma unroll
        for (int t = 0; t < 8; ++t) {
            int task = tid + t * 256;
            int tile = task >> 10;
            int idx  = task & 1023;
            int r = idx >> 3, q = idx & 7;
            int row = (tile == 0 ? bm : bn) + r;
            uint32_t dst = st + (uint32_t)tile * TILE_BYTES + (uint32_t)(r * TPAD + q * 8) * 2;
            CP_ASYNC16(dst, gp[tile] + (size_t)row * K_DIM + kc + q * 8);
        }
        CP_COMMIT();
    };

    issue(0, 0);
    issue(1, GBK);
    issue(2, 2 * GBK);

    const int g = lane >> 3;
    const int arow = wm + (g & 1) * 8 + (lane & 7);
    const int acoff = (g >> 1) * 8;
    const int brow0 = wn + (g >> 1) * 8 + (lane & 7);
    const int bcoff = (g & 1) * 8;

    for (int c = 0; c < NCHUNK; ++c) {
        if (c <= NCHUNK - 3)      { CP_WAIT2(); }
        else if (c == NCHUNK - 2) { CP_WAIT1(); }
        else                      { CP_WAIT0(); }
        __syncthreads();

        const uint32_t st = sbase + (uint32_t)(c % 3) * STAGE_BYTES;
        const uint32_t aT = st;
        const uint32_t bT = st + TILE_BYTES;

        #pragma unroll
        for (int ks = 0; ks < 4; ++ks) {
            const int acol = ks * 16 + acoff;
            const int bcol = ks * 16 + bcoff;
            uint32_t a[4][4];
            #pragma unroll
            for (int mf = 0; mf < 4; ++mf) {
                uint32_t off = (uint32_t)((arow + mf * 16) * TPAD + acol) * 2;
                LDSM_X4(a[mf][0], a[mf][1], a[mf][2], a[mf][3], aT + off);
            }
            #pragma unroll
            for (int nf2 = 0; nf2 < 2; ++nf2) {
                uint32_t off = (uint32_t)((brow0 + nf2 * 16) * TPAD + bcol) * 2;
                uint32_t bf[2][2];
                LDSM_X4(bf[0][0], bf[0][1], bf[1][0], bf[1][1], bT + off);
                #pragma unroll
                for (int mf = 0; mf < 4; ++mf)
                    #pragma unroll
                    for (int q = 0; q < 2; ++q)
                        MMA_F16(acc[mf][2 * nf2 + q], a[mf][0], a[mf][1], a[mf][2], a[mf][3],
                                bf[q][0], bf[q][1]);
            }
        }
        __syncthreads();
        if (c + 3 < NCHUNK) issue(c % 3, (c + 3) * GBK);
    }

    #pragma unroll
    for (int mf = 0; mf < 4; ++mf) {
        const int m = bm + wm + mf * 16 + (lane >> 2);
        #pragma unroll
        for (int nf = 0; nf < 4; ++nf) {
            const int n = bn + wn + nf * 8 + (lane & 3) * 2;
            const float2 bv = *(const float2*)&bias[n];
            store2(&C[(size_t)m * N + n],       acc[mf][nf][0] + bv.x, acc[mf][nf][1] + bv.y);
            store2(&C[(size_t)(m + 8) * N + n], acc[mf][nf][2] + bv.x, acc[mf][nf][3] + bv.y);
        }
    }
}

// ------- fp16 GEMM 64x128, GBK=64, 3-stage (proj) -------
#define A64_TILE (64 * TPAD * 2)              // 9216
#define STAGE64  (A64_TILE + TILE_BYTES)      // 27648
#define GEMM64_SMEM (3 * STAGE64)             // 82944 -> 2 CTAs/SM

__global__ __launch_bounds__(256, 2)
void gemm_mma64_kernel(const __half* __restrict__ A, const __half* __restrict__ B,
                       const float* __restrict__ bias, float* __restrict__ C, int N)
{
    extern __shared__ char dsm[];
    const uint32_t sbase = smem_u32(dsm);
    const int tid = threadIdx.x;
    const int lane = tid & 31;
    const int wid = tid >> 5;
    const int wm = (wid & 1) * 32;
    const int wn = (wid >> 1) * 32;
    const int bm = blockIdx.y * 64;
    const int bn = blockIdx.x * 128;

    float acc[2][4][4];
    #pragma unroll
    for (int i = 0; i < 2; i++)
        #pragma unroll
        for (int j = 0; j < 4; j++)
            #pragma unroll
            for (int r = 0; r < 4; r++) acc[i][j][r] = 0.f;

    auto issue = [&](int stage, int kc) {
        const uint32_t st = sbase + (uint32_t)stage * STAGE64;
        #pragma unroll
        for (int t = 0; t < 6; ++t) {
            int task = tid + t * 256;
            int tile, idx;
            if (task < 512) { tile = 0; idx = task; }
            else            { tile = 1; idx = task - 512; }
            int r = idx >> 3, q = idx & 7;
            int row = (tile == 0 ? bm : bn) + r;
            uint32_t dst = st + (tile ? A64_TILE : 0u) + (uint32_t)(r * TPAD + q * 8) * 2;
            CP_ASYNC16(dst, (tile == 0 ? A : B) + (size_t)row * K_DIM + kc + q * 8);
        }
        CP_COMMIT();
    };

    issue(0, 0);
    issue(1, GBK);
    issue(2, 2 * GBK);

    const int g = lane >> 3;
    const int arow = wm + (g & 1) * 8 + (lane & 7);
    const int acoff = (g >> 1) * 8;
    const int brow0 = wn + (g >> 1) * 8 + (lane & 7);
    const int bcoff = (g & 1) * 8;

    for (int c = 0; c < NCHUNK; ++c) {
        if (c <= NCHUNK - 3)      { CP_WAIT2(); }
        else if (c == NCHUNK - 2) { CP_WAIT1(); }
        else                      { CP_WAIT0(); }
        __syncthreads();

        const uint32_t st = sbase + (uint32_t)(c % 3) * STAGE64;
        const uint32_t aT = st;
        const uint32_t bT = st + A64_TILE;

        #pragma unroll
        for (int ks = 0; ks < 4; ++ks) {
            const int acol = ks * 16 + acoff;
            const int bcol = ks * 16 + bcoff;
            uint32_t a[2][4];
            #pragma unroll
            for (int mf = 0; mf < 2; ++mf) {
                uint32_t off = (uint32_t)((arow + mf * 16) * TPAD + acol) * 2;
                LDSM_X4(a[mf][0], a[mf][1], a[mf][2], a[mf][3], aT + off);
            }
            #pragma unroll
            for (int nf2 = 0; nf2 < 2; ++nf2) {
                uint32_t off = (uint32_t)((brow0 + nf2 * 16) * TPAD + bcol) * 2;
                uint32_t bf[2][2];
                LDSM_X4(bf[0][0], bf[0][1], bf[1][0], bf[1][1], bT + off);
                #pragma unroll
                for (int mf = 0; mf < 2; ++mf)
                    #pragma unroll
                    for (int q = 0; q < 2; ++q)
                        MMA_F16(acc[mf][2 * nf2 + q], a[mf][0], a[mf][1], a[mf][2], a[mf][3],
                                bf[q][0], bf[q][1]);
            }
        }
        __syncthreads();
        if (c + 3 < NCHUNK) issue(c % 3, (c + 3) * GBK);
    }

    #pragma unroll
    for (int mf = 0; mf < 2; ++mf) {
        const int m = bm + wm + mf * 16 + (lane >> 2);
        #pragma unroll
        for (int nf = 0; nf < 4; ++nf) {
            const int n = bn + wn + nf * 8 + (lane & 3) * 2;
            const float2 bv = *(const float2*)&bias[n];
            store2(&C[(size_t)m * N + n],       acc[mf][nf][0] + bv.x, acc[mf][nf][1] + bv.y);
            store2(&C[(size_t)(m + 8) * N + n], acc[mf][nf][2] + bv.x, acc[mf][nf][3] + bv.y);
        }
    }
}

// ==== MMA flash attention: all-fp16 single-product, band fused via MMA ====
#define TROWB 144
#define AT_K  0
#define AT_V  36864
#define AT_Q  73728
#define ATTN_SMEM 92160

__global__ __launch_bounds__(256, 2)
void attn_mma_kernel(const __half* __restrict__ qkvh, __half* __restrict__ oh)
{
    extern __shared__ char smraw[];
    const uint32_t sb = smem_u32(smraw);
    const int tid = threadIdx.x;
    const int lane = tid & 31;
    const int w = tid >> 5;

    const int bh = blockIdx.y;
    const int b = bh / NHEAD;
    const int h = bh % NHEAD;
    const int qb = gridDim.x - 1 - blockIdx.x;
    const int q0 = qb * QB;
    const int n_str = 16 * (qb + 1);
    const int n_pad = (n_str + 63) & ~63;
    const __half2 hscale = __float2half2_rn(0.125f);

    // Phase A: local band
    for (int task = tid; task < 144 * 16; task += 256) {
        const int lrow = task >> 4;
        const int sel  = (task >> 3) & 1;
        const int d8   = (task & 7) << 3;
        const int j    = q0 - 16 + lrow;
        uint4 pk = make_uint4(0, 0, 0, 0);
        if (j >= 0) {
            const size_t src = (size_t)(b * SEQ + j) * (3 * DMODEL)
                             + (size_t)(1 + sel) * DMODEL + h * HDIM + d8;
            pk = *(const uint4*)&qkvh[src];
        }
        *(uint4*)(smraw + (sel ? AT_V : AT_K) + lrow * TROWB + d8 * 2) = pk;
    }
    for (int task = tid; task < 128 * 8; task += 256) {
        const int r  = task >> 3;
        const int d8 = (task & 7) << 3;
        const size_t src = (size_t)(b * SEQ + q0 + r) * (3 * DMODEL) + h * HDIM + d8;
        uint4 v = *(const uint4*)&qkvh[src];
        __half2* pv = (__half2*)&v;
        #pragma unroll
        for (int k = 0; k < 4; ++k) pv[k] = __hmul2(pv[k], hscale);
        *(uint4*)(smraw + AT_Q + r * TROWB + d8 * 2) = v;
    }
    __syncthreads();

    const int g = lane >> 3;
    const int tig = lane & 3;
    const int arow = 16 * w + (g & 1) * 8 + (lane & 7);
    const int acoff = (g >> 1) * 8;
    uint32_t qf[4][4];
    #pragma unroll
    for (int kd = 0; kd < 4; ++kd) {
        const uint32_t off = (uint32_t)(arow * TROWB + (kd * 16 + acoff) * 2);
        LDSM_X4(qf[kd][0], qf[kd][1], qf[kd][2], qf[kd][3], sb + AT_Q + off);
    }

    float ofr[8][4];
    #pragma unroll
    for (int i = 0; i < 8; i++) { ofr[i][0]=0.f; ofr[i][1]=0.f; ofr[i][2]=0.f; ofr[i][3]=0.f; }
    float m0 = -1e30f, m1 = -1e30f, l0 = 0.f, l1 = 0.f;

    const int skrow = (g >> 1) * 8 + (lane & 7);
    const int sdcol = (g & 1) * 8;
    const int vkrow = (g & 1) * 8 + (lane & 7);
    const int vdcol = (g >> 1) * 8;
    const int qrow = lane >> 2;

    // band S2
    {
        const int lbase = 16 * w;
        float sfr[4][4];
        #pragma unroll
        for (int i = 0; i < 4; i++) { sfr[i][0]=0.f; sfr[i][1]=0.f; sfr[i][2]=0.f; sfr[i][3]=0.f; }

        #pragma unroll
        for (int kd = 0; kd < 4; ++kd) {
            #pragma unroll
            for (int kg = 0; kg < 2; ++kg) {
                const uint32_t addr = sb + AT_K +
                    (uint32_t)((lbase + kg * 16 + skrow) * TROWB + (kd * 16 + sdcol) * 2);
                uint32_t kf[4];
                LDSM_X4(kf[0], kf[1], kf[2], kf[3], addr);
                MMA_F16(sfr[2*kg],   qf[kd][0], qf[kd][1], qf[kd][2], qf[kd][3], kf[0], kf[1]);
                MMA_F16(sfr[2*kg+1], qf[kd][0], qf[kd][1], qf[kd][2], qf[kd][3], kf[2], kf[3]);
            }
        }

        const int j0 = q0 + 16 * w - 16;
        float mx0 = -1e30f, mx1 = -1e30f;
        #pragma unroll
        for (int nf = 0; nf < 4; ++nf) {
            #pragma unroll
            for (int r = 0; r < 2; ++r) {
                const int c = nf * 8 + 2 * tig + r;
                const int j = j0 + c;
                const bool ok = (((j & 7) != 0) && (j >= 0));
                const bool v0 = ok && (c == qrow + 16 || c == qrow + 15);
                const bool v1 = ok && (c == qrow + 24 || c == qrow + 23);
                if (!v0) sfr[nf][r]     = -1e30f;
                if (!v1) sfr[nf][r + 2] = -1e30f;
            }
            mx0 = fmaxf(mx0, fmaxf(sfr[nf][0], sfr[nf][1]));
            mx1 = fmaxf(mx1, fmaxf(sfr[nf][2], sfr[nf][3]));
        }
        mx0 = fmaxf(mx0, __shfl_xor_sync(0xFFFFFFFFu, mx0, 1));
        mx0 = fmaxf(mx0, __shfl_xor_sync(0xFFFFFFFFu, mx0, 2));
        mx1 = fmaxf(mx1, __shfl_xor_sync(0xFFFFFFFFu, mx1, 1));
        mx1 = fmaxf(mx1, __shfl_xor_sync(0xFFFFFFFFu, mx1, 2));
        const float mn0 = fmaxf(fmaxf(m0, mx0), -1e29f);
        const float mn1 = fmaxf(fmaxf(m1, mx1), -1e29f);
        float s0 = 0.f, s1 = 0.f;
        #pragma unroll
        for (int nf = 0; nf < 4; ++nf) {
            sfr[nf][0] = __expf(sfr[nf][0] - mn0);
            sfr[nf][1] = __expf(sfr[nf][1] - mn0);
            sfr[nf][2] = __expf(sfr[nf][2] - mn1);
            sfr[nf][3] = __expf(sfr[nf][3] - mn1);
            s0 += sfr[nf][0] + sfr[nf][1];
            s1 += sfr[nf][2] + sfr[nf][3];
        }
        s0 += __shfl_xor_sync(0xFFFFFFFFu, s0, 1);
        s0 += __shfl_xor_sync(0xFFFFFFFFu, s0, 2);
        s1 += __shfl_xor_sync(0xFFFFFFFFu, s1, 1);
        s1 += __shfl_xor_sync(0xFFFFFFFFu, s1, 2);
        l0 = s0; l1 = s1;
        m0 = mn0; m1 = mn1;

        uint32_t ph[2][4];
        #pragma unroll
        for (int kk = 0; kk < 2; ++kk) {
            ph[kk][0] = pack_f16x2(sfr[2*kk][0],   sfr[2*kk][1]);
            ph[kk][1] = pack_f16x2(sfr[2*kk][2],   sfr[2*kk][3]);
            ph[kk][2] = pack_f16x2(sfr[2*kk+1][0], sfr[2*kk+1][1]);
            ph[kk][3] = pack_f16x2(sfr[2*kk+1][2], sfr[2*kk+1][3]);
        }
        #pragma unroll
        for (int kk = 0; kk < 2; ++kk) {
            #pragma unroll
            for (int dd = 0; dd < 4; ++dd) {
                const uint32_t addr = sb + AT_V +
                    (uint32_t)((lbase + kk * 16 + vkrow) * TROWB + (dd * 16 + vdcol) * 2);
                uint32_t vf[4];
                LDSM_X4_T(vf[0], vf[1], vf[2], vf[3], addr);
                MMA_F16(ofr[2*dd],   ph[kk][0], ph[kk][1], ph[kk][2], ph[kk][3], vf[0], vf[1]);
                MMA_F16(ofr[2*dd+1], ph[kk][0], ph[kk][1], ph[kk][2], ph[kk][3], vf[2], vf[3]);
            }
        }
    }

    // Phase B: strided K/V
    __syncthreads();
    for (int task = tid; task < n_str * 16; task += 256) {
        const int t   = task >> 4;
        const int sel = (task >> 3) & 1;
        const int d8  = (task & 7) << 3;
        const size_t src = (size_t)(b * SEQ + t * STRIDE_) * (3 * DMODEL)
                         + (size_t)(1 + sel) * DMODEL + h * HDIM + d8;
        *(uint4*)(smraw + (sel ? AT_V : AT_K) + t * TROWB + d8 * 2) =
            *(const uint4*)&qkvh[src];
    }
    for (int task = tid; task < (n_pad - n_str) * 8; task += 256) {
        const int t  = n_str + (task >> 3);
        const int d8 = (task & 7) << 3;
        const uint4 z = make_uint4(0, 0, 0, 0);
        *(uint4*)(smraw + AT_K + t * TROWB + d8 * 2) = z;
        *(uint4*)(smraw + AT_V + t * TROWB + d8 * 2) = z;
    }
    __syncthreads();

    const int row0q = q0 + 16 * w + qrow;
    const int nt0 = (row0q >> 3) + 1;
    const int nt1 = ((row0q + 8) >> 3) + 1;
    const int nchunks = (16 * qb + 2 * w + 2 + 63) >> 6;

    for (int ch = 0; ch < nchunks; ++ch) {
        const int c0 = ch * 64;
        float sfr[8][4];
        #pragma unroll
        for (int i = 0; i < 8; i++) { sfr[i][0]=0.f; sfr[i][1]=0.f; sfr[i][2]=0.f; sfr[i][3]=0.f; }

        #pragma unroll
        for (int kd = 0; kd < 4; ++kd) {
            #pragma unroll
            for (int kg = 0; kg < 4; ++kg) {
                const uint32_t addr = sb + AT_K +
                    (uint32_t)((c0 + kg * 16 + skrow) * TROWB + (kd * 16 + sdcol) * 2);
                uint32_t kf[4];
                LDSM_X4(kf[0], kf[1], kf[2], kf[3], addr);
                MMA_F16(sfr[2*kg],   qf[kd][0], qf[kd][1], qf[kd][2], qf[kd][3], kf[0], kf[1]);
                MMA_F16(sfr[2*kg+1], qf[kd][0], qf[kd][1], qf[kd][2], qf[kd][3], kf[2], kf[3]);
            }
        }

        float mx0 = -1e30f, mx1 = -1e30f;
        #pragma unroll
        for (int nf = 0; nf < 8; ++nf) {
            const int tb = c0 + nf * 8 + 2 * tig;
            if (tb >= nt0)     sfr[nf][0] = -1e30f;
            if (tb + 1 >= nt0) sfr[nf][1] = -1e30f;
            if (tb >= nt1)     sfr[nf][2] = -1e30f;
            if (tb + 1 >= nt1) sfr[nf][3] = -1e30f;
            mx0 = fmaxf(mx0, fmaxf(sfr[nf][0], sfr[nf][1]));
            mx1 = fmaxf(mx1, fmaxf(sfr[nf][2], sfr[nf][3]));
        }
        mx0 = fmaxf(mx0, __shfl_xor_sync(0xFFFFFFFFu, mx0, 1));
        mx0 = fmaxf(mx0, __shfl_xor_sync(0xFFFFFFFFu, mx0, 2));
        mx1 = fmaxf(mx1, __shfl_xor_sync(0xFFFFFFFFu, mx1, 1));
        mx1 = fmaxf(mx1, __shfl_xor_sync(0xFFFFFFFFu, mx1, 2));
        const float mn0 = fmaxf(m0, mx0);
        const float mn1 = fmaxf(m1, mx1);
        const float al0 = __expf(m0 - mn0);
        const float al1 = __expf(m1 - mn1);
        float s0 = 0.f, s1 = 0.f;
        #pragma unroll
        for (int nf = 0; nf < 8; ++nf) {
            sfr[nf][0] = __expf(sfr[nf][0] - mn0);
            sfr[nf][1] = __expf(sfr[nf][1] - mn0);
            sfr[nf][2] = __expf(sfr[nf][2] - mn1);
            sfr[nf][3] = __expf(sfr[nf][3] - mn1);
            s0 += sfr[nf][0] + sfr[nf][1];
            s1 += sfr[nf][2] + sfr[nf][3];
        }
        s0 += __shfl_xor_sync(0xFFFFFFFFu, s0, 1);
        s0 += __shfl_xor_sync(0xFFFFFFFFu, s0, 2);
        s1 += __shfl_xor_sync(0xFFFFFFFFu, s1, 1);
        s1 += __shfl_xor_sync(0xFFFFFFFFu, s1, 2);
        l0 = l0 * al0 + s0;
        l1 = l1 * al1 + s1;
        m0 = mn0; m1 = mn1;
        #pragma unroll
        for (int nf = 0; nf < 8; ++nf) {
            ofr[nf][0] *= al0; ofr[nf][1] *= al0;
            ofr[nf][2] *= al1; ofr[nf][3] *= al1;
        }

        uint32_t ph[4][4];
        #pragma unroll
        for (int kk = 0; kk < 4; ++kk) {
            ph[kk][0] = pack_f16x2(sfr[2*kk][0],   sfr[2*kk][1]);
            ph[kk][1] = pack_f16x2(sfr[2*kk][2],   sfr[2*kk][3]);
            ph[kk][2] = pack_f16x2(sfr[2*kk+1][0], sfr[2*kk+1][1]);
            ph[kk][3] = pack_f16x2(sfr[2*kk+1][2], sfr[2*kk+1][3]);
        }
        #pragma unroll
        for (int kk = 0; kk < 4; ++kk) {
            #pragma unroll
            for (int dd = 0; dd < 4; ++dd) {
                const uint32_t addr = sb + AT_V +
                    (uint32_t)((c0 + kk * 16 + vkrow) * TROWB + (dd * 16 + vdcol) * 2);
                uint32_t vf[4];
                LDSM_X4_T(vf[0], vf[1], vf[2], vf[3], addr);
                MMA_F16(ofr[2*dd],   ph[kk][0], ph[kk][1], ph[kk][2], ph[kk][3], vf[0], vf[1]);
                MMA_F16(ofr[2*dd+1], ph[kk][0], ph[kk][1], ph[kk][2], ph[kk][3], vf[2], vf[3]);
            }
        }
    }

    // normalize + coalesced write
    const float inv0 = 1.f / l0;
    const float inv1 = 1.f / l1;
    __syncthreads();
    {
        const int r0 = 16 * w + qrow;
        #pragma unroll
        for (int nf = 0; nf < 8; ++nf) {
            const int colb = (nf * 8 + 2 * tig) * 2;
            *(__half2*)(smraw + AT_K + r0 * TROWB + colb) =
                __floats2half2_rn(ofr[nf][0] * inv0, ofr[nf][1] * inv0);
            *(__half2*)(smraw + AT_K + (r0 + 8) * TROWB + colb) =
                __floats2half2_rn(ofr[nf][2] * inv1, ofr[nf][3] * inv1);
        }
    }
    __syncwarp();
    #pragma unroll
    for (int t = 0; t < 4; ++t) {
        const int task = lane + t * 32;
        const int r16 = task >> 3;
        const int q = task & 7;
        const int srow = 16 * w + r16;
        const uint4 v = *(const uint4*)(smraw + AT_K + srow * TROWB + q * 16);
        const size_t ob = (size_t)(b * SEQ + q0 + srow) * DMODEL + h * HDIM + q * 8;
        *(uint4*)&oh[ob] = v;
    }
}

// ---------------- launcher ----------------
extern "C" void kernel_launch(void* const* d_in, const int* in_sizes, int n_in,
                              void* d_out, int out_size)
{
    const float* x      = (const float*)d_in[0];
    const float* qkv_w  = (const float*)d_in[1];
    const float* qkv_b  = (const float*)d_in[2];
    const float* out_w  = (const float*)d_in[3];
    const float* out_b  = (const float*)d_in[4];
    float* out = (float*)d_out;

    __half *qkvh, *ah, *bh, *owh, *xh;
    cudaGetSymbolAddress((void**)&qkvh, g_qkvh);
    cudaGetSymbolAddress((void**)&ah,   g_ah);
    cudaGetSymbolAddress((void**)&bh,   g_bh);
    cudaGetSymbolAddress((void**)&owh,  g_owh);
    cudaGetSymbolAddress((void**)&xh,   g_xh);

    cudaFuncSetAttribute(gemm_mma_kernel<__half>,
                         cudaFuncAttributeMaxDynamicSharedMemorySize, GEMM_SMEM);
    cudaFuncSetAttribute(gemm_mma64_kernel,
                         cudaFuncAttributeMaxDynamicSharedMemorySize, GEMM64_SMEM);
    cudaFuncSetAttribute(attn_mma_kernel,
                         cudaFuncAttributeMaxDynamicSharedMemorySize, ATTN_SMEM);

    // fused fp16 conversions (one launch)
    {
        const int n1 = M_TOTAL * K_DIM / 4;
        const int n2 = N_QKV * K_DIM / 4;
        const int n3 = DMODEL * K_DIM / 4;
        const int nt = n1 + n2 + n3;
        conv_all_kernel<<<(nt + 255) / 256, 256>>>(x, qkv_w, out_w, xh, bh, owh, n1, n2, n3);
    }

    // 1) QKV projection -> fp16 (128x128 tiles, 3-stage)
    gemm_mma_kernel<__half><<<dim3(N_QKV / 128, M_TOTAL / 128), 256, GEMM_SMEM>>>(
        xh, bh, qkv_b, qkvh, N_QKV);

    // 2) strided attention
    attn_mma_kernel<<<dim3(SEQ / QB, BATCH * NHEAD), 256, ATTN_SMEM>>>(qkvh, ah);

    // 3) output projection -> fp32 (64x128 tiles, 3-stage)
    gemm_mma64_kernel<<<dim3(DMODEL / 128, M_TOTAL / 64), 256, GEMM64_SMEM>>>(
        ah, owh, out_b, out, DMODEL);
}